// round 1
// baseline (speedup 1.0000x reference)
#include <cuda_runtime.h>
#include <cstdint>
#include <cstddef>

// Problem constants
#define DIMN   512
#define N_ROWS 16384          // B*L = 256*64
#define NB     256            // batch
// r = (c,h), c in [0,8), h in [0,64)  -> 512 "rank" terms

// ---------------- scratch (static device allocations; no cudaMalloc) -------
__device__ float g_q[(size_t)N_ROWS * DIMN];   // core_value/H -folded q projection
__device__ float g_k[(size_t)N_ROWS * DIMN];
__device__ float g_v[(size_t)N_ROWS * DIMN];
__device__ float g_F[(size_t)NB * 4096 * 64];  // per-b F[(i,j), k'] , 256 MB

// ---------------------------------------------------------------------------
// K1: projection GEMM  C[n,m] = sum_p x[n,p]*W[m,p] + bias[m]
//     optional fold: *= cv[c(n), h(m)] * 0.125   (only for q)
// tile 128x128, 256 threads, 8x8 per-thread tile
// ---------------------------------------------------------------------------
__global__ __launch_bounds__(256) void proj_kernel(
    const float* __restrict__ x, const float* __restrict__ W,
    const float* __restrict__ bias, const float* __restrict__ cv,
    float* __restrict__ outp)
{
    __shared__ float Xs[128][17];
    __shared__ float Ws[128][17];
    const int row0 = blockIdx.y * 128;
    const int col0 = blockIdx.x * 128;
    const int tid  = threadIdx.x;
    const int ry = tid >> 4;    // 0..15
    const int cx = tid & 15;    // 0..15

    float acc[8][8];
#pragma unroll
    for (int a = 0; a < 8; a++)
#pragma unroll
        for (int b = 0; b < 8; b++) acc[a][b] = 0.f;

    for (int p0 = 0; p0 < DIMN; p0 += 16) {
#pragma unroll
        for (int l = 0; l < 2; l++) {
            int idx = l * 256 + tid;          // 0..511 float4 slots
            int r = idx >> 2, seg = idx & 3;
            float4 t = *(const float4*)&x[(size_t)(row0 + r) * DIMN + p0 + seg * 4];
            Xs[r][seg*4+0] = t.x; Xs[r][seg*4+1] = t.y;
            Xs[r][seg*4+2] = t.z; Xs[r][seg*4+3] = t.w;
            float4 u = *(const float4*)&W[(size_t)(col0 + r) * DIMN + p0 + seg * 4];
            Ws[r][seg*4+0] = u.x; Ws[r][seg*4+1] = u.y;
            Ws[r][seg*4+2] = u.z; Ws[r][seg*4+3] = u.w;
        }
        __syncthreads();
#pragma unroll
        for (int pp = 0; pp < 16; pp++) {
            float a[8], b[8];
#pragma unroll
            for (int rm = 0; rm < 8; rm++) a[rm] = Xs[ry + rm*16][pp];
#pragma unroll
            for (int cn = 0; cn < 8; cn++) b[cn] = Ws[cx + cn*16][pp];
#pragma unroll
            for (int rm = 0; rm < 8; rm++)
#pragma unroll
                for (int cn = 0; cn < 8; cn++)
                    acc[rm][cn] = fmaf(a[rm], b[cn], acc[rm][cn]);
        }
        __syncthreads();
    }

#pragma unroll
    for (int rm = 0; rm < 8; rm++) {
        int r = row0 + ry + rm * 16;
#pragma unroll
        for (int cn = 0; cn < 8; cn++) {
            int cm = col0 + cx + cn * 16;
            float val = acc[rm][cn] + bias[cm];
            if (cv) {
                int c = r >> 11;       // flat-reshape: core index = row >> 11
                int h = cm & 63;
                val *= cv[c * 64 + h] * 0.125f;   // fold core_value and 1/H
            }
            outp[(size_t)r * DIMN + cm] = val;
        }
    }
}

// ---------------------------------------------------------------------------
// K2: per-b GEMM1.  F[(i,j), n] = sum_r (wq[i,r] * K[j,r]) * V[n,r]
// block: one b, i-pair {i0, i0+1}, all j (m = i_local*64 + j in [0,128)), n in [0,64)
// reduction r split by core c (chunks of 64 = one h-block, contiguous in gmem)
// 128 threads, 8x8 per-thread tile
// ---------------------------------------------------------------------------
__global__ __launch_bounds__(128) void gemm1_kernel(float* __restrict__ gF)
{
    __shared__ float Ks[64][65];
    __shared__ float Vs[64][65];
    __shared__ float Qs[2][64];
    const int b  = blockIdx.y;
    const int i0 = blockIdx.x * 2;
    const int tid = threadIdx.x;
    const int my = tid >> 3;   // 0..15
    const int nx = tid & 7;    // 0..7

    float acc[8][8];
#pragma unroll
    for (int a = 0; a < 8; a++)
#pragma unroll
        for (int bb2 = 0; bb2 < 8; bb2++) acc[a][bb2] = 0.f;

    for (int c = 0; c < 8; c++) {
        // the (c,b) K/V block is 8 consecutive rows = 4096 contiguous floats
        const size_t base = ((size_t)c * 2048 + (size_t)b * 8) * DIMN;
#pragma unroll
        for (int l = 0; l < 8; l++) {
            int idx4 = l * 128 + tid;       // 0..1023 float4 slots, coalesced
            int o = idx4 * 4;               // linear offset in the 4096 block
            int j = ((o >> 9) << 3) | ((o >> 6) & 7);
            int h = o & 63;
            float4 t = *(const float4*)&g_k[base + o];
            Ks[j][h+0] = t.x; Ks[j][h+1] = t.y; Ks[j][h+2] = t.z; Ks[j][h+3] = t.w;
            float4 u = *(const float4*)&g_v[base + o];
            Vs[j][h+0] = u.x; Vs[j][h+1] = u.y; Vs[j][h+2] = u.z; Vs[j][h+3] = u.w;
        }
        {
            // q rows for i0, i0+1: 128 contiguous floats (i0 even)
            const size_t qbase = ((size_t)c * 2048 + (size_t)b * 8 + (i0 >> 3)) * DIMN
                               + (size_t)(i0 & 7) * 64;
            Qs[tid >> 6][tid & 63] = g_q[qbase + tid];
        }
        __syncthreads();
#pragma unroll
        for (int rr = 0; rr < 64; rr++) {
            float a[8], bb[8];
#pragma unroll
            for (int mm = 0; mm < 8; mm++) {
                int m = my + mm * 16;                       // 0..127
                a[mm] = Qs[m >> 6][rr] * Ks[m & 63][rr];    // G formed on the fly
            }
#pragma unroll
            for (int nn = 0; nn < 8; nn++)
                bb[nn] = Vs[nx + nn * 8][rr];
#pragma unroll
            for (int mm = 0; mm < 8; mm++)
#pragma unroll
                for (int nn = 0; nn < 8; nn++)
                    acc[mm][nn] = fmaf(a[mm], bb[nn], acc[mm][nn]);
        }
        __syncthreads();
    }

    const size_t fbase = (size_t)b * 262144 + (size_t)i0 * 4096;
#pragma unroll
    for (int mm = 0; mm < 8; mm++) {
        int m = my + mm * 16;
#pragma unroll
        for (int nn = 0; nn < 8; nn++) {
            int n = nx + nn * 8;
            gF[fbase + (size_t)m * 64 + n] = acc[mm][nn];
        }
    }
}

// ---------------------------------------------------------------------------
// K3: per-b GEMM2.  out[b*64+i, n] = sum_k F_b[i,k]*Wo[n,k] + bo[n]
// F_b viewed as 64 x 4096 row-major (contiguous in (j,k')). 1/H folded in K1.
// block: one b, dim-tile of 128. 128 threads, 8x8 per-thread tile, KC=32
// ---------------------------------------------------------------------------
__global__ __launch_bounds__(128) void gemm2_kernel(
    const float* __restrict__ Wo, const float* __restrict__ bo,
    float* __restrict__ outp)
{
    __shared__ float As[64][33];
    __shared__ float Bs[128][33];
    const int b  = blockIdx.y;
    const int n0 = blockIdx.x * 128;
    const int tid = threadIdx.x;
    const int my = tid >> 4;   // 0..7
    const int nx = tid & 15;   // 0..15

    float acc[8][8];
#pragma unroll
    for (int a = 0; a < 8; a++)
#pragma unroll
        for (int bb2 = 0; bb2 < 8; bb2++) acc[a][bb2] = 0.f;

    const float* A = g_F + (size_t)b * 262144;

    for (int k0 = 0; k0 < 4096; k0 += 32) {
#pragma unroll
        for (int l = 0; l < 4; l++) {
            int idx = l * 128 + tid;        // 0..511 float4 slots
            int r = idx >> 3, seg = idx & 7;
            float4 t = *(const float4*)&A[(size_t)r * 4096 + k0 + seg * 4];
            As[r][seg*4+0] = t.x; As[r][seg*4+1] = t.y;
            As[r][seg*4+2] = t.z; As[r][seg*4+3] = t.w;
        }
#pragma unroll
        for (int l = 0; l < 8; l++) {
            int idx = l * 128 + tid;        // 0..1023 float4 slots
            int r = idx >> 3, seg = idx & 7;
            float4 t = *(const float4*)&Wo[(size_t)(n0 + r) * 4096 + k0 + seg * 4];
            Bs[r][seg*4+0] = t.x; Bs[r][seg*4+1] = t.y;
            Bs[r][seg*4+2] = t.z; Bs[r][seg*4+3] = t.w;
        }
        __syncthreads();
#pragma unroll
        for (int kk = 0; kk < 32; kk++) {
            float a[8], bb[8];
#pragma unroll
            for (int mm = 0; mm < 8; mm++) a[mm] = As[my + mm*8][kk];
#pragma unroll
            for (int nn = 0; nn < 8; nn++) bb[nn] = Bs[nx + nn*16][kk];
#pragma unroll
            for (int mm = 0; mm < 8; mm++)
#pragma unroll
                for (int nn = 0; nn < 8; nn++)
                    acc[mm][nn] = fmaf(a[mm], bb[nn], acc[mm][nn]);
        }
        __syncthreads();
    }

#pragma unroll
    for (int mm = 0; mm < 8; mm++) {
        int i = my + mm * 8;
#pragma unroll
        for (int nn = 0; nn < 8; nn++) {
            int n = n0 + nx + nn * 16;
            outp[((size_t)b * 64 + i) * DIMN + n] = acc[mm][nn] + bo[n];
        }
    }
}

// ---------------------------------------------------------------------------
extern "C" void kernel_launch(void* const* d_in, const int* in_sizes, int n_in,
                              void* d_out, int out_size)
{
    const float* x  = (const float*)d_in[0];
    const float* Wq = (const float*)d_in[1];
    const float* bq = (const float*)d_in[2];
    const float* Wk = (const float*)d_in[3];
    const float* bk = (const float*)d_in[4];
    const float* Wv = (const float*)d_in[5];
    const float* bv = (const float*)d_in[6];
    const float* cv = (const float*)d_in[7];   // core_value (8,64)
    const float* Wo = (const float*)d_in[8];
    const float* bo = (const float*)d_in[9];
    float* out = (float*)d_out;

    float *gq, *gk, *gv, *gF;
    cudaGetSymbolAddress((void**)&gq, g_q);
    cudaGetSymbolAddress((void**)&gk, g_k);
    cudaGetSymbolAddress((void**)&gv, g_v);
    cudaGetSymbolAddress((void**)&gF, g_F);

    dim3 gridP(4, 128);  // 512/128 col-tiles, 16384/128 row-tiles
    proj_kernel<<<gridP, 256>>>(x, Wq, bq, cv,      gq);
    proj_kernel<<<gridP, 256>>>(x, Wk, bk, nullptr, gk);
    proj_kernel<<<gridP, 256>>>(x, Wv, bv, nullptr, gv);

    gemm1_kernel<<<dim3(32, NB), 128>>>(gF);
    gemm2_kernel<<<dim3(4, NB), 128>>>(Wo, bo, out);
}

// round 2
// speedup vs baseline: 1.0009x; 1.0009x over previous
#include <cuda_runtime.h>
#include <cstdint>
#include <cstddef>

// Problem constants
#define DIMN   512
#define N_ROWS 16384          // B*L = 256*64
#define NB     256            // batch
// r = (c,h), c in [0,8), h in [0,64)  -> 512 "rank" terms

// ---------------- scratch (static device allocations; no cudaMalloc) -------
__device__ float g_q[(size_t)N_ROWS * DIMN];   // core_value/H -folded q projection
__device__ float g_k[(size_t)N_ROWS * DIMN];
__device__ float g_v[(size_t)N_ROWS * DIMN];
__device__ float g_F[(size_t)NB * 4096 * 64];  // per-b F[(i,j), k'] , 256 MB

// ---------------------------------------------------------------------------
// K1: projection GEMM  C[n,m] = sum_p x[n,p]*W[m,p] + bias[m]
//     optional fold: *= cv[c(n), h(m)] * 0.125   (only for q)
// tile 128x128, 256 threads, 8x8 per-thread tile
// ---------------------------------------------------------------------------
__global__ __launch_bounds__(256) void proj_kernel(
    const float* __restrict__ x, const float* __restrict__ W,
    const float* __restrict__ bias, const float* __restrict__ cv,
    float* __restrict__ outp)
{
    __shared__ float Xs[128][17];
    __shared__ float Ws[128][17];
    const int row0 = blockIdx.y * 128;
    const int col0 = blockIdx.x * 128;
    const int tid  = threadIdx.x;
    const int ry = tid >> 4;    // 0..15
    const int cx = tid & 15;    // 0..15

    float acc[8][8];
#pragma unroll
    for (int a = 0; a < 8; a++)
#pragma unroll
        for (int b = 0; b < 8; b++) acc[a][b] = 0.f;

    for (int p0 = 0; p0 < DIMN; p0 += 16) {
#pragma unroll
        for (int l = 0; l < 2; l++) {
            int idx = l * 256 + tid;          // 0..511 float4 slots
            int r = idx >> 2, seg = idx & 3;
            float4 t = *(const float4*)&x[(size_t)(row0 + r) * DIMN + p0 + seg * 4];
            Xs[r][seg*4+0] = t.x; Xs[r][seg*4+1] = t.y;
            Xs[r][seg*4+2] = t.z; Xs[r][seg*4+3] = t.w;
            float4 u = *(const float4*)&W[(size_t)(col0 + r) * DIMN + p0 + seg * 4];
            Ws[r][seg*4+0] = u.x; Ws[r][seg*4+1] = u.y;
            Ws[r][seg*4+2] = u.z; Ws[r][seg*4+3] = u.w;
        }
        __syncthreads();
#pragma unroll
        for (int pp = 0; pp < 16; pp++) {
            float a[8], b[8];
#pragma unroll
            for (int rm = 0; rm < 8; rm++) a[rm] = Xs[ry + rm*16][pp];
#pragma unroll
            for (int cn = 0; cn < 8; cn++) b[cn] = Ws[cx + cn*16][pp];
#pragma unroll
            for (int rm = 0; rm < 8; rm++)
#pragma unroll
                for (int cn = 0; cn < 8; cn++)
                    acc[rm][cn] = fmaf(a[rm], b[cn], acc[rm][cn]);
        }
        __syncthreads();
    }

#pragma unroll
    for (int rm = 0; rm < 8; rm++) {
        int r = row0 + ry + rm * 16;
#pragma unroll
        for (int cn = 0; cn < 8; cn++) {
            int cm = col0 + cx + cn * 16;
            float val = acc[rm][cn] + bias[cm];
            if (cv) {
                int c = r >> 11;       // flat-reshape: core index = row >> 11
                int h = cm & 63;
                val *= cv[c * 64 + h] * 0.125f;   // fold core_value and 1/H
            }
            outp[(size_t)r * DIMN + cm] = val;
        }
    }
}

// ---------------------------------------------------------------------------
// K2: per-b GEMM1.  F[(i,j), n] = sum_r (wq[i,r] * K[j,r]) * V[n,r]
// block: one b, i-pair {i0, i0+1}, all j (m = i_local*64 + j in [0,128)), n in [0,64)
// reduction r split by core c (chunks of 64 = one h-block, contiguous in gmem)
// 128 threads, 8x8 per-thread tile
// ---------------------------------------------------------------------------
__global__ __launch_bounds__(128) void gemm1_kernel(float* __restrict__ gF)
{
    __shared__ float Ks[64][65];
    __shared__ float Vs[64][65];
    __shared__ float Qs[2][64];
    const int b  = blockIdx.y;
    const int i0 = blockIdx.x * 2;
    const int tid = threadIdx.x;
    const int my = tid >> 3;   // 0..15
    const int nx = tid & 7;    // 0..7

    float acc[8][8];
#pragma unroll
    for (int a = 0; a < 8; a++)
#pragma unroll
        for (int bb2 = 0; bb2 < 8; bb2++) acc[a][bb2] = 0.f;

    for (int c = 0; c < 8; c++) {
        // the (c,b) K/V block is 8 consecutive rows = 4096 contiguous floats
        const size_t base = ((size_t)c * 2048 + (size_t)b * 8) * DIMN;
#pragma unroll
        for (int l = 0; l < 8; l++) {
            int idx4 = l * 128 + tid;       // 0..1023 float4 slots, coalesced
            int o = idx4 * 4;               // linear offset in the 4096 block
            int j = ((o >> 9) << 3) | ((o >> 6) & 7);
            int h = o & 63;
            float4 t = *(const float4*)&g_k[base + o];
            Ks[j][h+0] = t.x; Ks[j][h+1] = t.y; Ks[j][h+2] = t.z; Ks[j][h+3] = t.w;
            float4 u = *(const float4*)&g_v[base + o];
            Vs[j][h+0] = u.x; Vs[j][h+1] = u.y; Vs[j][h+2] = u.z; Vs[j][h+3] = u.w;
        }
        {
            // q rows for i0, i0+1: 128 contiguous floats (i0 even)
            const size_t qbase = ((size_t)c * 2048 + (size_t)b * 8 + (i0 >> 3)) * DIMN
                               + (size_t)(i0 & 7) * 64;
            Qs[tid >> 6][tid & 63] = g_q[qbase + tid];
        }
        __syncthreads();
#pragma unroll
        for (int rr = 0; rr < 64; rr++) {
            float a[8], bb[8];
#pragma unroll
            for (int mm = 0; mm < 8; mm++) {
                int m = my + mm * 16;                       // 0..127
                a[mm] = Qs[m >> 6][rr] * Ks[m & 63][rr];    // G formed on the fly
            }
#pragma unroll
            for (int nn = 0; nn < 8; nn++)
                bb[nn] = Vs[nx + nn * 8][rr];
#pragma unroll
            for (int mm = 0; mm < 8; mm++)
#pragma unroll
                for (int nn = 0; nn < 8; nn++)
                    acc[mm][nn] = fmaf(a[mm], bb[nn], acc[mm][nn]);
        }
        __syncthreads();
    }

    const size_t fbase = (size_t)b * 262144 + (size_t)i0 * 4096;
#pragma unroll
    for (int mm = 0; mm < 8; mm++) {
        int m = my + mm * 16;
#pragma unroll
        for (int nn = 0; nn < 8; nn++) {
            int n = nx + nn * 8;
            gF[fbase + (size_t)m * 64 + n] = acc[mm][nn];
        }
    }
}

// ---------------------------------------------------------------------------
// K3: per-b GEMM2.  out[b*64+i, n] = sum_k F_b[i,k]*Wo[n,k] + bo[n]
// F_b viewed as 64 x 4096 row-major (contiguous in (j,k')). 1/H folded in K1.
// block: one b, dim-tile of 128. 128 threads, 8x8 per-thread tile, KC=32
// ---------------------------------------------------------------------------
__global__ __launch_bounds__(128) void gemm2_kernel(
    const float* __restrict__ Wo, const float* __restrict__ bo,
    float* __restrict__ outp)
{
    __shared__ float As[64][33];
    __shared__ float Bs[128][33];
    const int b  = blockIdx.y;
    const int n0 = blockIdx.x * 128;
    const int tid = threadIdx.x;
    const int my = tid >> 4;   // 0..7
    const int nx = tid & 15;   // 0..15

    float acc[8][8];
#pragma unroll
    for (int a = 0; a < 8; a++)
#pragma unroll
        for (int bb2 = 0; bb2 < 8; bb2++) acc[a][bb2] = 0.f;

    const float* A = g_F + (size_t)b * 262144;

    for (int k0 = 0; k0 < 4096; k0 += 32) {
#pragma unroll
        for (int l = 0; l < 4; l++) {
            int idx = l * 128 + tid;        // 0..511 float4 slots
            int r = idx >> 3, seg = idx & 7;
            float4 t = *(const float4*)&A[(size_t)r * 4096 + k0 + seg * 4];
            As[r][seg*4+0] = t.x; As[r][seg*4+1] = t.y;
            As[r][seg*4+2] = t.z; As[r][seg*4+3] = t.w;
        }
#pragma unroll
        for (int l = 0; l < 8; l++) {
            int idx = l * 128 + tid;        // 0..1023 float4 slots
            int r = idx >> 3, seg = idx & 7;
            float4 t = *(const float4*)&Wo[(size_t)(n0 + r) * 4096 + k0 + seg * 4];
            Bs[r][seg*4+0] = t.x; Bs[r][seg*4+1] = t.y;
            Bs[r][seg*4+2] = t.z; Bs[r][seg*4+3] = t.w;
        }
        __syncthreads();
#pragma unroll
        for (int kk = 0; kk < 32; kk++) {
            float a[8], bb[8];
#pragma unroll
            for (int mm = 0; mm < 8; mm++) a[mm] = As[my + mm*8][kk];
#pragma unroll
            for (int nn = 0; nn < 8; nn++) bb[nn] = Bs[nx + nn*16][kk];
#pragma unroll
            for (int mm = 0; mm < 8; mm++)
#pragma unroll
                for (int nn = 0; nn < 8; nn++)
                    acc[mm][nn] = fmaf(a[mm], bb[nn], acc[mm][nn]);
        }
        __syncthreads();
    }

#pragma unroll
    for (int mm = 0; mm < 8; mm++) {
        int i = my + mm * 8;
#pragma unroll
        for (int nn = 0; nn < 8; nn++) {
            int n = n0 + nx + nn * 16;
            outp[((size_t)b * 64 + i) * DIMN + n] = acc[mm][nn] + bo[n];
        }
    }
}

// ---------------------------------------------------------------------------
extern "C" void kernel_launch(void* const* d_in, const int* in_sizes, int n_in,
                              void* d_out, int out_size)
{
    const float* x  = (const float*)d_in[0];
    const float* Wq = (const float*)d_in[1];
    const float* bq = (const float*)d_in[2];
    const float* Wk = (const float*)d_in[3];
    const float* bk = (const float*)d_in[4];
    const float* Wv = (const float*)d_in[5];
    const float* bv = (const float*)d_in[6];
    const float* cv = (const float*)d_in[7];   // core_value (8,64)
    const float* Wo = (const float*)d_in[8];
    const float* bo = (const float*)d_in[9];
    float* out = (float*)d_out;

    float *gq, *gk, *gv, *gF;
    cudaGetSymbolAddress((void**)&gq, g_q);
    cudaGetSymbolAddress((void**)&gk, g_k);
    cudaGetSymbolAddress((void**)&gv, g_v);
    cudaGetSymbolAddress((void**)&gF, g_F);

    dim3 gridP(4, 128);  // 512/128 col-tiles, 16384/128 row-tiles
    proj_kernel<<<gridP, 256>>>(x, Wq, bq, cv,      gq);
    proj_kernel<<<gridP, 256>>>(x, Wk, bk, nullptr, gk);
    proj_kernel<<<gridP, 256>>>(x, Wv, bv, nullptr, gv);

    gemm1_kernel<<<dim3(32, NB), 128>>>(gF);
    gemm2_kernel<<<dim3(4, NB), 128>>>(Wo, bo, out);
}

// round 4
// speedup vs baseline: 2.3701x; 2.3679x over previous
#include <cuda_runtime.h>
#include <cuda_bf16.h>
#include <cstdint>
#include <cstddef>

using bf16 = __nv_bfloat16;

// ---------------- static scratch (no cudaMalloc allowed) -------------------
__device__ bf16  g_xhi[(size_t)16384*512], g_xlo[(size_t)16384*512];
__device__ bf16  g_wqh[512*512], g_wql[512*512];
__device__ bf16  g_wkh[512*512], g_wkl[512*512];
__device__ bf16  g_wvh[512*512], g_wvl[512*512];
__device__ bf16  g_woh[(size_t)512*4096], g_wol[(size_t)512*4096];
__device__ float g_q[(size_t)16384*512],  g_k[(size_t)16384*512];
__device__ bf16  g_vhi[(size_t)16384*512], g_vlo[(size_t)16384*512];
__device__ bf16  g_Fhi[(size_t)16384*4096], g_Flo[(size_t)16384*4096];

// ---------------- helpers ----------------------------------------------------
__device__ __forceinline__ uint32_t smem_u32(const void* p) {
    uint32_t a;
    asm("{ .reg .u64 t; cvta.to.shared.u64 t, %1; cvt.u32.u64 %0, t; }"
        : "=r"(a) : "l"(p));
    return a;
}
__device__ __forceinline__ void cp16(uint32_t dst, const void* src) {
    asm volatile("cp.async.cg.shared.global [%0], [%1], 16;"
                 :: "r"(dst), "l"(src) : "memory");
}
#define CP_COMMIT() asm volatile("cp.async.commit_group;" ::: "memory")
#define CP_WAIT(n)  asm volatile("cp.async.wait_group %0;" :: "n"(n) : "memory")

__device__ __forceinline__ void mma16816(float* c, const uint32_t* a, const uint32_t* b) {
    asm volatile(
        "mma.sync.aligned.m16n8k16.row.col.f32.bf16.bf16.f32 "
        "{%0,%1,%2,%3}, {%4,%5,%6,%7}, {%8,%9}, {%0,%1,%2,%3};"
        : "+f"(c[0]), "+f"(c[1]), "+f"(c[2]), "+f"(c[3])
        : "r"(a[0]), "r"(a[1]), "r"(a[2]), "r"(a[3]), "r"(b[0]), "r"(b[1]));
}
__device__ __forceinline__ void bsplit(float f, bf16& h, bf16& l) {
    h = __float2bfloat16(f);
    l = __float2bfloat16(f - __bfloat162float(h));
}

// ---------------------------------------------------------------------------
// split_kernel: fp32 -> bf16 hi/lo
// ---------------------------------------------------------------------------
__global__ void split_kernel(const float* __restrict__ in,
                             bf16* __restrict__ hi, bf16* __restrict__ lo, int n) {
    int i = blockIdx.x * blockDim.x + threadIdx.x;
    if (i >= n) return;
    bf16 h, l; bsplit(in[i], h, l);
    hi[i] = h; lo[i] = l;
}

// ---------------------------------------------------------------------------
// mm_kernel: C(M x N) = A(M x K) @ B(N x K)^T via split-bf16 3-MMA (mma.sync)
//   CTA tile 128x128, 8 warps (2Mx4N) of 64x32, K-chunk 32, cp.async 2-stage.
//   mode 0: q  -> fp32 scramble-write, *cv/8 + bias
//   mode 1: k  -> fp32 scramble-write + bias
//   mode 2: v  -> bf16 hi/lo scramble-write + bias
//   mode 3: out-> fp32 row-major + bias
// ---------------------------------------------------------------------------
#define MM_STAGE 40960           // AHI(10240) ALO BHI BLO, pitch 40 bf16 = 80B
#define MM_SMEM  (2 * MM_STAGE)

__global__ __launch_bounds__(256) void mm_kernel(
    const bf16* __restrict__ Ahi, const bf16* __restrict__ Alo, int lda,
    const bf16* __restrict__ Bhi, const bf16* __restrict__ Blo, int ldb,
    int kTot, const float* __restrict__ bias, const float* __restrict__ cv,
    float* __restrict__ out0, bf16* __restrict__ outHi, bf16* __restrict__ outLo,
    int mode)
{
    extern __shared__ char sm[];
    const int tid = threadIdx.x, ln = tid & 31, wid = tid >> 5;
    const int g = ln >> 2, t = ln & 3;
    const int mw = wid >> 2, nw = wid & 3;
    const int m0 = blockIdx.y * 128, n0 = blockIdx.x * 128;
    const uint32_t sb = smem_u32(sm);

    float c[4][4][4];
#pragma unroll
    for (int a = 0; a < 4; a++)
#pragma unroll
        for (int b = 0; b < 4; b++)
#pragma unroll
            for (int d = 0; d < 4; d++) c[a][b][d] = 0.f;

    const int nCh = kTot >> 5;

#define LOAD_CHUNK(kc, s) do {                                                 \
    int _k0 = (kc) << 5;                                                       \
    uint32_t _b = sb + (s) * MM_STAGE;                                         \
    _Pragma("unroll")                                                          \
    for (int _it = 0; _it < 2; _it++) {                                        \
        int _idx = _it * 256 + tid, _r = _idx >> 2, _sg = _idx & 3;            \
        size_t _sa = (size_t)(m0 + _r) * lda + _k0 + _sg * 8;                  \
        size_t _sbo = (size_t)(n0 + _r) * ldb + _k0 + _sg * 8;                 \
        uint32_t _d = _r * 80 + _sg * 16;                                      \
        cp16(_b + _d,         Ahi + _sa);                                      \
        cp16(_b + 10240 + _d, Alo + _sa);                                      \
        cp16(_b + 20480 + _d, Bhi + _sbo);                                     \
        cp16(_b + 30720 + _d, Blo + _sbo);                                     \
    }                                                                          \
    CP_COMMIT();                                                               \
} while (0)

    LOAD_CHUNK(0, 0);

    for (int kc = 0; kc < nCh; kc++) {
        if (kc + 1 < nCh) { LOAD_CHUNK(kc + 1, (kc + 1) & 1); CP_WAIT(1); }
        else              { CP_WAIT(0); }
        __syncthreads();

        const char* base = sm + (kc & 1) * MM_STAGE;
        const char* aH = base, *aL = base + 10240, *bH = base + 20480, *bL = base + 30720;
#pragma unroll
        for (int ks = 0; ks < 2; ks++) {
            const int colb = ks * 32 + t * 4;
            uint32_t ah[4][4], al[4][4];
#pragma unroll
            for (int mt = 0; mt < 4; mt++) {
                int r0 = (mw * 64 + mt * 16 + g) * 80 + colb;
                ah[mt][0] = *(const uint32_t*)(aH + r0);
                ah[mt][1] = *(const uint32_t*)(aH + r0 + 640);
                ah[mt][2] = *(const uint32_t*)(aH + r0 + 16);
                ah[mt][3] = *(const uint32_t*)(aH + r0 + 656);
                al[mt][0] = *(const uint32_t*)(aL + r0);
                al[mt][1] = *(const uint32_t*)(aL + r0 + 640);
                al[mt][2] = *(const uint32_t*)(aL + r0 + 16);
                al[mt][3] = *(const uint32_t*)(aL + r0 + 656);
            }
#pragma unroll
            for (int nt = 0; nt < 4; nt++) {
                int nb = (nw * 32 + nt * 8 + g) * 80 + colb;
                uint32_t bh[2], bl[2];
                bh[0] = *(const uint32_t*)(bH + nb);
                bh[1] = *(const uint32_t*)(bH + nb + 16);
                bl[0] = *(const uint32_t*)(bL + nb);
                bl[1] = *(const uint32_t*)(bL + nb + 16);
#pragma unroll
                for (int mt = 0; mt < 4; mt++) {
                    mma16816(c[mt][nt], ah[mt], bh);
                    mma16816(c[mt][nt], ah[mt], bl);
                    mma16816(c[mt][nt], al[mt], bh);
                }
            }
        }
        __syncthreads();
    }

    // epilogue
#pragma unroll
    for (int mt = 0; mt < 4; mt++)
#pragma unroll
        for (int nt = 0; nt < 4; nt++) {
            int col = n0 + nw * 32 + nt * 8 + t * 2;
            float b0 = bias[col], b1 = bias[col + 1];
#pragma unroll
            for (int hseg = 0; hseg < 2; hseg++) {
                int row = m0 + mw * 64 + mt * 16 + g + hseg * 8;
                float v0 = c[mt][nt][hseg * 2 + 0] + b0;
                float v1 = c[mt][nt][hseg * 2 + 1] + b1;
                if (mode == 3) {
                    *(float2*)&out0[(size_t)row * 512 + col] = make_float2(v0, v1);
                } else {
                    int core = row >> 11, bb = (row >> 3) & 255;
                    int ii = (row & 7) * 8 + (col >> 6), hh = col & 63;
                    size_t dst = (size_t)(bb * 64 + ii) * 512 + core * 64 + hh;
                    if (mode == 0) {
                        v0 *= cv[core * 64 + hh]     * 0.125f;
                        v1 *= cv[core * 64 + hh + 1] * 0.125f;
                        *(float2*)&out0[dst] = make_float2(v0, v1);
                    } else if (mode == 1) {
                        *(float2*)&out0[dst] = make_float2(v0, v1);
                    } else {
                        bf16 h0, l0, h1, l1; bsplit(v0, h0, l0); bsplit(v1, h1, l1);
                        *(__nv_bfloat162*)&outHi[dst] = __halves2bfloat162(h0, h1);
                        *(__nv_bfloat162*)&outLo[dst] = __halves2bfloat162(l0, l1);
                    }
                }
            }
        }
#undef LOAD_CHUNK
}

// ---------------------------------------------------------------------------
// gemm1_kernel: per (b, i0): F[m=(iL,j), n] = sum_r q[i,r]k[j,r] v[n,r]
//   M=128 (2 i's x 64 j), N=64, K=512 in 8 chunks of 64.
//   G built fp32 in smem -> split bf16; V pre-split, staged via cp.async.
//   8 warps (4M x 2N), warp tile 32x32. Writes F as bf16 hi/lo.
// ---------------------------------------------------------------------------
#define G1_GHI 0
#define G1_GLO 18432
#define G1_VHI 36864
#define G1_VLO 46080
#define G1_KS  55296     /* 64 x 66 fp32 */
#define G1_QS  72192     /* 2 x 64 fp32  */
#define G1_SMEM 72704

__global__ __launch_bounds__(256) void gemm1_kernel()
{
    extern __shared__ char sm[];
    const uint32_t sb = smem_u32(sm);
    float* Ks = (float*)(sm + G1_KS);
    float* Qs = (float*)(sm + G1_QS);
    const int tid = threadIdx.x, ln = tid & 31, wid = tid >> 5;
    const int g = ln >> 2, t = ln & 3;
    const int mw = wid >> 1, nw = wid & 1;
    const int b = blockIdx.y, i0 = blockIdx.x * 2;

    float c[2][4][4];
#pragma unroll
    for (int a = 0; a < 2; a++)
#pragma unroll
        for (int bb = 0; bb < 4; bb++)
#pragma unroll
            for (int d = 0; d < 4; d++) c[a][bb][d] = 0.f;

    for (int kc = 0; kc < 8; kc++) {
        const int r0 = kc << 6;
        __syncthreads();   // previous chunk's mma reads done before overwrite

        // V hi/lo via cp.async: 64 rows x 8 uint4 per split
#pragma unroll
        for (int it = 0; it < 2; it++) {
            int idx = it * 256 + tid, r = idx >> 3, sg = idx & 7;
            size_t src = (size_t)(b * 64 + r) * 512 + r0 + sg * 8;
            uint32_t d = r * 144 + sg * 16;
            cp16(sb + G1_VHI + d, g_vhi + src);
            cp16(sb + G1_VLO + d, g_vlo + src);
        }
        CP_COMMIT();
        // K tile fp32 (for build): 64 rows x 16 float4
#pragma unroll
        for (int it = 0; it < 4; it++) {
            int idx = it * 256 + tid, r = idx >> 4, sg = idx & 15;
            float4 v = *(const float4*)&g_k[(size_t)(b * 64 + r) * 512 + r0 + sg * 4];
            Ks[r * 66 + sg * 4 + 0] = v.x; Ks[r * 66 + sg * 4 + 1] = v.y;
            Ks[r * 66 + sg * 4 + 2] = v.z; Ks[r * 66 + sg * 4 + 3] = v.w;
        }
        if (tid < 128)
            Qs[tid] = g_q[(size_t)(b * 64 + i0 + (tid >> 6)) * 512 + r0 + (tid & 63)];
        __syncthreads();

        // build G tile: 128 rows x 64 cols, split bf16 hi/lo
        {
            const int m = (wid & 3) * 32 + ln;      // 0..127
            const int half = wid >> 2;              // 0..1 -> cols 0..31 / 32..63
            const float* qrow = Qs + (m >> 6) * 64;
            const float* krow = Ks + (m & 63) * 66;
            uint16_t* ghr = (uint16_t*)(sm + G1_GHI) + m * 72;
            uint16_t* glr = (uint16_t*)(sm + G1_GLO) + m * 72;
#pragma unroll
            for (int cc = 0; cc < 16; cc++) {
                int c0 = half * 32 + cc * 2;
                float p0 = qrow[c0]     * krow[c0];
                float p1 = qrow[c0 + 1] * krow[c0 + 1];
                bf16 h0, l0, h1, l1; bsplit(p0, h0, l0); bsplit(p1, h1, l1);
                *(uint32_t*)(ghr + c0) =
                    (uint32_t)__bfloat16_as_ushort(h0) | ((uint32_t)__bfloat16_as_ushort(h1) << 16);
                *(uint32_t*)(glr + c0) =
                    (uint32_t)__bfloat16_as_ushort(l0) | ((uint32_t)__bfloat16_as_ushort(l1) << 16);
            }
        }
        CP_WAIT(0);
        __syncthreads();

        // mma: warp tile 32x32, K=64 (4 k16 steps)
        const char* aH = sm + G1_GHI, *aL = sm + G1_GLO;
        const char* bH = sm + G1_VHI, *bL = sm + G1_VLO;
#pragma unroll
        for (int ks = 0; ks < 4; ks++) {
            const int colb = ks * 32 + t * 4;
            uint32_t ah[2][4], al[2][4];
#pragma unroll
            for (int mt = 0; mt < 2; mt++) {
                int ro = (mw * 32 + mt * 16 + g) * 144 + colb;
                ah[mt][0] = *(const uint32_t*)(aH + ro);
                ah[mt][1] = *(const uint32_t*)(aH + ro + 1152);
                ah[mt][2] = *(const uint32_t*)(aH + ro + 16);
                ah[mt][3] = *(const uint32_t*)(aH + ro + 1168);
                al[mt][0] = *(const uint32_t*)(aL + ro);
                al[mt][1] = *(const uint32_t*)(aL + ro + 1152);
                al[mt][2] = *(const uint32_t*)(aL + ro + 16);
                al[mt][3] = *(const uint32_t*)(aL + ro + 1168);
            }
#pragma unroll
            for (int nt = 0; nt < 4; nt++) {
                int nb = (nw * 32 + nt * 8 + g) * 144 + colb;
                uint32_t bh[2], bl[2];
                bh[0] = *(const uint32_t*)(bH + nb);
                bh[1] = *(const uint32_t*)(bH + nb + 16);
                bl[0] = *(const uint32_t*)(bL + nb);
                bl[1] = *(const uint32_t*)(bL + nb + 16);
#pragma unroll
                for (int mt = 0; mt < 2; mt++) {
                    mma16816(c[mt][nt], ah[mt], bh);
                    mma16816(c[mt][nt], ah[mt], bl);
                    mma16816(c[mt][nt], al[mt], bh);
                }
            }
        }
    }

    // epilogue: write F hi/lo
#pragma unroll
    for (int mt = 0; mt < 2; mt++)
#pragma unroll
        for (int nt = 0; nt < 4; nt++) {
            int n = nw * 32 + nt * 8 + t * 2;
#pragma unroll
            for (int hseg = 0; hseg < 2; hseg++) {
                int m = mw * 32 + mt * 16 + g + hseg * 8;
                size_t rowF = (size_t)(b * 64 + i0 + (m >> 6));
                size_t dst = rowF * 4096 + (size_t)(m & 63) * 64 + n;
                float v0 = c[mt][nt][hseg * 2 + 0];
                float v1 = c[mt][nt][hseg * 2 + 1];
                bf16 h0, l0, h1, l1; bsplit(v0, h0, l0); bsplit(v1, h1, l1);
                *(__nv_bfloat162*)&g_Fhi[dst] = __halves2bfloat162(h0, h1);
                *(__nv_bfloat162*)&g_Flo[dst] = __halves2bfloat162(l0, l1);
            }
        }
}

// ---------------------------------------------------------------------------
extern "C" void kernel_launch(void* const* d_in, const int* in_sizes, int n_in,
                              void* d_out, int out_size)
{
    const float* x  = (const float*)d_in[0];
    const float* Wq = (const float*)d_in[1];
    const float* bq = (const float*)d_in[2];
    const float* Wk = (const float*)d_in[3];
    const float* bk = (const float*)d_in[4];
    const float* Wv = (const float*)d_in[5];
    const float* bv = (const float*)d_in[6];
    const float* cv = (const float*)d_in[7];
    const float* Wo = (const float*)d_in[8];
    const float* bo = (const float*)d_in[9];
    float* out = (float*)d_out;

    cudaFuncSetAttribute(mm_kernel, cudaFuncAttributeMaxDynamicSharedMemorySize, MM_SMEM);
    cudaFuncSetAttribute(gemm1_kernel, cudaFuncAttributeMaxDynamicSharedMemorySize, G1_SMEM);

    bf16 *xhi, *xlo, *wqh, *wql, *wkh, *wkl, *wvh, *wvl, *woh, *wol;
    bf16 *vhi, *vlo, *Fhi, *Flo;
    float *q, *k;
    cudaGetSymbolAddress((void**)&xhi, g_xhi); cudaGetSymbolAddress((void**)&xlo, g_xlo);
    cudaGetSymbolAddress((void**)&wqh, g_wqh); cudaGetSymbolAddress((void**)&wql, g_wql);
    cudaGetSymbolAddress((void**)&wkh, g_wkh); cudaGetSymbolAddress((void**)&wkl, g_wkl);
    cudaGetSymbolAddress((void**)&wvh, g_wvh); cudaGetSymbolAddress((void**)&wvl, g_wvl);
    cudaGetSymbolAddress((void**)&woh, g_woh); cudaGetSymbolAddress((void**)&wol, g_wol);
    cudaGetSymbolAddress((void**)&q, g_q);     cudaGetSymbolAddress((void**)&k, g_k);
    cudaGetSymbolAddress((void**)&vhi, g_vhi); cudaGetSymbolAddress((void**)&vlo, g_vlo);
    cudaGetSymbolAddress((void**)&Fhi, g_Fhi); cudaGetSymbolAddress((void**)&Flo, g_Flo);

    split_kernel<<<32768, 256>>>(x,  xhi, xlo, 16384 * 512);
    split_kernel<<<1024,  256>>>(Wq, wqh, wql, 512 * 512);
    split_kernel<<<1024,  256>>>(Wk, wkh, wkl, 512 * 512);
    split_kernel<<<1024,  256>>>(Wv, wvh, wvl, 512 * 512);
    split_kernel<<<8192,  256>>>(Wo, woh, wol, 512 * 4096);

    dim3 gp(4, 128);   // N-tiles, M-tiles
    mm_kernel<<<gp, 256, MM_SMEM>>>(xhi, xlo, 512, wqh, wql, 512, 512,
                                    bq, cv, q, nullptr, nullptr, 0);
    mm_kernel<<<gp, 256, MM_SMEM>>>(xhi, xlo, 512, wkh, wkl, 512, 512,
                                    bk, nullptr, k, nullptr, nullptr, 1);
    mm_kernel<<<gp, 256, MM_SMEM>>>(xhi, xlo, 512, wvh, wvl, 512, 512,
                                    bv, nullptr, nullptr, vhi, vlo, 2);

    gemm1_kernel<<<dim3(32, 256), 256, G1_SMEM>>>();

    mm_kernel<<<gp, 256, MM_SMEM>>>(Fhi, Flo, 4096, woh, wol, 4096, 4096,
                                    bo, nullptr, out, nullptr, nullptr, 3);
}

// round 5
// speedup vs baseline: 2.9331x; 1.2375x over previous
#include <cuda_runtime.h>
#include <cuda_bf16.h>
#include <cstdint>
#include <cstddef>

using bf16 = __nv_bfloat16;

// ---------------- static scratch (no cudaMalloc allowed) -------------------
__device__ bf16  g_xhi[(size_t)16384*512], g_xlo[(size_t)16384*512];
__device__ bf16  g_wqh[512*512], g_wql[512*512];
__device__ bf16  g_wkh[512*512], g_wkl[512*512];
__device__ bf16  g_wvh[512*512], g_wvl[512*512];
__device__ bf16  g_woh[(size_t)512*4096], g_wol[(size_t)512*4096];
__device__ float g_q[(size_t)16384*512];
__device__ float g_k[(size_t)16384*512];          // TRANSPOSED: [b][r][j] 256x512x64
__device__ bf16  g_vhi[(size_t)16384*512], g_vlo[(size_t)16384*512];
__device__ bf16  g_Fhi[(size_t)16384*4096], g_Flo[(size_t)16384*4096];

// ---------------- helpers ----------------------------------------------------
__device__ __forceinline__ uint32_t smem_u32(const void* p) {
    uint32_t a;
    asm("{ .reg .u64 t; cvta.to.shared.u64 t, %1; cvt.u32.u64 %0, t; }"
        : "=r"(a) : "l"(p));
    return a;
}
__device__ __forceinline__ void cp16(uint32_t dst, const void* src) {
    asm volatile("cp.async.cg.shared.global [%0], [%1], 16;"
                 :: "r"(dst), "l"(src) : "memory");
}
#define CP_COMMIT() asm volatile("cp.async.commit_group;" ::: "memory")
#define CP_WAIT(n)  asm volatile("cp.async.wait_group %0;" :: "n"(n) : "memory")

#define LDM_X4(r, a) \
    asm volatile("ldmatrix.sync.aligned.m8n8.x4.shared.b16 {%0,%1,%2,%3}, [%4];" \
        : "=r"((r)[0]), "=r"((r)[1]), "=r"((r)[2]), "=r"((r)[3]) : "r"(a))
#define LDM_X2(r, a) \
    asm volatile("ldmatrix.sync.aligned.m8n8.x2.shared.b16 {%0,%1}, [%2];" \
        : "=r"((r)[0]), "=r"((r)[1]) : "r"(a))

__device__ __forceinline__ void mma16816(float* c, const uint32_t* a, const uint32_t* b) {
    asm volatile(
        "mma.sync.aligned.m16n8k16.row.col.f32.bf16.bf16.f32 "
        "{%0,%1,%2,%3}, {%4,%5,%6,%7}, {%8,%9}, {%0,%1,%2,%3};"
        : "+f"(c[0]), "+f"(c[1]), "+f"(c[2]), "+f"(c[3])
        : "r"(a[0]), "r"(a[1]), "r"(a[2]), "r"(a[3]), "r"(b[0]), "r"(b[1]));
}
__device__ __forceinline__ void bsplit(float f, bf16& h, bf16& l) {
    h = __float2bfloat16(f);
    l = __float2bfloat16(f - __bfloat162float(h));
}
// pack two fp32 into bf16x2 hi word + bf16x2 lo (residual) word
__device__ __forceinline__ void pack_split(float p0, float p1, uint32_t& hi, uint32_t& lo) {
    uint32_t h;
    asm("cvt.rn.bf16x2.f32 %0, %1, %2;" : "=r"(h) : "f"(p1), "f"(p0));
    float h0 = __uint_as_float(h << 16);
    float h1 = __uint_as_float(h & 0xFFFF0000u);
    float l0 = p0 - h0, l1 = p1 - h1;
    uint32_t l;
    asm("cvt.rn.bf16x2.f32 %0, %1, %2;" : "=r"(l) : "f"(l1), "f"(l0));
    hi = h; lo = l;
}

// ---------------------------------------------------------------------------
__global__ void split_kernel(const float* __restrict__ in,
                             bf16* __restrict__ hi, bf16* __restrict__ lo, int n) {
    int i = blockIdx.x * blockDim.x + threadIdx.x;
    if (i >= n) return;
    bf16 h, l; bsplit(in[i], h, l);
    hi[i] = h; lo[i] = l;
}

// ---------------------------------------------------------------------------
// mm_kernel: C(M x N) = A(M x K) @ B(N x K)^T via split-bf16 3-MMA
//   CTA 128x128, 8 warps (2Mx4N) of 64x32, K-chunk 32, cp.async 2-stage,
//   ldmatrix fragment loads.
//   mode 0: q -> fp32 scramble + cv/8 + bias     mode 1: k -> fp32 TRANSPOSED
//   mode 2: v -> bf16 hi/lo scramble + bias      mode 3: out -> fp32 + bias
// ---------------------------------------------------------------------------
#define MM_STAGE 40960           // AHI(10240) ALO BHI BLO, pitch 40 bf16 = 80B
#define MM_SMEM  (2 * MM_STAGE)

__global__ __launch_bounds__(256, 2) void mm_kernel(
    const bf16* __restrict__ Ahi, const bf16* __restrict__ Alo, int lda,
    const bf16* __restrict__ Bhi, const bf16* __restrict__ Blo, int ldb,
    int kTot, const float* __restrict__ bias, const float* __restrict__ cv,
    float* __restrict__ out0, bf16* __restrict__ outHi, bf16* __restrict__ outLo,
    int mode)
{
    extern __shared__ char sm[];
    const int tid = threadIdx.x, ln = tid & 31, wid = tid >> 5;
    const int g = ln >> 2, t = ln & 3;
    const int mw = wid >> 2, nw = wid & 3;
    const int m0 = blockIdx.y * 128, n0 = blockIdx.x * 128;
    const uint32_t sb = smem_u32(sm);

    float c[4][4][4];
#pragma unroll
    for (int a = 0; a < 4; a++)
#pragma unroll
        for (int b = 0; b < 4; b++)
#pragma unroll
            for (int d = 0; d < 4; d++) c[a][b][d] = 0.f;

    const int nCh = kTot >> 5;

#define LOAD_CHUNK(kc, s) do {                                                 \
    int _k0 = (kc) << 5;                                                       \
    uint32_t _b = sb + (s) * MM_STAGE;                                         \
    _Pragma("unroll")                                                          \
    for (int _it = 0; _it < 2; _it++) {                                        \
        int _idx = _it * 256 + tid, _r = _idx >> 2, _sg = _idx & 3;            \
        size_t _sa = (size_t)(m0 + _r) * lda + _k0 + _sg * 8;                  \
        size_t _sbo = (size_t)(n0 + _r) * ldb + _k0 + _sg * 8;                 \
        uint32_t _d = _r * 80 + _sg * 16;                                      \
        cp16(_b + _d,         Ahi + _sa);                                      \
        cp16(_b + 10240 + _d, Alo + _sa);                                      \
        cp16(_b + 20480 + _d, Bhi + _sbo);                                     \
        cp16(_b + 30720 + _d, Blo + _sbo);                                     \
    }                                                                          \
    CP_COMMIT();                                                               \
} while (0)

    LOAD_CHUNK(0, 0);

    const uint32_t a_lane = (uint32_t)((mw * 64 + (ln & 15)) * 80 + ((ln & 16) ? 16 : 0));
    const uint32_t b_lane = (uint32_t)((nw * 32 + (ln & 7)) * 80 + ((ln & 8) ? 16 : 0));

    for (int kc = 0; kc < nCh; kc++) {
        if (kc + 1 < nCh) { LOAD_CHUNK(kc + 1, (kc + 1) & 1); CP_WAIT(1); }
        else              { CP_WAIT(0); }
        __syncthreads();

        const uint32_t stage = sb + (kc & 1) * MM_STAGE;
#pragma unroll
        for (int ks = 0; ks < 2; ks++) {
            const uint32_t kb = ks * 32;
            uint32_t ah[4][4], al[4][4];
#pragma unroll
            for (int mt = 0; mt < 4; mt++) {
                uint32_t ad = stage + a_lane + mt * (16 * 80) + kb;
                LDM_X4(ah[mt], ad);
                LDM_X4(al[mt], ad + 10240);
            }
#pragma unroll
            for (int nt = 0; nt < 4; nt++) {
                uint32_t bd = stage + 20480 + b_lane + nt * (8 * 80) + kb;
                uint32_t bh[2], bl[2];
                LDM_X2(bh, bd);
                LDM_X2(bl, bd + 10240);
#pragma unroll
                for (int mt = 0; mt < 4; mt++) {
                    mma16816(c[mt][nt], ah[mt], bh);
                    mma16816(c[mt][nt], ah[mt], bl);
                    mma16816(c[mt][nt], al[mt], bh);
                }
            }
        }
        __syncthreads();
    }

    // epilogue
#pragma unroll
    for (int mt = 0; mt < 4; mt++)
#pragma unroll
        for (int nt = 0; nt < 4; nt++) {
            int col = n0 + nw * 32 + nt * 8 + t * 2;
            float b0 = bias[col], b1 = bias[col + 1];
#pragma unroll
            for (int hseg = 0; hseg < 2; hseg++) {
                int row = m0 + mw * 64 + mt * 16 + g + hseg * 8;
                float v0 = c[mt][nt][hseg * 2 + 0] + b0;
                float v1 = c[mt][nt][hseg * 2 + 1] + b1;
                if (mode == 3) {
                    *(float2*)&out0[(size_t)row * 512 + col] = make_float2(v0, v1);
                } else {
                    int core = row >> 11, bb = (row >> 3) & 255;
                    int ii = (row & 7) * 8 + (col >> 6), hh = col & 63;
                    if (mode == 1) {
                        // transposed k: [b][r][j],  r = core*64+hh, j = ii
                        size_t rb = (size_t)bb * 512 + core * 64 + hh;
                        out0[rb * 64 + ii]       = v0;
                        out0[(rb + 1) * 64 + ii] = v1;
                    } else {
                        size_t dst = (size_t)(bb * 64 + ii) * 512 + core * 64 + hh;
                        if (mode == 0) {
                            v0 *= cv[core * 64 + hh]     * 0.125f;
                            v1 *= cv[core * 64 + hh + 1] * 0.125f;
                            *(float2*)&out0[dst] = make_float2(v0, v1);
                        } else {
                            bf16 h0, l0, h1, l1; bsplit(v0, h0, l0); bsplit(v1, h1, l1);
                            *(__nv_bfloat162*)&outHi[dst] = __halves2bfloat162(h0, h1);
                            *(__nv_bfloat162*)&outLo[dst] = __halves2bfloat162(l0, l1);
                        }
                    }
                }
            }
        }
#undef LOAD_CHUNK
}

// ---------------------------------------------------------------------------
// gemm1_kernel: per (b, i0): F[m=(iL,j), n] = sum_r q[i,r]k[j,r]v[n,r]
//   M=128, N=64, K=512 in 8 chunks of 64; cp.async double-buffered K/V/Q;
//   A-fragments (G = q.k) built DIRECTLY in registers from transposed K.
//   8 warps (4M x 2N), warp tile 32x32. Writes F as bf16 hi/lo.
// Stage layout (36352 B): K[c][j] 64x68 f32 (17408) | Vhi 64x72bf16 (9216)
//                         | Vlo (9216) | Q 2x64 f32 (512)
// ---------------------------------------------------------------------------
#define G1_STAGE 36352
#define G1_SMEM  (2 * G1_STAGE)

__global__ __launch_bounds__(256, 2) void gemm1_kernel()
{
    extern __shared__ char sm[];
    const uint32_t sb = smem_u32(sm);
    const int tid = threadIdx.x, ln = tid & 31, wid = tid >> 5;
    const int g = ln >> 2, t = ln & 3;
    const int mw = wid >> 1, nw = wid & 1;
    const int b = blockIdx.y, i0 = blockIdx.x * 2;
    const int il64 = (mw >> 1) * 64;
    const int jb = (mw & 1) * 32;

    float c[2][4][4];
#pragma unroll
    for (int a = 0; a < 2; a++)
#pragma unroll
        for (int bb = 0; bb < 4; bb++)
#pragma unroll
            for (int d = 0; d < 4; d++) c[a][bb][d] = 0.f;

#define G1_PREFETCH(kc_, s_) do {                                              \
    int _r0 = (kc_) << 6;                                                      \
    uint32_t _st = sb + (s_) * G1_STAGE;                                       \
    _Pragma("unroll")                                                          \
    for (int _it = 0; _it < 4; _it++) {                                        \
        int _i = _it * 256 + tid, _r = _i >> 4, _sg = _i & 15;                 \
        cp16(_st + _r * 272 + _sg * 16,                                        \
             g_k + ((size_t)b * 512 + _r0 + _r) * 64 + _sg * 4);               \
    }                                                                          \
    _Pragma("unroll")                                                          \
    for (int _it = 0; _it < 2; _it++) {                                        \
        int _i = _it * 256 + tid, _r = _i >> 3, _sg = _i & 7;                  \
        size_t _src = (size_t)(b * 64 + _r) * 512 + _r0 + _sg * 8;             \
        cp16(_st + 17408 + _r * 144 + _sg * 16, g_vhi + _src);                 \
        cp16(_st + 26624 + _r * 144 + _sg * 16, g_vlo + _src);                 \
    }                                                                          \
    if (tid < 32)                                                              \
        cp16(_st + 35840 + (tid >> 4) * 256 + (tid & 15) * 16,                 \
             g_q + ((size_t)(b * 64 + i0 + (tid >> 4))) * 512 + _r0 + (tid & 15) * 4); \
    CP_COMMIT();                                                               \
} while (0)

    G1_PREFETCH(0, 0);

    const uint32_t b_lane = (uint32_t)((nw * 32 + (ln & 7)) * 144 + ((ln & 8) ? 16 : 0));

    for (int kc = 0; kc < 8; kc++) {
        CP_WAIT(0);
        __syncthreads();
        if (kc < 7) G1_PREFETCH(kc + 1, (kc + 1) & 1);

        const int s = kc & 1;
        const float* Ks = (const float*)(sm + s * G1_STAGE);
        const float* Qs = (const float*)(sm + s * G1_STAGE + 35840);
        const uint32_t vbase = sb + s * G1_STAGE + 17408;

#pragma unroll
        for (int ks = 0; ks < 4; ks++) {
            const int c0e = ks * 16 + t * 2;
            float q0 = Qs[il64 + c0e],     q1 = Qs[il64 + c0e + 1];
            float q8 = Qs[il64 + c0e + 8], q9 = Qs[il64 + c0e + 9];
            uint32_t ah[2][4], al[2][4];
#pragma unroll
            for (int mt = 0; mt < 2; mt++) {
                const int j1 = jb + mt * 16 + g, j2 = j1 + 8;
                const float* K0 = Ks + (size_t)c0e * 68;
                float ka = K0[j1],          kb2 = K0[68 + j1];
                float kc2 = K0[j2],         kd  = K0[68 + j2];
                float ke = K0[8 * 68 + j1], kf  = K0[9 * 68 + j1];
                float kg = K0[8 * 68 + j2], kh  = K0[9 * 68 + j2];
                pack_split(q0 * ka,  q1 * kb2, ah[mt][0], al[mt][0]);
                pack_split(q0 * kc2, q1 * kd,  ah[mt][1], al[mt][1]);
                pack_split(q8 * ke,  q9 * kf,  ah[mt][2], al[mt][2]);
                pack_split(q8 * kg,  q9 * kh,  ah[mt][3], al[mt][3]);
            }
#pragma unroll
            for (int nt = 0; nt < 4; nt++) {
                uint32_t bd = vbase + b_lane + nt * (8 * 144) + ks * 32;
                uint32_t bh[2], bl[2];
                LDM_X2(bh, bd);
                LDM_X2(bl, bd + 9216);
#pragma unroll
                for (int mt = 0; mt < 2; mt++) {
                    mma16816(c[mt][nt], ah[mt], bh);
                    mma16816(c[mt][nt], ah[mt], bl);
                    mma16816(c[mt][nt], al[mt], bh);
                }
            }
        }
    }

    // epilogue: write F hi/lo
#pragma unroll
    for (int mt = 0; mt < 2; mt++)
#pragma unroll
        for (int nt = 0; nt < 4; nt++) {
            int n = nw * 32 + nt * 8 + t * 2;
#pragma unroll
            for (int hseg = 0; hseg < 2; hseg++) {
                int m = mw * 32 + mt * 16 + g + hseg * 8;
                size_t rowF = (size_t)(b * 64 + i0 + (m >> 6));
                size_t dst = rowF * 4096 + (size_t)(m & 63) * 64 + n;
                float v0 = c[mt][nt][hseg * 2 + 0];
                float v1 = c[mt][nt][hseg * 2 + 1];
                bf16 h0, l0, h1, l1; bsplit(v0, h0, l0); bsplit(v1, h1, l1);
                *(__nv_bfloat162*)&g_Fhi[dst] = __halves2bfloat162(h0, h1);
                *(__nv_bfloat162*)&g_Flo[dst] = __halves2bfloat162(l0, l1);
            }
        }
#undef G1_PREFETCH
}

// ---------------------------------------------------------------------------
extern "C" void kernel_launch(void* const* d_in, const int* in_sizes, int n_in,
                              void* d_out, int out_size)
{
    const float* x  = (const float*)d_in[0];
    const float* Wq = (const float*)d_in[1];
    const float* bq = (const float*)d_in[2];
    const float* Wk = (const float*)d_in[3];
    const float* bk = (const float*)d_in[4];
    const float* Wv = (const float*)d_in[5];
    const float* bv = (const float*)d_in[6];
    const float* cv = (const float*)d_in[7];
    const float* Wo = (const float*)d_in[8];
    const float* bo = (const float*)d_in[9];
    float* out = (float*)d_out;

    cudaFuncSetAttribute(mm_kernel, cudaFuncAttributeMaxDynamicSharedMemorySize, MM_SMEM);
    cudaFuncSetAttribute(gemm1_kernel, cudaFuncAttributeMaxDynamicSharedMemorySize, G1_SMEM);

    bf16 *xhi, *xlo, *wqh, *wql, *wkh, *wkl, *wvh, *wvl, *woh, *wol;
    bf16 *vhi, *vlo, *Fhi, *Flo;
    float *q, *k;
    cudaGetSymbolAddress((void**)&xhi, g_xhi); cudaGetSymbolAddress((void**)&xlo, g_xlo);
    cudaGetSymbolAddress((void**)&wqh, g_wqh); cudaGetSymbolAddress((void**)&wql, g_wql);
    cudaGetSymbolAddress((void**)&wkh, g_wkh); cudaGetSymbolAddress((void**)&wkl, g_wkl);
    cudaGetSymbolAddress((void**)&wvh, g_wvh); cudaGetSymbolAddress((void**)&wvl, g_wvl);
    cudaGetSymbolAddress((void**)&woh, g_woh); cudaGetSymbolAddress((void**)&wol, g_wol);
    cudaGetSymbolAddress((void**)&q, g_q);     cudaGetSymbolAddress((void**)&k, g_k);
    cudaGetSymbolAddress((void**)&vhi, g_vhi); cudaGetSymbolAddress((void**)&vlo, g_vlo);
    cudaGetSymbolAddress((void**)&Fhi, g_Fhi); cudaGetSymbolAddress((void**)&Flo, g_Flo);

    split_kernel<<<32768, 256>>>(x,  xhi, xlo, 16384 * 512);
    split_kernel<<<1024,  256>>>(Wq, wqh, wql, 512 * 512);
    split_kernel<<<1024,  256>>>(Wk, wkh, wkl, 512 * 512);
    split_kernel<<<1024,  256>>>(Wv, wvh, wvl, 512 * 512);
    split_kernel<<<8192,  256>>>(Wo, woh, wol, 512 * 4096);

    dim3 gp(4, 128);   // N-tiles, M-tiles
    mm_kernel<<<gp, 256, MM_SMEM>>>(xhi, xlo, 512, wqh, wql, 512, 512,
                                    bq, cv, q, nullptr, nullptr, 0);
    mm_kernel<<<gp, 256, MM_SMEM>>>(xhi, xlo, 512, wkh, wkl, 512, 512,
                                    bk, nullptr, k, nullptr, nullptr, 1);
    mm_kernel<<<gp, 256, MM_SMEM>>>(xhi, xlo, 512, wvh, wvl, 512, 512,
                                    bv, nullptr, nullptr, vhi, vlo, 2);

    gemm1_kernel<<<dim3(32, 256), 256, G1_SMEM>>>();

    mm_kernel<<<gp, 256, MM_SMEM>>>(Fhi, Flo, 4096, woh, wol, 4096, 4096,
                                    bo, nullptr, out, nullptr, nullptr, 3);
}

// round 6
// speedup vs baseline: 2.9702x; 1.0127x over previous
#include <cuda_runtime.h>
#include <cuda_bf16.h>
#include <cstdint>
#include <cstddef>

using bf16 = __nv_bfloat16;

// ---------------- static scratch (no cudaMalloc allowed) -------------------
__device__ bf16  g_xhi[(size_t)16384*512], g_xlo[(size_t)16384*512];
__device__ bf16  g_wch[(size_t)1536*512], g_wcl[(size_t)1536*512];  // [Wq;Wk;Wv]
__device__ bf16  g_woh[(size_t)512*4096], g_wol[(size_t)512*4096];
__device__ float g_q[(size_t)16384*512];
__device__ float g_k[(size_t)16384*512];          // TRANSPOSED: [b][r][j] 256x512x64
__device__ bf16  g_vhi[(size_t)16384*512], g_vlo[(size_t)16384*512];
__device__ bf16  g_Fhi[(size_t)16384*4096], g_Flo[(size_t)16384*4096];

// ---------------- helpers ----------------------------------------------------
__device__ __forceinline__ uint32_t smem_u32(const void* p) {
    uint32_t a;
    asm("{ .reg .u64 t; cvta.to.shared.u64 t, %1; cvt.u32.u64 %0, t; }"
        : "=r"(a) : "l"(p));
    return a;
}
__device__ __forceinline__ void cp16(uint32_t dst, const void* src) {
    asm volatile("cp.async.cg.shared.global [%0], [%1], 16;"
                 :: "r"(dst), "l"(src) : "memory");
}
#define CP_COMMIT() asm volatile("cp.async.commit_group;" ::: "memory")
#define CP_WAIT(n)  asm volatile("cp.async.wait_group %0;" :: "n"(n) : "memory")

#define LDM_X4(r, a) \
    asm volatile("ldmatrix.sync.aligned.m8n8.x4.shared.b16 {%0,%1,%2,%3}, [%4];" \
        : "=r"((r)[0]), "=r"((r)[1]), "=r"((r)[2]), "=r"((r)[3]) : "r"(a))
#define LDM_X2(r, a) \
    asm volatile("ldmatrix.sync.aligned.m8n8.x2.shared.b16 {%0,%1}, [%2];" \
        : "=r"((r)[0]), "=r"((r)[1]) : "r"(a))

__device__ __forceinline__ void mma16816(float* c, const uint32_t* a, const uint32_t* b) {
    asm volatile(
        "mma.sync.aligned.m16n8k16.row.col.f32.bf16.bf16.f32 "
        "{%0,%1,%2,%3}, {%4,%5,%6,%7}, {%8,%9}, {%0,%1,%2,%3};"
        : "+f"(c[0]), "+f"(c[1]), "+f"(c[2]), "+f"(c[3])
        : "r"(a[0]), "r"(a[1]), "r"(a[2]), "r"(a[3]), "r"(b[0]), "r"(b[1]));
}
__device__ __forceinline__ void bsplit(float f, bf16& h, bf16& l) {
    h = __float2bfloat16(f);
    l = __float2bfloat16(f - __bfloat162float(h));
}
__device__ __forceinline__ void pack_split(float p0, float p1, uint32_t& hi, uint32_t& lo) {
    uint32_t h;
    asm("cvt.rn.bf16x2.f32 %0, %1, %2;" : "=r"(h) : "f"(p1), "f"(p0));
    float h0 = __uint_as_float(h << 16);
    float h1 = __uint_as_float(h & 0xFFFF0000u);
    float l0 = p0 - h0, l1 = p1 - h1;
    uint32_t l;
    asm("cvt.rn.bf16x2.f32 %0, %1, %2;" : "=r"(l) : "f"(l1), "f"(l0));
    hi = h; lo = l;
}

// ---------------------------------------------------------------------------
// split4: fp32 -> bf16 hi/lo, 4 elements per thread
// ---------------------------------------------------------------------------
__global__ void split4_kernel(const float4* __restrict__ in,
                              uint2* __restrict__ hi, uint2* __restrict__ lo) {
    int i = blockIdx.x * blockDim.x + threadIdx.x;
    float4 v = in[i];
    bf16 h0,l0,h1,l1,h2,l2,h3,l3;
    bsplit(v.x,h0,l0); bsplit(v.y,h1,l1); bsplit(v.z,h2,l2); bsplit(v.w,h3,l3);
    uint2 ho, lw;
    ho.x = (uint32_t)__bfloat16_as_ushort(h0) | ((uint32_t)__bfloat16_as_ushort(h1) << 16);
    ho.y = (uint32_t)__bfloat16_as_ushort(h2) | ((uint32_t)__bfloat16_as_ushort(h3) << 16);
    lw.x = (uint32_t)__bfloat16_as_ushort(l0) | ((uint32_t)__bfloat16_as_ushort(l1) << 16);
    lw.y = (uint32_t)__bfloat16_as_ushort(l2) | ((uint32_t)__bfloat16_as_ushort(l3) << 16);
    hi[i] = ho; lo[i] = lw;
}

// ---------------------------------------------------------------------------
// mm_kernel: C(M x N) = A(M x K) @ B(N x K)^T via split-bf16 3-MMA
//   CTA 128x128, 8 warps (2Mx4N) of 64x32, K-chunk 32, cp.async 2-stage,
//   ldmatrix fragment loads.
//   mode 3: out -> fp32 row-major + bias
//   mode 4: merged projections; proj = n0>>9 selects q/k/v epilogue
// ---------------------------------------------------------------------------
#define MM_STAGE 40960
#define MM_SMEM  (2 * MM_STAGE)

__global__ __launch_bounds__(256, 2) void mm_kernel(
    const bf16* __restrict__ Ahi, const bf16* __restrict__ Alo, int lda,
    const bf16* __restrict__ Bhi, const bf16* __restrict__ Blo, int ldb,
    int kTot, const float* __restrict__ bq, const float* __restrict__ bk,
    const float* __restrict__ bv, const float* __restrict__ cv,
    float* __restrict__ outQ, float* __restrict__ outK,
    bf16* __restrict__ outVhi, bf16* __restrict__ outVlo,
    float* __restrict__ out0, const float* __restrict__ bo, int mode)
{
    extern __shared__ char sm[];
    const int tid = threadIdx.x, ln = tid & 31, wid = tid >> 5;
    const int g = ln >> 2, t = ln & 3;
    const int mw = wid >> 2, nw = wid & 3;
    const int m0 = blockIdx.y * 128, n0 = blockIdx.x * 128;
    const uint32_t sb = smem_u32(sm);

    float c[4][4][4];
#pragma unroll
    for (int a = 0; a < 4; a++)
#pragma unroll
        for (int b = 0; b < 4; b++)
#pragma unroll
            for (int d = 0; d < 4; d++) c[a][b][d] = 0.f;

    const int nCh = kTot >> 5;

#define LOAD_CHUNK(kc, s) do {                                                 \
    int _k0 = (kc) << 5;                                                       \
    uint32_t _b = sb + (s) * MM_STAGE;                                         \
    _Pragma("unroll")                                                          \
    for (int _it = 0; _it < 2; _it++) {                                        \
        int _idx = _it * 256 + tid, _r = _idx >> 2, _sg = _idx & 3;            \
        size_t _sa = (size_t)(m0 + _r) * lda + _k0 + _sg * 8;                  \
        size_t _sbo = (size_t)(n0 + _r) * ldb + _k0 + _sg * 8;                 \
        uint32_t _d = _r * 80 + _sg * 16;                                      \
        cp16(_b + _d,         Ahi + _sa);                                      \
        cp16(_b + 10240 + _d, Alo + _sa);                                      \
        cp16(_b + 20480 + _d, Bhi + _sbo);                                     \
        cp16(_b + 30720 + _d, Blo + _sbo);                                     \
    }                                                                          \
    CP_COMMIT();                                                               \
} while (0)

    LOAD_CHUNK(0, 0);

    const uint32_t a_lane = (uint32_t)((mw * 64 + (ln & 15)) * 80 + ((ln & 16) ? 16 : 0));
    const uint32_t b_lane = (uint32_t)((nw * 32 + (ln & 7)) * 80 + ((ln & 8) ? 16 : 0));

    for (int kc = 0; kc < nCh; kc++) {
        if (kc + 1 < nCh) { LOAD_CHUNK(kc + 1, (kc + 1) & 1); CP_WAIT(1); }
        else              { CP_WAIT(0); }
        __syncthreads();

        const uint32_t stage = sb + (kc & 1) * MM_STAGE;
#pragma unroll
        for (int ks = 0; ks < 2; ks++) {
            const uint32_t kb = ks * 32;
            uint32_t ah[4][4], al[4][4];
#pragma unroll
            for (int mt = 0; mt < 4; mt++) {
                uint32_t ad = stage + a_lane + mt * (16 * 80) + kb;
                LDM_X4(ah[mt], ad);
                LDM_X4(al[mt], ad + 10240);
            }
#pragma unroll
            for (int nt = 0; nt < 4; nt++) {
                uint32_t bd = stage + 20480 + b_lane + nt * (8 * 80) + kb;
                uint32_t bh[2], bl[2];
                LDM_X2(bh, bd);
                LDM_X2(bl, bd + 10240);
#pragma unroll
                for (int mt = 0; mt < 4; mt++) {
                    mma16816(c[mt][nt], ah[mt], bh);
                    mma16816(c[mt][nt], ah[mt], bl);
                    mma16816(c[mt][nt], al[mt], bh);
                }
            }
        }
        __syncthreads();
    }

    // epilogue
    const int proj = n0 >> 9;   // mode 4: 0=q 1=k 2=v
    const float* bias = (mode == 3) ? bo : (proj == 0 ? bq : proj == 1 ? bk : bv);
#pragma unroll
    for (int mt = 0; mt < 4; mt++)
#pragma unroll
        for (int nt = 0; nt < 4; nt++) {
            int colg = n0 + nw * 32 + nt * 8 + t * 2;
            int col = (mode == 3) ? colg : (colg & 511);
            float b0 = bias[col], b1 = bias[col + 1];
#pragma unroll
            for (int hseg = 0; hseg < 2; hseg++) {
                int row = m0 + mw * 64 + mt * 16 + g + hseg * 8;
                float v0 = c[mt][nt][hseg * 2 + 0] + b0;
                float v1 = c[mt][nt][hseg * 2 + 1] + b1;
                if (mode == 3) {
                    *(float2*)&out0[(size_t)row * 512 + col] = make_float2(v0, v1);
                } else {
                    int core = row >> 11, bb = (row >> 3) & 255;
                    int ii = (row & 7) * 8 + (col >> 6), hh = col & 63;
                    if (proj == 1) {
                        size_t rb = (size_t)bb * 512 + core * 64 + hh;
                        outK[rb * 64 + ii]       = v0;
                        outK[(rb + 1) * 64 + ii] = v1;
                    } else {
                        size_t dst = (size_t)(bb * 64 + ii) * 512 + core * 64 + hh;
                        if (proj == 0) {
                            v0 *= cv[core * 64 + hh]     * 0.125f;
                            v1 *= cv[core * 64 + hh + 1] * 0.125f;
                            *(float2*)&outQ[dst] = make_float2(v0, v1);
                        } else {
                            bf16 h0, l0, h1, l1; bsplit(v0, h0, l0); bsplit(v1, h1, l1);
                            *(__nv_bfloat162*)&outVhi[dst] = __halves2bfloat162(h0, h1);
                            *(__nv_bfloat162*)&outVlo[dst] = __halves2bfloat162(l0, l1);
                        }
                    }
                }
            }
        }
#undef LOAD_CHUNK
}

// ---------------------------------------------------------------------------
// gemm1_kernel: per (b, i0=4 i's): F[m=(iL,j), n] = sum_r q[i,r]k[j,r]v[n,r]
//   M=256, N=64, K=512 in 8 chunks of 64; 3-stage cp.async pipeline;
//   A-fragments (G = q.k) built in registers from transposed K.
//   512 threads, 16 warps (8M x 2N), warp tile 32x32. F written bf16 hi/lo.
// Stage (36864B): K[r][j] 64x68 f32 | Vhi 64x72 bf16 | Vlo | Q 4x64 f32
// ---------------------------------------------------------------------------
#define G1_K   0
#define G1_VHI 17408
#define G1_VLO 26624
#define G1_Q   35840
#define G1_STAGE 36864
#define G1_SMEM  (3 * G1_STAGE)

__global__ __launch_bounds__(512, 1) void gemm1_kernel()
{
    extern __shared__ char sm[];
    const uint32_t sb = smem_u32(sm);
    const int tid = threadIdx.x, ln = tid & 31, wid = tid >> 5;
    const int g = ln >> 2, t = ln & 3;
    const int mw = wid >> 1, nw = wid & 1;
    const int b = blockIdx.y, i0 = blockIdx.x * 4;
    const int il = mw >> 1;            // 0..3 (i within group of 4)
    const int jb = (mw & 1) * 32;

    float c[2][4][4];
#pragma unroll
    for (int a = 0; a < 2; a++)
#pragma unroll
        for (int bb = 0; bb < 4; bb++)
#pragma unroll
            for (int d = 0; d < 4; d++) c[a][bb][d] = 0.f;

#define G1_PREFETCH(kc_, s_) do {                                              \
    int _r0 = (kc_) << 6;                                                      \
    uint32_t _st = sb + (s_) * G1_STAGE;                                       \
    _Pragma("unroll")                                                          \
    for (int _it = 0; _it < 2; _it++) {                                        \
        int _i = _it * 512 + tid, _r = _i >> 4, _sg = _i & 15;                 \
        cp16(_st + G1_K + _r * 272 + _sg * 16,                                 \
             g_k + ((size_t)b * 512 + _r0 + _r) * 64 + _sg * 4);               \
    }                                                                          \
    {                                                                          \
        int _r = tid >> 3, _sg = tid & 7;                                      \
        size_t _src = (size_t)(b * 64 + _r) * 512 + _r0 + _sg * 8;             \
        cp16(_st + G1_VHI + _r * 144 + _sg * 16, g_vhi + _src);                \
        cp16(_st + G1_VLO + _r * 144 + _sg * 16, g_vlo + _src);                \
    }                                                                          \
    if (tid < 64)                                                              \
        cp16(_st + G1_Q + (tid >> 4) * 256 + (tid & 15) * 16,                  \
             g_q + ((size_t)(b * 64 + i0 + (tid >> 4))) * 512 + _r0 + (tid & 15) * 4); \
    CP_COMMIT();                                                               \
} while (0)

    G1_PREFETCH(0, 0);
    G1_PREFETCH(1, 1);

    const uint32_t b_lane = (uint32_t)((nw * 32 + (ln & 7)) * 144 + ((ln & 8) ? 16 : 0));

    for (int kc = 0; kc < 8; kc++) {
        if (kc == 7) CP_WAIT(0); else CP_WAIT(1);
        __syncthreads();
        if (kc < 6) G1_PREFETCH(kc + 2, (kc + 2) % 3);

        const int s = kc % 3;
        const float* Ks = (const float*)(sm + s * G1_STAGE + G1_K);
        const float* Qs = (const float*)(sm + s * G1_STAGE + G1_Q);
        const uint32_t vbase = sb + s * G1_STAGE + G1_VHI;

#pragma unroll
        for (int ks = 0; ks < 4; ks++) {
            const int c0e = ks * 16 + t * 2;
            float2 qa = *(const float2*)&Qs[il * 64 + c0e];
            float2 qb = *(const float2*)&Qs[il * 64 + c0e + 8];
            uint32_t ah[2][4], al[2][4];
#pragma unroll
            for (int mt = 0; mt < 2; mt++) {
                const int j1 = jb + mt * 16 + g, j2 = j1 + 8;
                const float* K0 = Ks + (size_t)c0e * 68;
                float ka = K0[j1],          kb2 = K0[68 + j1];
                float kc2 = K0[j2],         kd  = K0[68 + j2];
                float ke = K0[8 * 68 + j1], kf  = K0[9 * 68 + j1];
                float kg = K0[8 * 68 + j2], kh  = K0[9 * 68 + j2];
                pack_split(qa.x * ka,  qa.y * kb2, ah[mt][0], al[mt][0]);
                pack_split(qa.x * kc2, qa.y * kd,  ah[mt][1], al[mt][1]);
                pack_split(qb.x * ke,  qb.y * kf,  ah[mt][2], al[mt][2]);
                pack_split(qb.x * kg,  qb.y * kh,  ah[mt][3], al[mt][3]);
            }
#pragma unroll
            for (int nt = 0; nt < 4; nt++) {
                uint32_t bd = vbase + b_lane + nt * (8 * 144) + ks * 32;
                uint32_t bh[2], bl[2];
                LDM_X2(bh, bd);
                LDM_X2(bl, bd + 9216);
#pragma unroll
                for (int mt = 0; mt < 2; mt++) {
                    mma16816(c[mt][nt], ah[mt], bh);
                    mma16816(c[mt][nt], ah[mt], bl);
                    mma16816(c[mt][nt], al[mt], bh);
                }
            }
        }
    }

    // epilogue: write F hi/lo
#pragma unroll
    for (int mt = 0; mt < 2; mt++)
#pragma unroll
        for (int nt = 0; nt < 4; nt++) {
            int n = nw * 32 + nt * 8 + t * 2;
#pragma unroll
            for (int hseg = 0; hseg < 2; hseg++) {
                int m = mw * 32 + mt * 16 + g + hseg * 8;   // 0..255
                size_t rowF = (size_t)(b * 64 + i0 + (m >> 6));
                size_t dst = rowF * 4096 + (size_t)(m & 63) * 64 + n;
                float v0 = c[mt][nt][hseg * 2 + 0];
                float v1 = c[mt][nt][hseg * 2 + 1];
                bf16 h0, l0, h1, l1; bsplit(v0, h0, l0); bsplit(v1, h1, l1);
                *(__nv_bfloat162*)&g_Fhi[dst] = __halves2bfloat162(h0, h1);
                *(__nv_bfloat162*)&g_Flo[dst] = __halves2bfloat162(l0, l1);
            }
        }
#undef G1_PREFETCH
}

// ---------------------------------------------------------------------------
extern "C" void kernel_launch(void* const* d_in, const int* in_sizes, int n_in,
                              void* d_out, int out_size)
{
    const float* x  = (const float*)d_in[0];
    const float* Wq = (const float*)d_in[1];
    const float* bq = (const float*)d_in[2];
    const float* Wk = (const float*)d_in[3];
    const float* bk = (const float*)d_in[4];
    const float* Wv = (const float*)d_in[5];
    const float* bv = (const float*)d_in[6];
    const float* cv = (const float*)d_in[7];
    const float* Wo = (const float*)d_in[8];
    const float* bo = (const float*)d_in[9];
    float* out = (float*)d_out;

    cudaFuncSetAttribute(mm_kernel, cudaFuncAttributeMaxDynamicSharedMemorySize, MM_SMEM);
    cudaFuncSetAttribute(gemm1_kernel, cudaFuncAttributeMaxDynamicSharedMemorySize, G1_SMEM);

    bf16 *xhi, *xlo, *wch, *wcl, *woh, *wol, *vhi, *vlo, *Fhi, *Flo;
    float *q, *k;
    cudaGetSymbolAddress((void**)&xhi, g_xhi); cudaGetSymbolAddress((void**)&xlo, g_xlo);
    cudaGetSymbolAddress((void**)&wch, g_wch); cudaGetSymbolAddress((void**)&wcl, g_wcl);
    cudaGetSymbolAddress((void**)&woh, g_woh); cudaGetSymbolAddress((void**)&wol, g_wol);
    cudaGetSymbolAddress((void**)&q, g_q);     cudaGetSymbolAddress((void**)&k, g_k);
    cudaGetSymbolAddress((void**)&vhi, g_vhi); cudaGetSymbolAddress((void**)&vlo, g_vlo);
    cudaGetSymbolAddress((void**)&Fhi, g_Fhi); cudaGetSymbolAddress((void**)&Flo, g_Flo);

    // launch index:                                                     idx
    split4_kernel<<<8192, 256>>>((const float4*)x, (uint2*)xhi, (uint2*)xlo);          // 0
    split4_kernel<<<256, 256>>>((const float4*)Wq, (uint2*)wch, (uint2*)wcl);          // 1
    split4_kernel<<<256, 256>>>((const float4*)Wk,
                                (uint2*)(wch + 512*512), (uint2*)(wcl + 512*512));     // 2
    split4_kernel<<<256, 256>>>((const float4*)Wv,
                                (uint2*)(wch + 2*512*512), (uint2*)(wcl + 2*512*512)); // 3

    mm_kernel<<<dim3(12, 128), 256, MM_SMEM>>>(xhi, xlo, 512, wch, wcl, 512, 512,
                                               bq, bk, bv, cv, q, k, vhi, vlo,
                                               nullptr, nullptr, 4);                   // 4

    gemm1_kernel<<<dim3(16, 256), 512, G1_SMEM>>>();                                   // 5

    split4_kernel<<<2048, 256>>>((const float4*)Wo, (uint2*)woh, (uint2*)wol);         // 6

    mm_kernel<<<dim3(4, 128), 256, MM_SMEM>>>(Fhi, Flo, 4096, woh, wol, 4096, 4096,
                                              nullptr, nullptr, nullptr, nullptr,
                                              nullptr, nullptr, nullptr, nullptr,
                                              out, bo, 3);                             // 7
}

// round 7
// speedup vs baseline: 3.0759x; 1.0356x over previous
#include <cuda_runtime.h>
#include <cuda_bf16.h>
#include <cstdint>
#include <cstddef>

using bf16 = __nv_bfloat16;

// ---------------- static scratch (no cudaMalloc allowed) -------------------
__device__ bf16  g_xhi[(size_t)16384*512], g_xlo[(size_t)16384*512];
__device__ bf16  g_wch[(size_t)1536*512], g_wcl[(size_t)1536*512];  // [Wq;Wk;Wv]
__device__ bf16  g_woh[(size_t)512*4096], g_wol[(size_t)512*4096];
__device__ float g_q[(size_t)16384*512];
__device__ float g_k[(size_t)16384*512];          // TRANSPOSED: [b][r][j] 256x512x64
__device__ bf16  g_vhi[(size_t)16384*512], g_vlo[(size_t)16384*512];
__device__ bf16  g_Fhi[(size_t)16384*4096], g_Flo[(size_t)16384*4096];

// ---------------- helpers ----------------------------------------------------
__device__ __forceinline__ uint32_t smem_u32(const void* p) {
    uint32_t a;
    asm("{ .reg .u64 t; cvta.to.shared.u64 t, %1; cvt.u32.u64 %0, t; }"
        : "=r"(a) : "l"(p));
    return a;
}
__device__ __forceinline__ void cp16(uint32_t dst, const void* src) {
    asm volatile("cp.async.cg.shared.global [%0], [%1], 16;"
                 :: "r"(dst), "l"(src) : "memory");
}
#define CP_COMMIT() asm volatile("cp.async.commit_group;" ::: "memory")
#define CP_WAIT(n)  asm volatile("cp.async.wait_group %0;" :: "n"(n) : "memory")

#define LDM_X4(r, a) \
    asm volatile("ldmatrix.sync.aligned.m8n8.x4.shared.b16 {%0,%1,%2,%3}, [%4];" \
        : "=r"((r)[0]), "=r"((r)[1]), "=r"((r)[2]), "=r"((r)[3]) : "r"(a))
#define LDM_X2(r, a) \
    asm volatile("ldmatrix.sync.aligned.m8n8.x2.shared.b16 {%0,%1}, [%2];" \
        : "=r"((r)[0]), "=r"((r)[1]) : "r"(a))

__device__ __forceinline__ void mma16816(float* c, const uint32_t* a, const uint32_t* b) {
    asm volatile(
        "mma.sync.aligned.m16n8k16.row.col.f32.bf16.bf16.f32 "
        "{%0,%1,%2,%3}, {%4,%5,%6,%7}, {%8,%9}, {%0,%1,%2,%3};"
        : "+f"(c[0]), "+f"(c[1]), "+f"(c[2]), "+f"(c[3])
        : "r"(a[0]), "r"(a[1]), "r"(a[2]), "r"(a[3]), "r"(b[0]), "r"(b[1]));
}
__device__ __forceinline__ void bsplit(float f, bf16& h, bf16& l) {
    h = __float2bfloat16(f);
    l = __float2bfloat16(f - __bfloat162float(h));
}
__device__ __forceinline__ void pack_split(float p0, float p1, uint32_t& hi, uint32_t& lo) {
    uint32_t h;
    asm("cvt.rn.bf16x2.f32 %0, %1, %2;" : "=r"(h) : "f"(p1), "f"(p0));
    float h0 = __uint_as_float(h << 16);
    float h1 = __uint_as_float(h & 0xFFFF0000u);
    float l0 = p0 - h0, l1 = p1 - h1;
    uint32_t l;
    asm("cvt.rn.bf16x2.f32 %0, %1, %2;" : "=r"(l) : "f"(l1), "f"(l0));
    hi = h; lo = l;
}

// ---------------------------------------------------------------------------
// split4: fp32 -> bf16 hi/lo, 4 elements per thread
// ---------------------------------------------------------------------------
__global__ void split4_kernel(const float4* __restrict__ in,
                              uint2* __restrict__ hi, uint2* __restrict__ lo) {
    int i = blockIdx.x * blockDim.x + threadIdx.x;
    float4 v = in[i];
    bf16 h0,l0,h1,l1,h2,l2,h3,l3;
    bsplit(v.x,h0,l0); bsplit(v.y,h1,l1); bsplit(v.z,h2,l2); bsplit(v.w,h3,l3);
    uint2 ho, lw;
    ho.x = (uint32_t)__bfloat16_as_ushort(h0) | ((uint32_t)__bfloat16_as_ushort(h1) << 16);
    ho.y = (uint32_t)__bfloat16_as_ushort(h2) | ((uint32_t)__bfloat16_as_ushort(h3) << 16);
    lw.x = (uint32_t)__bfloat16_as_ushort(l0) | ((uint32_t)__bfloat16_as_ushort(l1) << 16);
    lw.y = (uint32_t)__bfloat16_as_ushort(l2) | ((uint32_t)__bfloat16_as_ushort(l3) << 16);
    hi[i] = ho; lo[i] = lw;
}

// ---------------------------------------------------------------------------
// mm_kernel: C(M x N) = A(M x K) @ B(N x K)^T via split-bf16 3-MMA
//   CTA 128x128, 8 warps (2Mx4N) of 64x32, K-chunk 32, cp.async 2-stage,
//   ldmatrix fragment loads.
//   mode 3: out -> fp32 row-major + bias
//   mode 4: merged projections; proj = n0>>9 selects q/k/v epilogue
// ---------------------------------------------------------------------------
#define MM_STAGE 40960
#define MM_SMEM  (2 * MM_STAGE)

__global__ __launch_bounds__(256, 2) void mm_kernel(
    const bf16* __restrict__ Ahi, const bf16* __restrict__ Alo, int lda,
    const bf16* __restrict__ Bhi, const bf16* __restrict__ Blo, int ldb,
    int kTot, const float* __restrict__ bq, const float* __restrict__ bk,
    const float* __restrict__ bv, const float* __restrict__ cv,
    float* __restrict__ outQ, float* __restrict__ outK,
    bf16* __restrict__ outVhi, bf16* __restrict__ outVlo,
    float* __restrict__ out0, const float* __restrict__ bo, int mode)
{
    extern __shared__ char sm[];
    const int tid = threadIdx.x, ln = tid & 31, wid = tid >> 5;
    const int g = ln >> 2, t = ln & 3;
    const int mw = wid >> 2, nw = wid & 3;
    const int m0 = blockIdx.y * 128, n0 = blockIdx.x * 128;
    const uint32_t sb = smem_u32(sm);

    float c[4][4][4];
#pragma unroll
    for (int a = 0; a < 4; a++)
#pragma unroll
        for (int b = 0; b < 4; b++)
#pragma unroll
            for (int d = 0; d < 4; d++) c[a][b][d] = 0.f;

    const int nCh = kTot >> 5;

#define LOAD_CHUNK(kc, s) do {                                                 \
    int _k0 = (kc) << 5;                                                       \
    uint32_t _b = sb + (s) * MM_STAGE;                                         \
    _Pragma("unroll")                                                          \
    for (int _it = 0; _it < 2; _it++) {                                        \
        int _idx = _it * 256 + tid, _r = _idx >> 2, _sg = _idx & 3;            \
        size_t _sa = (size_t)(m0 + _r) * lda + _k0 + _sg * 8;                  \
        size_t _sbo = (size_t)(n0 + _r) * ldb + _k0 + _sg * 8;                 \
        uint32_t _d = _r * 80 + _sg * 16;                                      \
        cp16(_b + _d,         Ahi + _sa);                                      \
        cp16(_b + 10240 + _d, Alo + _sa);                                      \
        cp16(_b + 20480 + _d, Bhi + _sbo);                                     \
        cp16(_b + 30720 + _d, Blo + _sbo);                                     \
    }                                                                          \
    CP_COMMIT();                                                               \
} while (0)

    LOAD_CHUNK(0, 0);

    const uint32_t a_lane = (uint32_t)((mw * 64 + (ln & 15)) * 80 + ((ln & 16) ? 16 : 0));
    const uint32_t b_lane = (uint32_t)((nw * 32 + (ln & 7)) * 80 + ((ln & 8) ? 16 : 0));

    for (int kc = 0; kc < nCh; kc++) {
        if (kc + 1 < nCh) { LOAD_CHUNK(kc + 1, (kc + 1) & 1); CP_WAIT(1); }
        else              { CP_WAIT(0); }
        __syncthreads();

        const uint32_t stage = sb + (kc & 1) * MM_STAGE;
#pragma unroll
        for (int ks = 0; ks < 2; ks++) {
            const uint32_t kb = ks * 32;
            uint32_t ah[4][4], al[4][4];
#pragma unroll
            for (int mt = 0; mt < 4; mt++) {
                uint32_t ad = stage + a_lane + mt * (16 * 80) + kb;
                LDM_X4(ah[mt], ad);
                LDM_X4(al[mt], ad + 10240);
            }
#pragma unroll
            for (int nt = 0; nt < 4; nt++) {
                uint32_t bd = stage + 20480 + b_lane + nt * (8 * 80) + kb;
                uint32_t bh[2], bl[2];
                LDM_X2(bh, bd);
                LDM_X2(bl, bd + 10240);
#pragma unroll
                for (int mt = 0; mt < 4; mt++) {
                    mma16816(c[mt][nt], ah[mt], bh);
                    mma16816(c[mt][nt], ah[mt], bl);
                    mma16816(c[mt][nt], al[mt], bh);
                }
            }
        }
        __syncthreads();
    }

    // epilogue
    const int proj = n0 >> 9;   // mode 4: 0=q 1=k 2=v
    const float* bias = (mode == 3) ? bo : (proj == 0 ? bq : proj == 1 ? bk : bv);
#pragma unroll
    for (int mt = 0; mt < 4; mt++)
#pragma unroll
        for (int nt = 0; nt < 4; nt++) {
            int colg = n0 + nw * 32 + nt * 8 + t * 2;
            int col = (mode == 3) ? colg : (colg & 511);
            float b0 = bias[col], b1 = bias[col + 1];
#pragma unroll
            for (int hseg = 0; hseg < 2; hseg++) {
                int row = m0 + mw * 64 + mt * 16 + g + hseg * 8;
                float v0 = c[mt][nt][hseg * 2 + 0] + b0;
                float v1 = c[mt][nt][hseg * 2 + 1] + b1;
                if (mode == 3) {
                    *(float2*)&out0[(size_t)row * 512 + col] = make_float2(v0, v1);
                } else {
                    int core = row >> 11, bb = (row >> 3) & 255;
                    int ii = (row & 7) * 8 + (col >> 6), hh = col & 63;
                    if (proj == 1) {
                        size_t rb = (size_t)bb * 512 + core * 64 + hh;
                        outK[rb * 64 + ii]       = v0;
                        outK[(rb + 1) * 64 + ii] = v1;
                    } else {
                        size_t dst = (size_t)(bb * 64 + ii) * 512 + core * 64 + hh;
                        if (proj == 0) {
                            v0 *= cv[core * 64 + hh]     * 0.125f;
                            v1 *= cv[core * 64 + hh + 1] * 0.125f;
                            *(float2*)&outQ[dst] = make_float2(v0, v1);
                        } else {
                            bf16 h0, l0, h1, l1; bsplit(v0, h0, l0); bsplit(v1, h1, l1);
                            *(__nv_bfloat162*)&outVhi[dst] = __halves2bfloat162(h0, h1);
                            *(__nv_bfloat162*)&outVlo[dst] = __halves2bfloat162(l0, l1);
                        }
                    }
                }
            }
        }
#undef LOAD_CHUNK
}

// ---------------------------------------------------------------------------
// gemm1_kernel: per (b, i0=4 i's): F[m=(iL,j), n] = sum_r q[i,r]k[j,r]v[n,r]
//   M=256, N=64, K=512 in 8 chunks of 64; 3-stage cp.async pipeline.
//   NEW: 16 warps x (16M x 64N) warp tiles -> A-fragment build (pack_split)
//   volume halved; B fragments via LDM_X4 (two n8 tiles per instr).
// Stage (36864B): K[r][j] 64x68 f32 | Vhi 64x72 bf16 | Vlo | Q 4x64 f32
// ---------------------------------------------------------------------------
#define G1_K   0
#define G1_VHI 17408
#define G1_VLO 26624
#define G1_Q   35840
#define G1_STAGE 36864
#define G1_SMEM  (3 * G1_STAGE)

__global__ __launch_bounds__(512, 1) void gemm1_kernel()
{
    extern __shared__ char sm[];
    const uint32_t sb = smem_u32(sm);
    const int tid = threadIdx.x, ln = tid & 31, wid = tid >> 5;
    const int g = ln >> 2, t = ln & 3;
    const int b = blockIdx.y, i0 = blockIdx.x * 4;
    const int il = wid >> 2;            // i within group of 4
    const int jb = (wid & 3) * 16;      // j base within 64

    float c[8][4];                      // [nt][frag]
#pragma unroll
    for (int a = 0; a < 8; a++)
#pragma unroll
        for (int d = 0; d < 4; d++) c[a][d] = 0.f;

#define G1_PREFETCH(kc_, s_) do {                                              \
    int _r0 = (kc_) << 6;                                                      \
    uint32_t _st = sb + (s_) * G1_STAGE;                                       \
    _Pragma("unroll")                                                          \
    for (int _it = 0; _it < 2; _it++) {                                        \
        int _i = _it * 512 + tid, _r = _i >> 4, _sg = _i & 15;                 \
        cp16(_st + G1_K + _r * 272 + _sg * 16,                                 \
             g_k + ((size_t)b * 512 + _r0 + _r) * 64 + _sg * 4);               \
    }                                                                          \
    {                                                                          \
        int _r = tid >> 3, _sg = tid & 7;                                      \
        size_t _src = (size_t)(b * 64 + _r) * 512 + _r0 + _sg * 8;             \
        cp16(_st + G1_VHI + _r * 144 + _sg * 16, g_vhi + _src);                \
        cp16(_st + G1_VLO + _r * 144 + _sg * 16, g_vlo + _src);                \
    }                                                                          \
    if (tid < 64)                                                              \
        cp16(_st + G1_Q + (tid >> 4) * 256 + (tid & 15) * 16,                  \
             g_q + ((size_t)(b * 64 + i0 + (tid >> 4))) * 512 + _r0 + (tid & 15) * 4); \
    CP_COMMIT();                                                               \
} while (0)

    G1_PREFETCH(0, 0);
    G1_PREFETCH(1, 1);

    // ldmatrix x4 lane->row map for two n8 tiles: mats [nt:klo, nt:khi, nt+1:klo, nt+1:khi]
    const uint32_t b_lane4 = (uint32_t)(((ln & 7) + ((ln & 16) ? 8 : 0)) * 144
                                        + ((ln & 8) ? 16 : 0));

    for (int kc = 0; kc < 8; kc++) {
        if (kc == 7) CP_WAIT(0); else CP_WAIT(1);
        __syncthreads();
        if (kc < 6) G1_PREFETCH(kc + 2, (kc + 2) % 3);

        const int s = kc % 3;
        const float* Ks = (const float*)(sm + s * G1_STAGE + G1_K);
        const float* Qs = (const float*)(sm + s * G1_STAGE + G1_Q);
        const uint32_t vbase = sb + s * G1_STAGE + G1_VHI;

#pragma unroll
        for (int ks = 0; ks < 4; ks++) {
            const int c0e = ks * 16 + t * 2;
            float2 qa = *(const float2*)&Qs[il * 64 + c0e];
            float2 qb = *(const float2*)&Qs[il * 64 + c0e + 8];
            const int j1 = jb + g, j2 = j1 + 8;
            const float* K0 = Ks + (size_t)c0e * 68;
            float ka = K0[j1],          kb2 = K0[68 + j1];
            float kc2 = K0[j2],         kd  = K0[68 + j2];
            float ke = K0[8 * 68 + j1], kf  = K0[9 * 68 + j1];
            float kg = K0[8 * 68 + j2], kh  = K0[9 * 68 + j2];
            uint32_t ah[4], al[4];
            pack_split(qa.x * ka,  qa.y * kb2, ah[0], al[0]);
            pack_split(qa.x * kc2, qa.y * kd,  ah[1], al[1]);
            pack_split(qb.x * ke,  qb.y * kf,  ah[2], al[2]);
            pack_split(qb.x * kg,  qb.y * kh,  ah[3], al[3]);
#pragma unroll
            for (int ntp = 0; ntp < 4; ntp++) {
                uint32_t bd = vbase + b_lane4 + ntp * (16 * 144) + ks * 32;
                uint32_t bh4[4], bl4[4];
                LDM_X4(bh4, bd);
                LDM_X4(bl4, bd + 9216);
                mma16816(c[2 * ntp],     ah, bh4);
                mma16816(c[2 * ntp],     ah, bl4);
                mma16816(c[2 * ntp],     al, bh4);
                mma16816(c[2 * ntp + 1], ah, bh4 + 2);
                mma16816(c[2 * ntp + 1], ah, bl4 + 2);
                mma16816(c[2 * ntp + 1], al, bh4 + 2);
            }
        }
    }

    // epilogue: write F hi/lo
#pragma unroll
    for (int nt = 0; nt < 8; nt++) {
        int n = nt * 8 + t * 2;
#pragma unroll
        for (int hseg = 0; hseg < 2; hseg++) {
            int m = wid * 16 + g + hseg * 8;            // 0..255
            size_t rowF = (size_t)(b * 64 + i0 + (m >> 6));
            size_t dst = rowF * 4096 + (size_t)(m & 63) * 64 + n;
            float v0 = c[nt][hseg * 2 + 0];
            float v1 = c[nt][hseg * 2 + 1];
            bf16 h0, l0, h1, l1; bsplit(v0, h0, l0); bsplit(v1, h1, l1);
            *(__nv_bfloat162*)&g_Fhi[dst] = __halves2bfloat162(h0, h1);
            *(__nv_bfloat162*)&g_Flo[dst] = __halves2bfloat162(l0, l1);
        }
    }
#undef G1_PREFETCH
}

// ---------------------------------------------------------------------------
extern "C" void kernel_launch(void* const* d_in, const int* in_sizes, int n_in,
                              void* d_out, int out_size)
{
    const float* x  = (const float*)d_in[0];
    const float* Wq = (const float*)d_in[1];
    const float* bq = (const float*)d_in[2];
    const float* Wk = (const float*)d_in[3];
    const float* bk = (const float*)d_in[4];
    const float* Wv = (const float*)d_in[5];
    const float* bv = (const float*)d_in[6];
    const float* cv = (const float*)d_in[7];
    const float* Wo = (const float*)d_in[8];
    const float* bo = (const float*)d_in[9];
    float* out = (float*)d_out;

    cudaFuncSetAttribute(mm_kernel, cudaFuncAttributeMaxDynamicSharedMemorySize, MM_SMEM);
    cudaFuncSetAttribute(gemm1_kernel, cudaFuncAttributeMaxDynamicSharedMemorySize, G1_SMEM);

    bf16 *xhi, *xlo, *wch, *wcl, *woh, *wol, *vhi, *vlo, *Fhi, *Flo;
    float *q, *k;
    cudaGetSymbolAddress((void**)&xhi, g_xhi); cudaGetSymbolAddress((void**)&xlo, g_xlo);
    cudaGetSymbolAddress((void**)&wch, g_wch); cudaGetSymbolAddress((void**)&wcl, g_wcl);
    cudaGetSymbolAddress((void**)&woh, g_woh); cudaGetSymbolAddress((void**)&wol, g_wol);
    cudaGetSymbolAddress((void**)&q, g_q);     cudaGetSymbolAddress((void**)&k, g_k);
    cudaGetSymbolAddress((void**)&vhi, g_vhi); cudaGetSymbolAddress((void**)&vlo, g_vlo);
    cudaGetSymbolAddress((void**)&Fhi, g_Fhi); cudaGetSymbolAddress((void**)&Flo, g_Flo);

    split4_kernel<<<8192, 256>>>((const float4*)x, (uint2*)xhi, (uint2*)xlo);
    split4_kernel<<<256, 256>>>((const float4*)Wq, (uint2*)wch, (uint2*)wcl);
    split4_kernel<<<256, 256>>>((const float4*)Wk,
                                (uint2*)(wch + 512*512), (uint2*)(wcl + 512*512));
    split4_kernel<<<256, 256>>>((const float4*)Wv,
                                (uint2*)(wch + 2*512*512), (uint2*)(wcl + 2*512*512));

    mm_kernel<<<dim3(12, 128), 256, MM_SMEM>>>(xhi, xlo, 512, wch, wcl, 512, 512,
                                               bq, bk, bv, cv, q, k, vhi, vlo,
                                               nullptr, nullptr, 4);

    gemm1_kernel<<<dim3(16, 256), 512, G1_SMEM>>>();

    split4_kernel<<<2048, 256>>>((const float4*)Wo, (uint2*)woh, (uint2*)wol);

    mm_kernel<<<dim3(4, 128), 256, MM_SMEM>>>(Fhi, Flo, 4096, woh, wol, 4096, 4096,
                                              nullptr, nullptr, nullptr, nullptr,
                                              nullptr, nullptr, nullptr, nullptr,
                                              out, bo, 3);
}

// round 8
// speedup vs baseline: 3.6153x; 1.1753x over previous
#include <cuda_runtime.h>
#include <cuda_bf16.h>
#include <cuda_fp16.h>
#include <cstdint>
#include <cstddef>

using bf16 = __nv_bfloat16;

// ---------------- static scratch (no cudaMalloc allowed) -------------------
__device__ bf16   g_xhi[(size_t)16384*512], g_xlo[(size_t)16384*512];
__device__ bf16   g_wch[(size_t)1536*512], g_wcl[(size_t)1536*512];  // [Wq;Wk;Wv]
__device__ __half g_wo16[(size_t)512*4096];          // 16*Wo, fp16 single
__device__ float  g_q[(size_t)16384*512];            // q * cv * 2  (= 16 * cv/8)
__device__ float  g_k[(size_t)16384*512];            // TRANSPOSED: [b][r][j]
__device__ __half g_vhi[(size_t)16384*512], g_vlo[(size_t)16384*512];
__device__ __half g_Fhi[(size_t)16384*4096], g_Flo[(size_t)16384*4096]; // 16*F

// ---------------- helpers ----------------------------------------------------
__device__ __forceinline__ uint32_t smem_u32(const void* p) {
    uint32_t a;
    asm("{ .reg .u64 t; cvta.to.shared.u64 t, %1; cvt.u32.u64 %0, t; }"
        : "=r"(a) : "l"(p));
    return a;
}
__device__ __forceinline__ void cp16(uint32_t dst, const void* src) {
    asm volatile("cp.async.cg.shared.global [%0], [%1], 16;"
                 :: "r"(dst), "l"(src) : "memory");
}
#define CP_COMMIT() asm volatile("cp.async.commit_group;" ::: "memory")
#define CP_WAIT(n)  asm volatile("cp.async.wait_group %0;" :: "n"(n) : "memory")

#define LDM_X4(r, a) \
    asm volatile("ldmatrix.sync.aligned.m8n8.x4.shared.b16 {%0,%1,%2,%3}, [%4];" \
        : "=r"((r)[0]), "=r"((r)[1]), "=r"((r)[2]), "=r"((r)[3]) : "r"(a))
#define LDM_X2(r, a) \
    asm volatile("ldmatrix.sync.aligned.m8n8.x2.shared.b16 {%0,%1}, [%2];" \
        : "=r"((r)[0]), "=r"((r)[1]) : "r"(a))

__device__ __forceinline__ void mma_bf16(float* c, const uint32_t* a, const uint32_t* b) {
    asm volatile(
        "mma.sync.aligned.m16n8k16.row.col.f32.bf16.bf16.f32 "
        "{%0,%1,%2,%3}, {%4,%5,%6,%7}, {%8,%9}, {%0,%1,%2,%3};"
        : "+f"(c[0]), "+f"(c[1]), "+f"(c[2]), "+f"(c[3])
        : "r"(a[0]), "r"(a[1]), "r"(a[2]), "r"(a[3]), "r"(b[0]), "r"(b[1]));
}
__device__ __forceinline__ void mma_f16(float* c, const uint32_t* a, const uint32_t* b) {
    asm volatile(
        "mma.sync.aligned.m16n8k16.row.col.f32.f16.f16.f32 "
        "{%0,%1,%2,%3}, {%4,%5,%6,%7}, {%8,%9}, {%0,%1,%2,%3};"
        : "+f"(c[0]), "+f"(c[1]), "+f"(c[2]), "+f"(c[3])
        : "r"(a[0]), "r"(a[1]), "r"(a[2]), "r"(a[3]), "r"(b[0]), "r"(b[1]));
}
__device__ __forceinline__ void bsplit(float f, bf16& h, bf16& l) {
    h = __float2bfloat16(f);
    l = __float2bfloat16(f - __bfloat162float(h));
}
__device__ __forceinline__ uint32_t pack_f16x2(float p0, float p1) {
    uint32_t r;
    asm("cvt.rn.f16x2.f32 %0, %1, %2;" : "=r"(r) : "f"(p1), "f"(p0));
    return r;
}
__device__ __forceinline__ void hsplit(float f, __half& h, __half& l) {
    h = __float2half_rn(f);
    l = __float2half_rn(f - __half2float(h));
}

// ---------------------------------------------------------------------------
// split4: fp32 -> bf16 hi/lo, 4 per thread
// ---------------------------------------------------------------------------
__global__ void split4_kernel(const float4* __restrict__ in,
                              uint2* __restrict__ hi, uint2* __restrict__ lo) {
    int i = blockIdx.x * blockDim.x + threadIdx.x;
    float4 v = in[i];
    bf16 h0,l0,h1,l1,h2,l2,h3,l3;
    bsplit(v.x,h0,l0); bsplit(v.y,h1,l1); bsplit(v.z,h2,l2); bsplit(v.w,h3,l3);
    uint2 ho, lw;
    ho.x = (uint32_t)__bfloat16_as_ushort(h0) | ((uint32_t)__bfloat16_as_ushort(h1) << 16);
    ho.y = (uint32_t)__bfloat16_as_ushort(h2) | ((uint32_t)__bfloat16_as_ushort(h3) << 16);
    lw.x = (uint32_t)__bfloat16_as_ushort(l0) | ((uint32_t)__bfloat16_as_ushort(l1) << 16);
    lw.y = (uint32_t)__bfloat16_as_ushort(l2) | ((uint32_t)__bfloat16_as_ushort(l3) << 16);
    hi[i] = ho; lo[i] = lw;
}

// cvt16: fp32 -> fp16 single, scaled by 16
__global__ void cvt16_kernel(const float4* __restrict__ in, uint2* __restrict__ out) {
    int i = blockIdx.x * blockDim.x + threadIdx.x;
    float4 v = in[i];
    uint2 o;
    o.x = pack_f16x2(16.f * v.x, 16.f * v.y);
    o.y = pack_f16x2(16.f * v.z, 16.f * v.w);
    out[i] = o;
}

// ---------------------------------------------------------------------------
// mm_kernel (projections, bf16 3-term): C = A(16384xK) @ B(1536xK)^T
//   proj = n0>>9: 0=q (fp32 scramble, *cv*2), 1=k (fp32 transposed),
//                 2=v (fp16 hi/lo scramble)
// ---------------------------------------------------------------------------
#define MM_STAGE 40960
#define MM_SMEM  (2 * MM_STAGE)

__global__ __launch_bounds__(256, 2) void mm_kernel(
    const bf16* __restrict__ Ahi, const bf16* __restrict__ Alo, int lda,
    const bf16* __restrict__ Bhi, const bf16* __restrict__ Blo, int ldb,
    int kTot, const float* __restrict__ bq, const float* __restrict__ bk,
    const float* __restrict__ bv, const float* __restrict__ cv,
    float* __restrict__ outQ, float* __restrict__ outK,
    __half* __restrict__ outVhi, __half* __restrict__ outVlo)
{
    extern __shared__ char sm[];
    const int tid = threadIdx.x, ln = tid & 31, wid = tid >> 5;
    const int g = ln >> 2, t = ln & 3;
    const int mw = wid >> 2, nw = wid & 3;
    const int m0 = blockIdx.y * 128, n0 = blockIdx.x * 128;
    const uint32_t sb = smem_u32(sm);

    float c[4][4][4];
#pragma unroll
    for (int a = 0; a < 4; a++)
#pragma unroll
        for (int b = 0; b < 4; b++)
#pragma unroll
            for (int d = 0; d < 4; d++) c[a][b][d] = 0.f;

    const int nCh = kTot >> 5;

#define LOAD_CHUNK(kc, s) do {                                                 \
    int _k0 = (kc) << 5;                                                       \
    uint32_t _b = sb + (s) * MM_STAGE;                                         \
    _Pragma("unroll")                                                          \
    for (int _it = 0; _it < 2; _it++) {                                        \
        int _idx = _it * 256 + tid, _r = _idx >> 2, _sg = _idx & 3;            \
        size_t _sa = (size_t)(m0 + _r) * lda + _k0 + _sg * 8;                  \
        size_t _sbo = (size_t)(n0 + _r) * ldb + _k0 + _sg * 8;                 \
        uint32_t _d = _r * 80 + _sg * 16;                                      \
        cp16(_b + _d,         Ahi + _sa);                                      \
        cp16(_b + 10240 + _d, Alo + _sa);                                      \
        cp16(_b + 20480 + _d, Bhi + _sbo);                                     \
        cp16(_b + 30720 + _d, Blo + _sbo);                                     \
    }                                                                          \
    CP_COMMIT();                                                               \
} while (0)

    LOAD_CHUNK(0, 0);

    const uint32_t a_lane = (uint32_t)((mw * 64 + (ln & 15)) * 80 + ((ln & 16) ? 16 : 0));
    const uint32_t b_lane = (uint32_t)((nw * 32 + (ln & 7)) * 80 + ((ln & 8) ? 16 : 0));

    for (int kc = 0; kc < nCh; kc++) {
        if (kc + 1 < nCh) { LOAD_CHUNK(kc + 1, (kc + 1) & 1); CP_WAIT(1); }
        else              { CP_WAIT(0); }
        __syncthreads();

        const uint32_t stage = sb + (kc & 1) * MM_STAGE;
#pragma unroll
        for (int ks = 0; ks < 2; ks++) {
            const uint32_t kb = ks * 32;
            uint32_t ah[4][4], al[4][4];
#pragma unroll
            for (int mt = 0; mt < 4; mt++) {
                uint32_t ad = stage + a_lane + mt * (16 * 80) + kb;
                LDM_X4(ah[mt], ad);
                LDM_X4(al[mt], ad + 10240);
            }
#pragma unroll
            for (int nt = 0; nt < 4; nt++) {
                uint32_t bd = stage + 20480 + b_lane + nt * (8 * 80) + kb;
                uint32_t bh[2], bl[2];
                LDM_X2(bh, bd);
                LDM_X2(bl, bd + 10240);
#pragma unroll
                for (int mt = 0; mt < 4; mt++) {
                    mma_bf16(c[mt][nt], ah[mt], bh);
                    mma_bf16(c[mt][nt], ah[mt], bl);
                    mma_bf16(c[mt][nt], al[mt], bh);
                }
            }
        }
        __syncthreads();
    }

    // epilogue (scramble-write per reference flat reshape)
    const int proj = n0 >> 9;
    const float* bias = (proj == 0 ? bq : proj == 1 ? bk : bv);
#pragma unroll
    for (int mt = 0; mt < 4; mt++)
#pragma unroll
        for (int nt = 0; nt < 4; nt++) {
            int col = (n0 + nw * 32 + nt * 8 + t * 2) & 511;
            float b0 = bias[col], b1 = bias[col + 1];
#pragma unroll
            for (int hseg = 0; hseg < 2; hseg++) {
                int row = m0 + mw * 64 + mt * 16 + g + hseg * 8;
                float v0 = c[mt][nt][hseg * 2 + 0] + b0;
                float v1 = c[mt][nt][hseg * 2 + 1] + b1;
                int core = row >> 11, bb = (row >> 3) & 255;
                int ii = (row & 7) * 8 + (col >> 6), hh = col & 63;
                if (proj == 1) {
                    size_t rb = (size_t)bb * 512 + core * 64 + hh;
                    outK[rb * 64 + ii]       = v0;
                    outK[(rb + 1) * 64 + ii] = v1;
                } else {
                    size_t dst = (size_t)(bb * 64 + ii) * 512 + core * 64 + hh;
                    if (proj == 0) {
                        v0 *= cv[core * 64 + hh]     * 2.0f;   // 16 * cv/8
                        v1 *= cv[core * 64 + hh + 1] * 2.0f;
                        *(float2*)&outQ[dst] = make_float2(v0, v1);
                    } else {
                        __half h0, l0, h1, l1; hsplit(v0, h0, l0); hsplit(v1, h1, l1);
                        *(__half2*)&outVhi[dst] = __halves2half2(h0, h1);
                        *(__half2*)&outVlo[dst] = __halves2half2(l0, l1);
                    }
                }
            }
        }
#undef LOAD_CHUNK
}

// ---------------------------------------------------------------------------
// gemm1_kernel (fp16 2-term): F16s[m,n] = sum_r fp16(16 q k) * (Vh+Vl)
//   per (b, i0=4 i's); M=256, N=64, K=512 in 8 chunks; 3-stage pipeline.
//   16 warps x (16M x 64N); A fragments built with one cvt per pair.
// Stage (36864B): K[r][j] 64x68 f32 | Vhi 64x72 f16 | Vlo | Q 4x64 f32
// ---------------------------------------------------------------------------
#define G1_K   0
#define G1_VHI 17408
#define G1_VLO 26624
#define G1_Q   35840
#define G1_STAGE 36864
#define G1_SMEM  (3 * G1_STAGE)

__global__ __launch_bounds__(512, 1) void gemm1_kernel()
{
    extern __shared__ char sm[];
    const uint32_t sb = smem_u32(sm);
    const int tid = threadIdx.x, ln = tid & 31, wid = tid >> 5;
    const int g = ln >> 2, t = ln & 3;
    const int b = blockIdx.y, i0 = blockIdx.x * 4;
    const int il = wid >> 2;
    const int jb = (wid & 3) * 16;

    float c[8][4];
#pragma unroll
    for (int a = 0; a < 8; a++)
#pragma unroll
        for (int d = 0; d < 4; d++) c[a][d] = 0.f;

#define G1_PREFETCH(kc_, s_) do {                                              \
    int _r0 = (kc_) << 6;                                                      \
    uint32_t _st = sb + (s_) * G1_STAGE;                                       \
    _Pragma("unroll")                                                          \
    for (int _it = 0; _it < 2; _it++) {                                        \
        int _i = _it * 512 + tid, _r = _i >> 4, _sg = _i & 15;                 \
        cp16(_st + G1_K + _r * 272 + _sg * 16,                                 \
             g_k + ((size_t)b * 512 + _r0 + _r) * 64 + _sg * 4);               \
    }                                                                          \
    {                                                                          \
        int _r = tid >> 3, _sg = tid & 7;                                      \
        size_t _src = (size_t)(b * 64 + _r) * 512 + _r0 + _sg * 8;             \
        cp16(_st + G1_VHI + _r * 144 + _sg * 16, g_vhi + _src);                \
        cp16(_st + G1_VLO + _r * 144 + _sg * 16, g_vlo + _src);                \
    }                                                                          \
    if (tid < 64)                                                              \
        cp16(_st + G1_Q + (tid >> 4) * 256 + (tid & 15) * 16,                  \
             g_q + ((size_t)(b * 64 + i0 + (tid >> 4))) * 512 + _r0 + (tid & 15) * 4); \
    CP_COMMIT();                                                               \
} while (0)

    G1_PREFETCH(0, 0);
    G1_PREFETCH(1, 1);

    const uint32_t b_lane4 = (uint32_t)(((ln & 7) + ((ln & 16) ? 8 : 0)) * 144
                                        + ((ln & 8) ? 16 : 0));

    for (int kc = 0; kc < 8; kc++) {
        if (kc == 7) CP_WAIT(0); else CP_WAIT(1);
        __syncthreads();
        if (kc < 6) G1_PREFETCH(kc + 2, (kc + 2) % 3);

        const int s = kc % 3;
        const float* Ks = (const float*)(sm + s * G1_STAGE + G1_K);
        const float* Qs = (const float*)(sm + s * G1_STAGE + G1_Q);
        const uint32_t vbase = sb + s * G1_STAGE + G1_VHI;

#pragma unroll
        for (int ks = 0; ks < 4; ks++) {
            const int c0e = ks * 16 + t * 2;
            float2 qa = *(const float2*)&Qs[il * 64 + c0e];
            float2 qb = *(const float2*)&Qs[il * 64 + c0e + 8];
            const int j1 = jb + g, j2 = j1 + 8;
            const float* K0 = Ks + (size_t)c0e * 68;
            uint32_t ah[4];
            ah[0] = pack_f16x2(qa.x * K0[j1],          qa.y * K0[68 + j1]);
            ah[1] = pack_f16x2(qa.x * K0[j2],          qa.y * K0[68 + j2]);
            ah[2] = pack_f16x2(qb.x * K0[8 * 68 + j1], qb.y * K0[9 * 68 + j1]);
            ah[3] = pack_f16x2(qb.x * K0[8 * 68 + j2], qb.y * K0[9 * 68 + j2]);
#pragma unroll
            for (int ntp = 0; ntp < 4; ntp++) {
                uint32_t bd = vbase + b_lane4 + ntp * (16 * 144) + ks * 32;
                uint32_t bh4[4], bl4[4];
                LDM_X4(bh4, bd);
                LDM_X4(bl4, bd + 9216);
                mma_f16(c[2 * ntp],     ah, bh4);
                mma_f16(c[2 * ntp],     ah, bl4);
                mma_f16(c[2 * ntp + 1], ah, bh4 + 2);
                mma_f16(c[2 * ntp + 1], ah, bl4 + 2);
            }
        }
    }

    // epilogue: write 16F as fp16 hi/lo
#pragma unroll
    for (int nt = 0; nt < 8; nt++) {
        int n = nt * 8 + t * 2;
#pragma unroll
        for (int hseg = 0; hseg < 2; hseg++) {
            int m = wid * 16 + g + hseg * 8;
            size_t rowF = (size_t)(b * 64 + i0 + (m >> 6));
            size_t dst = rowF * 4096 + (size_t)(m & 63) * 64 + n;
            float v0 = c[nt][hseg * 2 + 0];
            float v1 = c[nt][hseg * 2 + 1];
            __half h0, l0, h1, l1; hsplit(v0, h0, l0); hsplit(v1, h1, l1);
            *(__half2*)&g_Fhi[dst] = __halves2half2(h0, h1);
            *(__half2*)&g_Flo[dst] = __halves2half2(l0, l1);
        }
    }
#undef G1_PREFETCH
}

// ---------------------------------------------------------------------------
// gemm2_kernel (fp16 2-term): out = ((Fh+Fl) @ Wo16^T)/256 + bo
//   CTA 128x128, 8 warps (2Mx4N), K-chunk 32, 2-stage cp.async.
// Stage (30720B): Fh 128x40f16 | Fl | Wo16 128x40f16
// ---------------------------------------------------------------------------
#define G2_STAGE 30720
#define G2_SMEM  (2 * G2_STAGE)

__global__ __launch_bounds__(256, 2) void gemm2_kernel(
    const float* __restrict__ bo, float* __restrict__ out0)
{
    extern __shared__ char sm[];
    const int tid = threadIdx.x, ln = tid & 31, wid = tid >> 5;
    const int g = ln >> 2, t = ln & 3;
    const int mw = wid >> 2, nw = wid & 3;
    const int m0 = blockIdx.y * 128, n0 = blockIdx.x * 128;
    const uint32_t sb = smem_u32(sm);

    float c[4][4][4];
#pragma unroll
    for (int a = 0; a < 4; a++)
#pragma unroll
        for (int b = 0; b < 4; b++)
#pragma unroll
            for (int d = 0; d < 4; d++) c[a][b][d] = 0.f;

#define G2_LOAD(kc, s) do {                                                    \
    int _k0 = (kc) << 5;                                                       \
    uint32_t _b = sb + (s) * G2_STAGE;                                         \
    _Pragma("unroll")                                                          \
    for (int _it = 0; _it < 2; _it++) {                                        \
        int _idx = _it * 256 + tid, _r = _idx >> 2, _sg = _idx & 3;            \
        size_t _sa = (size_t)(m0 + _r) * 4096 + _k0 + _sg * 8;                 \
        size_t _sb2 = (size_t)(n0 + _r) * 4096 + _k0 + _sg * 8;                \
        uint32_t _d = _r * 80 + _sg * 16;                                      \
        cp16(_b + _d,         g_Fhi + _sa);                                    \
        cp16(_b + 10240 + _d, g_Flo + _sa);                                    \
        cp16(_b + 20480 + _d, g_wo16 + _sb2);                                  \
    }                                                                          \
    CP_COMMIT();                                                               \
} while (0)

    G2_LOAD(0, 0);

    const uint32_t a_lane = (uint32_t)((mw * 64 + (ln & 15)) * 80 + ((ln & 16) ? 16 : 0));
    const uint32_t b_lane = (uint32_t)((nw * 32 + (ln & 7)) * 80 + ((ln & 8) ? 16 : 0));

    for (int kc = 0; kc < 128; kc++) {
        if (kc + 1 < 128) { G2_LOAD(kc + 1, (kc + 1) & 1); CP_WAIT(1); }
        else              { CP_WAIT(0); }
        __syncthreads();

        const uint32_t stage = sb + (kc & 1) * G2_STAGE;
#pragma unroll
        for (int ks = 0; ks < 2; ks++) {
            const uint32_t kb = ks * 32;
            uint32_t ah[4][4], al[4][4];
#pragma unroll
            for (int mt = 0; mt < 4; mt++) {
                uint32_t ad = stage + a_lane + mt * (16 * 80) + kb;
                LDM_X4(ah[mt], ad);
                LDM_X4(al[mt], ad + 10240);
            }
#pragma unroll
            for (int nt = 0; nt < 4; nt++) {
                uint32_t bd = stage + 20480 + b_lane + nt * (8 * 80) + kb;
                uint32_t bh[2];
                LDM_X2(bh, bd);
#pragma unroll
                for (int mt = 0; mt < 4; mt++) {
                    mma_f16(c[mt][nt], ah[mt], bh);
                    mma_f16(c[mt][nt], al[mt], bh);
                }
            }
        }
        __syncthreads();
    }

    // epilogue: /256 + bias
#pragma unroll
    for (int mt = 0; mt < 4; mt++)
#pragma unroll
        for (int nt = 0; nt < 4; nt++) {
            int col = n0 + nw * 32 + nt * 8 + t * 2;
            float b0 = bo[col], b1 = bo[col + 1];
#pragma unroll
            for (int hseg = 0; hseg < 2; hseg++) {
                int row = m0 + mw * 64 + mt * 16 + g + hseg * 8;
                float v0 = c[mt][nt][hseg * 2 + 0] * 0.00390625f + b0;
                float v1 = c[mt][nt][hseg * 2 + 1] * 0.00390625f + b1;
                *(float2*)&out0[(size_t)row * 512 + col] = make_float2(v0, v1);
            }
        }
#undef G2_LOAD
}

// ---------------------------------------------------------------------------
extern "C" void kernel_launch(void* const* d_in, const int* in_sizes, int n_in,
                              void* d_out, int out_size)
{
    const float* x  = (const float*)d_in[0];
    const float* Wq = (const float*)d_in[1];
    const float* bq = (const float*)d_in[2];
    const float* Wk = (const float*)d_in[3];
    const float* bk = (const float*)d_in[4];
    const float* Wv = (const float*)d_in[5];
    const float* bv = (const float*)d_in[6];
    const float* cv = (const float*)d_in[7];
    const float* Wo = (const float*)d_in[8];
    const float* bo = (const float*)d_in[9];
    float* out = (float*)d_out;

    cudaFuncSetAttribute(mm_kernel, cudaFuncAttributeMaxDynamicSharedMemorySize, MM_SMEM);
    cudaFuncSetAttribute(gemm1_kernel, cudaFuncAttributeMaxDynamicSharedMemorySize, G1_SMEM);
    cudaFuncSetAttribute(gemm2_kernel, cudaFuncAttributeMaxDynamicSharedMemorySize, G2_SMEM);

    bf16 *xhi, *xlo, *wch, *wcl;
    __half *wo16, *vhi, *vlo;
    float *q, *k;
    cudaGetSymbolAddress((void**)&xhi, g_xhi); cudaGetSymbolAddress((void**)&xlo, g_xlo);
    cudaGetSymbolAddress((void**)&wch, g_wch); cudaGetSymbolAddress((void**)&wcl, g_wcl);
    cudaGetSymbolAddress((void**)&wo16, g_wo16);
    cudaGetSymbolAddress((void**)&q, g_q);     cudaGetSymbolAddress((void**)&k, g_k);
    cudaGetSymbolAddress((void**)&vhi, g_vhi); cudaGetSymbolAddress((void**)&vlo, g_vlo);

    split4_kernel<<<8192, 256>>>((const float4*)x, (uint2*)xhi, (uint2*)xlo);
    split4_kernel<<<256, 256>>>((const float4*)Wq, (uint2*)wch, (uint2*)wcl);
    split4_kernel<<<256, 256>>>((const float4*)Wk,
                                (uint2*)(wch + 512*512), (uint2*)(wcl + 512*512));
    split4_kernel<<<256, 256>>>((const float4*)Wv,
                                (uint2*)(wch + 2*512*512), (uint2*)(wcl + 2*512*512));
    cvt16_kernel<<<2048, 256>>>((const float4*)Wo, (uint2*)wo16);

    mm_kernel<<<dim3(12, 128), 256, MM_SMEM>>>(xhi, xlo, 512, wch, wcl, 512, 512,
                                               bq, bk, bv, cv, q, k, vhi, vlo);

    gemm1_kernel<<<dim3(16, 256), 512, G1_SMEM>>>();

    gemm2_kernel<<<dim3(4, 128), 256, G2_SMEM>>>(bo, out);
}

// round 9
// speedup vs baseline: 5.0889x; 1.4076x over previous
#include <cuda_runtime.h>
#include <cuda_bf16.h>
#include <cuda_fp16.h>
#include <cstdint>
#include <cstddef>

using bf16 = __nv_bfloat16;

// ---------------- static scratch (no cudaMalloc allowed) -------------------
__device__ bf16   g_xhi[(size_t)16384*512], g_xlo[(size_t)16384*512];
__device__ bf16   g_wch[(size_t)1536*512], g_wcl[(size_t)1536*512];  // [Wq;Wk;Wv]
__device__ __half g_wo16[(size_t)512*4096];          // 16*Wo, fp16 single
__device__ float  g_q[(size_t)16384*512];            // q * cv * 2  (= 16 * cv/8)
__device__ float  g_k[(size_t)16384*512];            // TRANSPOSED: [b][r][j]
__device__ __half g_v16[(size_t)16384*512];          // v, fp16 single
__device__ __half g_F16[(size_t)16384*4096];         // 16*F, fp16 single

// ---------------- helpers ----------------------------------------------------
__device__ __forceinline__ uint32_t smem_u32(const void* p) {
    uint32_t a;
    asm("{ .reg .u64 t; cvta.to.shared.u64 t, %1; cvt.u32.u64 %0, t; }"
        : "=r"(a) : "l"(p));
    return a;
}
__device__ __forceinline__ void cp16(uint32_t dst, const void* src) {
    asm volatile("cp.async.cg.shared.global [%0], [%1], 16;"
                 :: "r"(dst), "l"(src) : "memory");
}
#define CP_COMMIT() asm volatile("cp.async.commit_group;" ::: "memory")
#define CP_WAIT(n)  asm volatile("cp.async.wait_group %0;" :: "n"(n) : "memory")

#define LDM_X4(r, a) \
    asm volatile("ldmatrix.sync.aligned.m8n8.x4.shared.b16 {%0,%1,%2,%3}, [%4];" \
        : "=r"((r)[0]), "=r"((r)[1]), "=r"((r)[2]), "=r"((r)[3]) : "r"(a))
#define LDM_X2(r, a) \
    asm volatile("ldmatrix.sync.aligned.m8n8.x2.shared.b16 {%0,%1}, [%2];" \
        : "=r"((r)[0]), "=r"((r)[1]) : "r"(a))

__device__ __forceinline__ void mma_bf16(float* c, const uint32_t* a, const uint32_t* b) {
    asm volatile(
        "mma.sync.aligned.m16n8k16.row.col.f32.bf16.bf16.f32 "
        "{%0,%1,%2,%3}, {%4,%5,%6,%7}, {%8,%9}, {%0,%1,%2,%3};"
        : "+f"(c[0]), "+f"(c[1]), "+f"(c[2]), "+f"(c[3])
        : "r"(a[0]), "r"(a[1]), "r"(a[2]), "r"(a[3]), "r"(b[0]), "r"(b[1]));
}
__device__ __forceinline__ void mma_f16(float* c, const uint32_t* a, const uint32_t* b) {
    asm volatile(
        "mma.sync.aligned.m16n8k16.row.col.f32.f16.f16.f32 "
        "{%0,%1,%2,%3}, {%4,%5,%6,%7}, {%8,%9}, {%0,%1,%2,%3};"
        : "+f"(c[0]), "+f"(c[1]), "+f"(c[2]), "+f"(c[3])
        : "r"(a[0]), "r"(a[1]), "r"(a[2]), "r"(a[3]), "r"(b[0]), "r"(b[1]));
}
__device__ __forceinline__ void bsplit(float f, bf16& h, bf16& l) {
    h = __float2bfloat16(f);
    l = __float2bfloat16(f - __bfloat162float(h));
}
__device__ __forceinline__ uint32_t pack_f16x2(float p0, float p1) {
    uint32_t r;
    asm("cvt.rn.f16x2.f32 %0, %1, %2;" : "=r"(r) : "f"(p1), "f"(p0));
    return r;
}

// ---------------------------------------------------------------------------
// split4: fp32 -> bf16 hi/lo, 4 per thread
// ---------------------------------------------------------------------------
__global__ void split4_kernel(const float4* __restrict__ in,
                              uint2* __restrict__ hi, uint2* __restrict__ lo) {
    int i = blockIdx.x * blockDim.x + threadIdx.x;
    float4 v = in[i];
    bf16 h0,l0,h1,l1,h2,l2,h3,l3;
    bsplit(v.x,h0,l0); bsplit(v.y,h1,l1); bsplit(v.z,h2,l2); bsplit(v.w,h3,l3);
    uint2 ho, lw;
    ho.x = (uint32_t)__bfloat16_as_ushort(h0) | ((uint32_t)__bfloat16_as_ushort(h1) << 16);
    ho.y = (uint32_t)__bfloat16_as_ushort(h2) | ((uint32_t)__bfloat16_as_ushort(h3) << 16);
    lw.x = (uint32_t)__bfloat16_as_ushort(l0) | ((uint32_t)__bfloat16_as_ushort(l1) << 16);
    lw.y = (uint32_t)__bfloat16_as_ushort(l2) | ((uint32_t)__bfloat16_as_ushort(l3) << 16);
    hi[i] = ho; lo[i] = lw;
}

// cvt16: fp32 -> fp16 single, scaled by 16
__global__ void cvt16_kernel(const float4* __restrict__ in, uint2* __restrict__ out) {
    int i = blockIdx.x * blockDim.x + threadIdx.x;
    float4 v = in[i];
    uint2 o;
    o.x = pack_f16x2(16.f * v.x, 16.f * v.y);
    o.y = pack_f16x2(16.f * v.z, 16.f * v.w);
    out[i] = o;
}

// ---------------------------------------------------------------------------
// mm_kernel (projections, bf16 3-term): C = A(16384xK) @ B(1536xK)^T
//   proj = n0>>9: 0=q (fp32 scramble, *cv*2), 1=k (fp32 transposed),
//                 2=v (fp16 single scramble)
// ---------------------------------------------------------------------------
#define MM_STAGE 40960
#define MM_SMEM  (2 * MM_STAGE)

__global__ __launch_bounds__(256, 2) void mm_kernel(
    const bf16* __restrict__ Ahi, const bf16* __restrict__ Alo, int lda,
    const bf16* __restrict__ Bhi, const bf16* __restrict__ Blo, int ldb,
    int kTot, const float* __restrict__ bq, const float* __restrict__ bk,
    const float* __restrict__ bv, const float* __restrict__ cv,
    float* __restrict__ outQ, float* __restrict__ outK,
    __half* __restrict__ outV)
{
    extern __shared__ char sm[];
    const int tid = threadIdx.x, ln = tid & 31, wid = tid >> 5;
    const int g = ln >> 2, t = ln & 3;
    const int mw = wid >> 2, nw = wid & 3;
    const int m0 = blockIdx.y * 128, n0 = blockIdx.x * 128;
    const uint32_t sb = smem_u32(sm);

    float c[4][4][4];
#pragma unroll
    for (int a = 0; a < 4; a++)
#pragma unroll
        for (int b = 0; b < 4; b++)
#pragma unroll
            for (int d = 0; d < 4; d++) c[a][b][d] = 0.f;

    const int nCh = kTot >> 5;

#define LOAD_CHUNK(kc, s) do {                                                 \
    int _k0 = (kc) << 5;                                                       \
    uint32_t _b = sb + (s) * MM_STAGE;                                         \
    _Pragma("unroll")                                                          \
    for (int _it = 0; _it < 2; _it++) {                                        \
        int _idx = _it * 256 + tid, _r = _idx >> 2, _sg = _idx & 3;            \
        size_t _sa = (size_t)(m0 + _r) * lda + _k0 + _sg * 8;                  \
        size_t _sbo = (size_t)(n0 + _r) * ldb + _k0 + _sg * 8;                 \
        uint32_t _d = _r * 80 + _sg * 16;                                      \
        cp16(_b + _d,         Ahi + _sa);                                      \
        cp16(_b + 10240 + _d, Alo + _sa);                                      \
        cp16(_b + 20480 + _d, Bhi + _sbo);                                     \
        cp16(_b + 30720 + _d, Blo + _sbo);                                     \
    }                                                                          \
    CP_COMMIT();                                                               \
} while (0)

    LOAD_CHUNK(0, 0);

    const uint32_t a_lane = (uint32_t)((mw * 64 + (ln & 15)) * 80 + ((ln & 16) ? 16 : 0));
    const uint32_t b_lane = (uint32_t)((nw * 32 + (ln & 7)) * 80 + ((ln & 8) ? 16 : 0));

    for (int kc = 0; kc < nCh; kc++) {
        if (kc + 1 < nCh) { LOAD_CHUNK(kc + 1, (kc + 1) & 1); CP_WAIT(1); }
        else              { CP_WAIT(0); }
        __syncthreads();

        const uint32_t stage = sb + (kc & 1) * MM_STAGE;
#pragma unroll
        for (int ks = 0; ks < 2; ks++) {
            const uint32_t kb = ks * 32;
            uint32_t ah[4][4], al[4][4];
#pragma unroll
            for (int mt = 0; mt < 4; mt++) {
                uint32_t ad = stage + a_lane + mt * (16 * 80) + kb;
                LDM_X4(ah[mt], ad);
                LDM_X4(al[mt], ad + 10240);
            }
#pragma unroll
            for (int nt = 0; nt < 4; nt++) {
                uint32_t bd = stage + 20480 + b_lane + nt * (8 * 80) + kb;
                uint32_t bh[2], bl[2];
                LDM_X2(bh, bd);
                LDM_X2(bl, bd + 10240);
#pragma unroll
                for (int mt = 0; mt < 4; mt++) {
                    mma_bf16(c[mt][nt], ah[mt], bh);
                    mma_bf16(c[mt][nt], ah[mt], bl);
                    mma_bf16(c[mt][nt], al[mt], bh);
                }
            }
        }
        __syncthreads();
    }

    // epilogue (scramble-write per reference flat reshape)
    const int proj = n0 >> 9;
    const float* bias = (proj == 0 ? bq : proj == 1 ? bk : bv);
#pragma unroll
    for (int mt = 0; mt < 4; mt++)
#pragma unroll
        for (int nt = 0; nt < 4; nt++) {
            int col = (n0 + nw * 32 + nt * 8 + t * 2) & 511;
            float b0 = bias[col], b1 = bias[col + 1];
#pragma unroll
            for (int hseg = 0; hseg < 2; hseg++) {
                int row = m0 + mw * 64 + mt * 16 + g + hseg * 8;
                float v0 = c[mt][nt][hseg * 2 + 0] + b0;
                float v1 = c[mt][nt][hseg * 2 + 1] + b1;
                int core = row >> 11, bb = (row >> 3) & 255;
                int ii = (row & 7) * 8 + (col >> 6), hh = col & 63;
                if (proj == 1) {
                    size_t rb = (size_t)bb * 512 + core * 64 + hh;
                    outK[rb * 64 + ii]       = v0;
                    outK[(rb + 1) * 64 + ii] = v1;
                } else {
                    size_t dst = (size_t)(bb * 64 + ii) * 512 + core * 64 + hh;
                    if (proj == 0) {
                        v0 *= cv[core * 64 + hh]     * 2.0f;   // 16 * cv/8
                        v1 *= cv[core * 64 + hh + 1] * 2.0f;
                        *(float2*)&outQ[dst] = make_float2(v0, v1);
                    } else {
                        *(uint32_t*)&outV[dst] = pack_f16x2(v0, v1);
                    }
                }
            }
        }
#undef LOAD_CHUNK
}

// ---------------------------------------------------------------------------
// gemm1_kernel (fp16 single-single): F16[m,n] = sum_r fp16(16 q k) * fp16(v)
//   per (b, i0=4 i's); M=256, N=64, K=512 in 8 chunks; 3-stage pipeline.
//   16 warps x (16M x 64N); A fragments built with one cvt per pair.
// Stage (27648B): K[r][j] 64x68 f32 | V16 64x72 f16 | Q 4x64 f32
// ---------------------------------------------------------------------------
#define G1_K   0
#define G1_V   17408
#define G1_Q   26624
#define G1_STAGE 27648
#define G1_SMEM  (3 * G1_STAGE)

__global__ __launch_bounds__(512, 1) void gemm1_kernel()
{
    extern __shared__ char sm[];
    const uint32_t sb = smem_u32(sm);
    const int tid = threadIdx.x, ln = tid & 31, wid = tid >> 5;
    const int g = ln >> 2, t = ln & 3;
    const int b = blockIdx.y, i0 = blockIdx.x * 4;
    const int il = wid >> 2;
    const int jb = (wid & 3) * 16;

    float c[8][4];
#pragma unroll
    for (int a = 0; a < 8; a++)
#pragma unroll
        for (int d = 0; d < 4; d++) c[a][d] = 0.f;

#define G1_PREFETCH(kc_, s_) do {                                              \
    int _r0 = (kc_) << 6;                                                      \
    uint32_t _st = sb + (s_) * G1_STAGE;                                       \
    _Pragma("unroll")                                                          \
    for (int _it = 0; _it < 2; _it++) {                                        \
        int _i = _it * 512 + tid, _r = _i >> 4, _sg = _i & 15;                 \
        cp16(_st + G1_K + _r * 272 + _sg * 16,                                 \
             g_k + ((size_t)b * 512 + _r0 + _r) * 64 + _sg * 4);               \
    }                                                                          \
    {                                                                          \
        int _r = tid >> 3, _sg = tid & 7;                                      \
        size_t _src = (size_t)(b * 64 + _r) * 512 + _r0 + _sg * 8;             \
        cp16(_st + G1_V + _r * 144 + _sg * 16, g_v16 + _src);                  \
    }                                                                          \
    if (tid < 64)                                                              \
        cp16(_st + G1_Q + (tid >> 4) * 256 + (tid & 15) * 16,                  \
             g_q + ((size_t)(b * 64 + i0 + (tid >> 4))) * 512 + _r0 + (tid & 15) * 4); \
    CP_COMMIT();                                                               \
} while (0)

    G1_PREFETCH(0, 0);
    G1_PREFETCH(1, 1);

    const uint32_t b_lane4 = (uint32_t)(((ln & 7) + ((ln & 16) ? 8 : 0)) * 144
                                        + ((ln & 8) ? 16 : 0));

    for (int kc = 0; kc < 8; kc++) {
        if (kc == 7) CP_WAIT(0); else CP_WAIT(1);
        __syncthreads();
        if (kc < 6) G1_PREFETCH(kc + 2, (kc + 2) % 3);

        const int s = kc % 3;
        const float* Ks = (const float*)(sm + s * G1_STAGE + G1_K);
        const float* Qs = (const float*)(sm + s * G1_STAGE + G1_Q);
        const uint32_t vbase = sb + s * G1_STAGE + G1_V;

#pragma unroll
        for (int ks = 0; ks < 4; ks++) {
            const int c0e = ks * 16 + t * 2;
            float2 qa = *(const float2*)&Qs[il * 64 + c0e];
            float2 qb = *(const float2*)&Qs[il * 64 + c0e + 8];
            const int j1 = jb + g, j2 = j1 + 8;
            const float* K0 = Ks + (size_t)c0e * 68;
            uint32_t ah[4];
            ah[0] = pack_f16x2(qa.x * K0[j1],          qa.y * K0[68 + j1]);
            ah[1] = pack_f16x2(qa.x * K0[j2],          qa.y * K0[68 + j2]);
            ah[2] = pack_f16x2(qb.x * K0[8 * 68 + j1], qb.y * K0[9 * 68 + j1]);
            ah[3] = pack_f16x2(qb.x * K0[8 * 68 + j2], qb.y * K0[9 * 68 + j2]);
#pragma unroll
            for (int ntp = 0; ntp < 4; ntp++) {
                uint32_t bd = vbase + b_lane4 + ntp * (16 * 144) + ks * 32;
                uint32_t bh4[4];
                LDM_X4(bh4, bd);
                mma_f16(c[2 * ntp],     ah, bh4);
                mma_f16(c[2 * ntp + 1], ah, bh4 + 2);
            }
        }
    }

    // epilogue: write 16F as fp16 single
#pragma unroll
    for (int nt = 0; nt < 8; nt++) {
        int n = nt * 8 + t * 2;
#pragma unroll
        for (int hseg = 0; hseg < 2; hseg++) {
            int m = wid * 16 + g + hseg * 8;
            size_t rowF = (size_t)(b * 64 + i0 + (m >> 6));
            size_t dst = rowF * 4096 + (size_t)(m & 63) * 64 + n;
            *(uint32_t*)&g_F16[dst] =
                pack_f16x2(c[nt][hseg * 2 + 0], c[nt][hseg * 2 + 1]);
        }
    }
#undef G1_PREFETCH
}

// ---------------------------------------------------------------------------
// gemm2_kernel (fp16 single-single): out = (F16 @ Wo16^T)/256 + bo
//   CTA 128x128, 8 warps (2Mx4N), K-chunk 32, 2-stage cp.async.
// Stage (20480B): F16 128x40f16 | Wo16 128x40f16
// ---------------------------------------------------------------------------
#define G2_STAGE 20480
#define G2_SMEM  (2 * G2_STAGE)

__global__ __launch_bounds__(256, 2) void gemm2_kernel(
    const float* __restrict__ bo, float* __restrict__ out0)
{
    extern __shared__ char sm[];
    const int tid = threadIdx.x, ln = tid & 31, wid = tid >> 5;
    const int g = ln >> 2, t = ln & 3;
    const int mw = wid >> 2, nw = wid & 3;
    const int m0 = blockIdx.y * 128, n0 = blockIdx.x * 128;
    const uint32_t sb = smem_u32(sm);

    float c[4][4][4];
#pragma unroll
    for (int a = 0; a < 4; a++)
#pragma unroll
        for (int b = 0; b < 4; b++)
#pragma unroll
            for (int d = 0; d < 4; d++) c[a][b][d] = 0.f;

#define G2_LOAD(kc, s) do {                                                    \
    int _k0 = (kc) << 5;                                                       \
    uint32_t _b = sb + (s) * G2_STAGE;                                         \
    _Pragma("unroll")                                                          \
    for (int _it = 0; _it < 2; _it++) {                                        \
        int _idx = _it * 256 + tid, _r = _idx >> 2, _sg = _idx & 3;            \
        size_t _sa = (size_t)(m0 + _r) * 4096 + _k0 + _sg * 8;                 \
        size_t _sb2 = (size_t)(n0 + _r) * 4096 + _k0 + _sg * 8;                \
        uint32_t _d = _r * 80 + _sg * 16;                                      \
        cp16(_b + _d,         g_F16 + _sa);                                    \
        cp16(_b + 10240 + _d, g_wo16 + _sb2);                                  \
    }                                                                          \
    CP_COMMIT();                                                               \
} while (0)

    G2_LOAD(0, 0);

    const uint32_t a_lane = (uint32_t)((mw * 64 + (ln & 15)) * 80 + ((ln & 16) ? 16 : 0));
    const uint32_t b_lane = (uint32_t)((nw * 32 + (ln & 7)) * 80 + ((ln & 8) ? 16 : 0));

    for (int kc = 0; kc < 128; kc++) {
        if (kc + 1 < 128) { G2_LOAD(kc + 1, (kc + 1) & 1); CP_WAIT(1); }
        else              { CP_WAIT(0); }
        __syncthreads();

        const uint32_t stage = sb + (kc & 1) * G2_STAGE;
#pragma unroll
        for (int ks = 0; ks < 2; ks++) {
            const uint32_t kb = ks * 32;
            uint32_t ah[4][4];
#pragma unroll
            for (int mt = 0; mt < 4; mt++) {
                uint32_t ad = stage + a_lane + mt * (16 * 80) + kb;
                LDM_X4(ah[mt], ad);
            }
#pragma unroll
            for (int nt = 0; nt < 4; nt++) {
                uint32_t bd = stage + 10240 + b_lane + nt * (8 * 80) + kb;
                uint32_t bh[2];
                LDM_X2(bh, bd);
#pragma unroll
                for (int mt = 0; mt < 4; mt++)
                    mma_f16(c[mt][nt], ah[mt], bh);
            }
        }
        __syncthreads();
    }

    // epilogue: /256 + bias
#pragma unroll
    for (int mt = 0; mt < 4; mt++)
#pragma unroll
        for (int nt = 0; nt < 4; nt++) {
            int col = n0 + nw * 32 + nt * 8 + t * 2;
            float b0 = bo[col], b1 = bo[col + 1];
#pragma unroll
            for (int hseg = 0; hseg < 2; hseg++) {
                int row = m0 + mw * 64 + mt * 16 + g + hseg * 8;
                float v0 = c[mt][nt][hseg * 2 + 0] * 0.00390625f + b0;
                float v1 = c[mt][nt][hseg * 2 + 1] * 0.00390625f + b1;
                *(float2*)&out0[(size_t)row * 512 + col] = make_float2(v0, v1);
            }
        }
#undef G2_LOAD
}

// ---------------------------------------------------------------------------
extern "C" void kernel_launch(void* const* d_in, const int* in_sizes, int n_in,
                              void* d_out, int out_size)
{
    const float* x  = (const float*)d_in[0];
    const float* Wq = (const float*)d_in[1];
    const float* bq = (const float*)d_in[2];
    const float* Wk = (const float*)d_in[3];
    const float* bk = (const float*)d_in[4];
    const float* Wv = (const float*)d_in[5];
    const float* bv = (const float*)d_in[6];
    const float* cv = (const float*)d_in[7];
    const float* Wo = (const float*)d_in[8];
    const float* bo = (const float*)d_in[9];
    float* out = (float*)d_out;

    cudaFuncSetAttribute(mm_kernel, cudaFuncAttributeMaxDynamicSharedMemorySize, MM_SMEM);
    cudaFuncSetAttribute(gemm1_kernel, cudaFuncAttributeMaxDynamicSharedMemorySize, G1_SMEM);
    cudaFuncSetAttribute(gemm2_kernel, cudaFuncAttributeMaxDynamicSharedMemorySize, G2_SMEM);

    bf16 *xhi, *xlo, *wch, *wcl;
    __half *wo16, *v16;
    float *q, *k;
    cudaGetSymbolAddress((void**)&xhi, g_xhi); cudaGetSymbolAddress((void**)&xlo, g_xlo);
    cudaGetSymbolAddress((void**)&wch, g_wch); cudaGetSymbolAddress((void**)&wcl, g_wcl);
    cudaGetSymbolAddress((void**)&wo16, g_wo16);
    cudaGetSymbolAddress((void**)&q, g_q);     cudaGetSymbolAddress((void**)&k, g_k);
    cudaGetSymbolAddress((void**)&v16, g_v16);

    split4_kernel<<<8192, 256>>>((const float4*)x, (uint2*)xhi, (uint2*)xlo);
    split4_kernel<<<256, 256>>>((const float4*)Wq, (uint2*)wch, (uint2*)wcl);
    split4_kernel<<<256, 256>>>((const float4*)Wk,
                                (uint2*)(wch + 512*512), (uint2*)(wcl + 512*512));
    split4_kernel<<<256, 256>>>((const float4*)Wv,
                                (uint2*)(wch + 2*512*512), (uint2*)(wcl + 2*512*512));
    cvt16_kernel<<<2048, 256>>>((const float4*)Wo, (uint2*)wo16);

    mm_kernel<<<dim3(12, 128), 256, MM_SMEM>>>(xhi, xlo, 512, wch, wcl, 512, 512,
                                               bq, bk, bv, cv, q, k, v16);

    gemm1_kernel<<<dim3(16, 256), 512, G1_SMEM>>>();

    gemm2_kernel<<<dim3(4, 128), 256, G2_SMEM>>>(bo, out);
}

// round 10
// speedup vs baseline: 5.7418x; 1.1283x over previous
#include <cuda_runtime.h>
#include <cuda_bf16.h>
#include <cuda_fp16.h>
#include <cstdint>
#include <cstddef>

// ---------------- static scratch (no cudaMalloc allowed) -------------------
__device__ __half g_xhi[(size_t)16384*512], g_xlo[(size_t)16384*512];  // x hi/lo fp16
__device__ __half g_wc16[(size_t)1536*512];          // 16*[Wq;Wk;Wv] fp16 single
__device__ __half g_wo16[(size_t)512*4096];          // 16*Wo fp16 single
__device__ float  g_q[(size_t)16384*512];            // q * cv * 2  (= 16 * cv/8)
__device__ float  g_k[(size_t)16384*512];            // TRANSPOSED: [b][r][j]
__device__ __half g_v16[(size_t)16384*512];          // v fp16 single
__device__ __half g_F16[(size_t)16384*4096];         // 16*F fp16 single

// ---------------- helpers ----------------------------------------------------
__device__ __forceinline__ uint32_t smem_u32(const void* p) {
    uint32_t a;
    asm("{ .reg .u64 t; cvta.to.shared.u64 t, %1; cvt.u32.u64 %0, t; }"
        : "=r"(a) : "l"(p));
    return a;
}
__device__ __forceinline__ void cp16(uint32_t dst, const void* src) {
    asm volatile("cp.async.cg.shared.global [%0], [%1], 16;"
                 :: "r"(dst), "l"(src) : "memory");
}
#define CP_COMMIT() asm volatile("cp.async.commit_group;" ::: "memory")
#define CP_WAIT(n)  asm volatile("cp.async.wait_group %0;" :: "n"(n) : "memory")

#define LDM_X4(r, a) \
    asm volatile("ldmatrix.sync.aligned.m8n8.x4.shared.b16 {%0,%1,%2,%3}, [%4];" \
        : "=r"((r)[0]), "=r"((r)[1]), "=r"((r)[2]), "=r"((r)[3]) : "r"(a))
#define LDM_X2(r, a) \
    asm volatile("ldmatrix.sync.aligned.m8n8.x2.shared.b16 {%0,%1}, [%2];" \
        : "=r"((r)[0]), "=r"((r)[1]) : "r"(a))

__device__ __forceinline__ void mma_f16(float* c, const uint32_t* a, const uint32_t* b) {
    asm volatile(
        "mma.sync.aligned.m16n8k16.row.col.f32.f16.f16.f32 "
        "{%0,%1,%2,%3}, {%4,%5,%6,%7}, {%8,%9}, {%0,%1,%2,%3};"
        : "+f"(c[0]), "+f"(c[1]), "+f"(c[2]), "+f"(c[3])
        : "r"(a[0]), "r"(a[1]), "r"(a[2]), "r"(a[3]), "r"(b[0]), "r"(b[1]));
}
__device__ __forceinline__ uint32_t pack_f16x2(float p0, float p1) {
    uint32_t r;
    asm("cvt.rn.f16x2.f32 %0, %1, %2;" : "=r"(r) : "f"(p1), "f"(p0));
    return r;
}
__device__ __forceinline__ void hsplit(float f, __half& h, __half& l) {
    h = __float2half_rn(f);
    l = __float2half_rn(f - __half2float(h));
}

// ---------------------------------------------------------------------------
// split4h: fp32 -> fp16 hi/lo, 4 per thread
// ---------------------------------------------------------------------------
__global__ void split4h_kernel(const float4* __restrict__ in,
                               uint2* __restrict__ hi, uint2* __restrict__ lo) {
    int i = blockIdx.x * blockDim.x + threadIdx.x;
    float4 v = in[i];
    __half h0,l0,h1,l1,h2,l2,h3,l3;
    hsplit(v.x,h0,l0); hsplit(v.y,h1,l1); hsplit(v.z,h2,l2); hsplit(v.w,h3,l3);
    uint2 ho, lw;
    ho.x = (uint32_t)__half_as_ushort(h0) | ((uint32_t)__half_as_ushort(h1) << 16);
    ho.y = (uint32_t)__half_as_ushort(h2) | ((uint32_t)__half_as_ushort(h3) << 16);
    lw.x = (uint32_t)__half_as_ushort(l0) | ((uint32_t)__half_as_ushort(l1) << 16);
    lw.y = (uint32_t)__half_as_ushort(l2) | ((uint32_t)__half_as_ushort(l3) << 16);
    hi[i] = ho; lo[i] = lw;
}

// cvt16: fp32 -> fp16 single, scaled by 16
__global__ void cvt16_kernel(const float4* __restrict__ in, uint2* __restrict__ out) {
    int i = blockIdx.x * blockDim.x + threadIdx.x;
    float4 v = in[i];
    uint2 o;
    o.x = pack_f16x2(16.f * v.x, 16.f * v.y);
    o.y = pack_f16x2(16.f * v.z, 16.f * v.w);
    out[i] = o;
}

// ---------------------------------------------------------------------------
// mm_kernel (projections, fp16 2-term): 16*C = (xhi+xlo) @ (16*W)^T
//   CTA 128x128, 8 warps (2Mx4N), K-chunk 32, 2-stage cp.async.
//   proj = n0>>9: 0=q (fp32 scramble, *cv*2), 1=k (fp32 transposed),
//                 2=v (fp16 single scramble)
// Stage (30720B): Ahi 128x40f16 | Alo | W16 128x40f16
// ---------------------------------------------------------------------------
#define MM_STAGE 30720
#define MM_SMEM  (2 * MM_STAGE)

__global__ __launch_bounds__(256, 2) void mm_kernel(
    const float* __restrict__ bq, const float* __restrict__ bk,
    const float* __restrict__ bv, const float* __restrict__ cv,
    float* __restrict__ outQ, float* __restrict__ outK,
    __half* __restrict__ outV)
{
    extern __shared__ char sm[];
    const int tid = threadIdx.x, ln = tid & 31, wid = tid >> 5;
    const int g = ln >> 2, t = ln & 3;
    const int mw = wid >> 2, nw = wid & 3;
    const int m0 = blockIdx.y * 128, n0 = blockIdx.x * 128;
    const uint32_t sb = smem_u32(sm);

    float c[4][4][4];
#pragma unroll
    for (int a = 0; a < 4; a++)
#pragma unroll
        for (int b = 0; b < 4; b++)
#pragma unroll
            for (int d = 0; d < 4; d++) c[a][b][d] = 0.f;

#define LOAD_CHUNK(kc, s) do {                                                 \
    int _k0 = (kc) << 5;                                                       \
    uint32_t _b = sb + (s) * MM_STAGE;                                         \
    _Pragma("unroll")                                                          \
    for (int _it = 0; _it < 2; _it++) {                                        \
        int _idx = _it * 256 + tid, _r = _idx >> 2, _sg = _idx & 3;            \
        size_t _sa = (size_t)(m0 + _r) * 512 + _k0 + _sg * 8;                  \
        size_t _sbo = (size_t)(n0 + _r) * 512 + _k0 + _sg * 8;                 \
        uint32_t _d = _r * 80 + _sg * 16;                                      \
        cp16(_b + _d,         g_xhi + _sa);                                    \
        cp16(_b + 10240 + _d, g_xlo + _sa);                                    \
        cp16(_b + 20480 + _d, g_wc16 + _sbo);                                  \
    }                                                                          \
    CP_COMMIT();                                                               \
} while (0)

    LOAD_CHUNK(0, 0);

    const uint32_t a_lane = (uint32_t)((mw * 64 + (ln & 15)) * 80 + ((ln & 16) ? 16 : 0));
    const uint32_t b_lane = (uint32_t)((nw * 32 + (ln & 7)) * 80 + ((ln & 8) ? 16 : 0));

    for (int kc = 0; kc < 16; kc++) {
        if (kc + 1 < 16) { LOAD_CHUNK(kc + 1, (kc + 1) & 1); CP_WAIT(1); }
        else             { CP_WAIT(0); }
        __syncthreads();

        const uint32_t stage = sb + (kc & 1) * MM_STAGE;
#pragma unroll
        for (int ks = 0; ks < 2; ks++) {
            const uint32_t kb = ks * 32;
            uint32_t ah[4][4], al[4][4];
#pragma unroll
            for (int mt = 0; mt < 4; mt++) {
                uint32_t ad = stage + a_lane + mt * (16 * 80) + kb;
                LDM_X4(ah[mt], ad);
                LDM_X4(al[mt], ad + 10240);
            }
#pragma unroll
            for (int nt = 0; nt < 4; nt++) {
                uint32_t bd = stage + 20480 + b_lane + nt * (8 * 80) + kb;
                uint32_t bh[2];
                LDM_X2(bh, bd);
#pragma unroll
                for (int mt = 0; mt < 4; mt++) {
                    mma_f16(c[mt][nt], ah[mt], bh);
                    mma_f16(c[mt][nt], al[mt], bh);
                }
            }
        }
        __syncthreads();
    }

    // epilogue: C_true = accum/16 + bias, scramble-write per reference reshape
    const int proj = n0 >> 9;
    const float* bias = (proj == 0 ? bq : proj == 1 ? bk : bv);
#pragma unroll
    for (int mt = 0; mt < 4; mt++)
#pragma unroll
        for (int nt = 0; nt < 4; nt++) {
            int col = (n0 + nw * 32 + nt * 8 + t * 2) & 511;
            float b0 = bias[col], b1 = bias[col + 1];
#pragma unroll
            for (int hseg = 0; hseg < 2; hseg++) {
                int row = m0 + mw * 64 + mt * 16 + g + hseg * 8;
                float v0 = c[mt][nt][hseg * 2 + 0] * 0.0625f + b0;
                float v1 = c[mt][nt][hseg * 2 + 1] * 0.0625f + b1;
                int core = row >> 11, bb = (row >> 3) & 255;
                int ii = (row & 7) * 8 + (col >> 6), hh = col & 63;
                if (proj == 1) {
                    size_t rb = (size_t)bb * 512 + core * 64 + hh;
                    outK[rb * 64 + ii]       = v0;
                    outK[(rb + 1) * 64 + ii] = v1;
                } else {
                    size_t dst = (size_t)(bb * 64 + ii) * 512 + core * 64 + hh;
                    if (proj == 0) {
                        v0 *= cv[core * 64 + hh]     * 2.0f;   // 16 * cv/8
                        v1 *= cv[core * 64 + hh + 1] * 2.0f;
                        *(float2*)&outQ[dst] = make_float2(v0, v1);
                    } else {
                        *(uint32_t*)&outV[dst] = pack_f16x2(v0, v1);
                    }
                }
            }
        }
#undef LOAD_CHUNK
}

// ---------------------------------------------------------------------------
// gemm1_kernel (fp16 single-single): F16[m,n] = sum_r fp16(16 q k) * fp16(v)
//   per (b, i0=4 i's); M=256, N=64, K=512 in 8 chunks; 3-stage pipeline.
//   16 warps x (16M x 64N); A fragments built with one cvt per pair.
// Stage (27648B): K[r][j] 64x68 f32 | V16 64x72 f16 | Q 4x64 f32
// ---------------------------------------------------------------------------
#define G1_K   0
#define G1_V   17408
#define G1_Q   26624
#define G1_STAGE 27648
#define G1_SMEM  (3 * G1_STAGE)

__global__ __launch_bounds__(512, 1) void gemm1_kernel()
{
    extern __shared__ char sm[];
    const uint32_t sb = smem_u32(sm);
    const int tid = threadIdx.x, ln = tid & 31, wid = tid >> 5;
    const int g = ln >> 2, t = ln & 3;
    const int b = blockIdx.y, i0 = blockIdx.x * 4;
    const int il = wid >> 2;
    const int jb = (wid & 3) * 16;

    float c[8][4];
#pragma unroll
    for (int a = 0; a < 8; a++)
#pragma unroll
        for (int d = 0; d < 4; d++) c[a][d] = 0.f;

#define G1_PREFETCH(kc_, s_) do {                                              \
    int _r0 = (kc_) << 6;                                                      \
    uint32_t _st = sb + (s_) * G1_STAGE;                                       \
    _Pragma("unroll")                                                          \
    for (int _it = 0; _it < 2; _it++) {                                        \
        int _i = _it * 512 + tid, _r = _i >> 4, _sg = _i & 15;                 \
        cp16(_st + G1_K + _r * 272 + _sg * 16,                                 \
             g_k + ((size_t)b * 512 + _r0 + _r) * 64 + _sg * 4);               \
    }                                                                          \
    {                                                                          \
        int _r = tid >> 3, _sg = tid & 7;                                      \
        size_t _src = (size_t)(b * 64 + _r) * 512 + _r0 + _sg * 8;             \
        cp16(_st + G1_V + _r * 144 + _sg * 16, g_v16 + _src);                  \
    }                                                                          \
    if (tid < 64)                                                              \
        cp16(_st + G1_Q + (tid >> 4) * 256 + (tid & 15) * 16,                  \
             g_q + ((size_t)(b * 64 + i0 + (tid >> 4))) * 512 + _r0 + (tid & 15) * 4); \
    CP_COMMIT();                                                               \
} while (0)

    G1_PREFETCH(0, 0);
    G1_PREFETCH(1, 1);

    const uint32_t b_lane4 = (uint32_t)(((ln & 7) + ((ln & 16) ? 8 : 0)) * 144
                                        + ((ln & 8) ? 16 : 0));

    for (int kc = 0; kc < 8; kc++) {
        if (kc == 7) CP_WAIT(0); else CP_WAIT(1);
        __syncthreads();
        if (kc < 6) G1_PREFETCH(kc + 2, (kc + 2) % 3);

        const int s = kc % 3;
        const float* Ks = (const float*)(sm + s * G1_STAGE + G1_K);
        const float* Qs = (const float*)(sm + s * G1_STAGE + G1_Q);
        const uint32_t vbase = sb + s * G1_STAGE + G1_V;

#pragma unroll
        for (int ks = 0; ks < 4; ks++) {
            const int c0e = ks * 16 + t * 2;
            float2 qa = *(const float2*)&Qs[il * 64 + c0e];
            float2 qb = *(const float2*)&Qs[il * 64 + c0e + 8];
            const int j1 = jb + g, j2 = j1 + 8;
            const float* K0 = Ks + (size_t)c0e * 68;
            uint32_t ah[4];
            ah[0] = pack_f16x2(qa.x * K0[j1],          qa.y * K0[68 + j1]);
            ah[1] = pack_f16x2(qa.x * K0[j2],          qa.y * K0[68 + j2]);
            ah[2] = pack_f16x2(qb.x * K0[8 * 68 + j1], qb.y * K0[9 * 68 + j1]);
            ah[3] = pack_f16x2(qb.x * K0[8 * 68 + j2], qb.y * K0[9 * 68 + j2]);
#pragma unroll
            for (int ntp = 0; ntp < 4; ntp++) {
                uint32_t bd = vbase + b_lane4 + ntp * (16 * 144) + ks * 32;
                uint32_t bh4[4];
                LDM_X4(bh4, bd);
                mma_f16(c[2 * ntp],     ah, bh4);
                mma_f16(c[2 * ntp + 1], ah, bh4 + 2);
            }
        }
    }

    // epilogue: write 16F as fp16 single
#pragma unroll
    for (int nt = 0; nt < 8; nt++) {
        int n = nt * 8 + t * 2;
#pragma unroll
        for (int hseg = 0; hseg < 2; hseg++) {
            int m = wid * 16 + g + hseg * 8;
            size_t rowF = (size_t)(b * 64 + i0 + (m >> 6));
            size_t dst = rowF * 4096 + (size_t)(m & 63) * 64 + n;
            *(uint32_t*)&g_F16[dst] =
                pack_f16x2(c[nt][hseg * 2 + 0], c[nt][hseg * 2 + 1]);
        }
    }
#undef G1_PREFETCH
}

// ---------------------------------------------------------------------------
// gemm2_kernel (fp16 single-single): out = (F16 @ Wo16^T)/256 + bo
//   CTA 128x128, 8 warps (2Mx4N), K-chunk 64, 2-stage cp.async.
// Stage (36864B): F16 128x72f16 | Wo16 128x72f16
// ---------------------------------------------------------------------------
#define G2_STAGE 36864
#define G2_SMEM  (2 * G2_STAGE)

__global__ __launch_bounds__(256, 2) void gemm2_kernel(
    const float* __restrict__ bo, float* __restrict__ out0)
{
    extern __shared__ char sm[];
    const int tid = threadIdx.x, ln = tid & 31, wid = tid >> 5;
    const int g = ln >> 2, t = ln & 3;
    const int mw = wid >> 2, nw = wid & 3;
    const int m0 = blockIdx.y * 128, n0 = blockIdx.x * 128;
    const uint32_t sb = smem_u32(sm);

    float c[4][4][4];
#pragma unroll
    for (int a = 0; a < 4; a++)
#pragma unroll
        for (int b = 0; b < 4; b++)
#pragma unroll
            for (int d = 0; d < 4; d++) c[a][b][d] = 0.f;

#define G2_LOAD(kc, s) do {                                                    \
    int _k0 = (kc) << 6;                                                       \
    uint32_t _b = sb + (s) * G2_STAGE;                                         \
    _Pragma("unroll")                                                          \
    for (int _it = 0; _it < 4; _it++) {                                        \
        int _idx = _it * 256 + tid, _r = _idx >> 3, _sg = _idx & 7;            \
        size_t _sa = (size_t)(m0 + _r) * 4096 + _k0 + _sg * 8;                 \
        size_t _sb2 = (size_t)(n0 + _r) * 4096 + _k0 + _sg * 8;                \
        uint32_t _d = _r * 144 + _sg * 16;                                     \
        cp16(_b + _d,         g_F16 + _sa);                                    \
        cp16(_b + 18432 + _d, g_wo16 + _sb2);                                  \
    }                                                                          \
    CP_COMMIT();                                                               \
} while (0)

    G2_LOAD(0, 0);

    const uint32_t a_lane = (uint32_t)((mw * 64 + (ln & 15)) * 144 + ((ln & 16) ? 16 : 0));
    const uint32_t b_lane = (uint32_t)((nw * 32 + (ln & 7)) * 144 + ((ln & 8) ? 16 : 0));

    for (int kc = 0; kc < 64; kc++) {
        if (kc + 1 < 64) { G2_LOAD(kc + 1, (kc + 1) & 1); CP_WAIT(1); }
        else             { CP_WAIT(0); }
        __syncthreads();

        const uint32_t stage = sb + (kc & 1) * G2_STAGE;
#pragma unroll
        for (int ks = 0; ks < 4; ks++) {
            const uint32_t kb = ks * 32;
            uint32_t ah[4][4];
#pragma unroll
            for (int mt = 0; mt < 4; mt++) {
                uint32_t ad = stage + a_lane + mt * (16 * 144) + kb;
                LDM_X4(ah[mt], ad);
            }
#pragma unroll
            for (int nt = 0; nt < 4; nt++) {
                uint32_t bd = stage + 18432 + b_lane + nt * (8 * 144) + kb;
                uint32_t bh[2];
                LDM_X2(bh, bd);
#pragma unroll
                for (int mt = 0; mt < 4; mt++)
                    mma_f16(c[mt][nt], ah[mt], bh);
            }
        }
        __syncthreads();
    }

    // epilogue: /256 + bias
#pragma unroll
    for (int mt = 0; mt < 4; mt++)
#pragma unroll
        for (int nt = 0; nt < 4; nt++) {
            int col = n0 + nw * 32 + nt * 8 + t * 2;
            float b0 = bo[col], b1 = bo[col + 1];
#pragma unroll
            for (int hseg = 0; hseg < 2; hseg++) {
                int row = m0 + mw * 64 + mt * 16 + g + hseg * 8;
                float v0 = c[mt][nt][hseg * 2 + 0] * 0.00390625f + b0;
                float v1 = c[mt][nt][hseg * 2 + 1] * 0.00390625f + b1;
                *(float2*)&out0[(size_t)row * 512 + col] = make_float2(v0, v1);
            }
        }
#undef G2_LOAD
}

// ---------------------------------------------------------------------------
extern "C" void kernel_launch(void* const* d_in, const int* in_sizes, int n_in,
                              void* d_out, int out_size)
{
    const float* x  = (const float*)d_in[0];
    const float* Wq = (const float*)d_in[1];
    const float* bq = (const float*)d_in[2];
    const float* Wk = (const float*)d_in[3];
    const float* bk = (const float*)d_in[4];
    const float* Wv = (const float*)d_in[5];
    const float* bv = (const float*)d_in[6];
    const float* cv = (const float*)d_in[7];
    const float* Wo = (const float*)d_in[8];
    const float* bo = (const float*)d_in[9];
    float* out = (float*)d_out;

    cudaFuncSetAttribute(mm_kernel, cudaFuncAttributeMaxDynamicSharedMemorySize, MM_SMEM);
    cudaFuncSetAttribute(gemm1_kernel, cudaFuncAttributeMaxDynamicSharedMemorySize, G1_SMEM);
    cudaFuncSetAttribute(gemm2_kernel, cudaFuncAttributeMaxDynamicSharedMemorySize, G2_SMEM);

    __half *xhi, *xlo, *wc16, *wo16, *v16;
    float *q, *k;
    cudaGetSymbolAddress((void**)&xhi, g_xhi); cudaGetSymbolAddress((void**)&xlo, g_xlo);
    cudaGetSymbolAddress((void**)&wc16, g_wc16);
    cudaGetSymbolAddress((void**)&wo16, g_wo16);
    cudaGetSymbolAddress((void**)&q, g_q);     cudaGetSymbolAddress((void**)&k, g_k);
    cudaGetSymbolAddress((void**)&v16, g_v16);

    split4h_kernel<<<8192, 256>>>((const float4*)x, (uint2*)xhi, (uint2*)xlo);
    cvt16_kernel<<<256, 256>>>((const float4*)Wq, (uint2*)wc16);
    cvt16_kernel<<<256, 256>>>((const float4*)Wk, (uint2*)(wc16 + 512*512));
    cvt16_kernel<<<256, 256>>>((const float4*)Wv, (uint2*)(wc16 + 2*512*512));
    cvt16_kernel<<<2048, 256>>>((const float4*)Wo, (uint2*)wo16);

    mm_kernel<<<dim3(12, 128), 256, MM_SMEM>>>(bq, bk, bv, cv, q, k, v16);

    gemm1_kernel<<<dim3(16, 256), 512, G1_SMEM>>>();

    gemm2_kernel<<<dim3(4, 128), 256, G2_SMEM>>>(bo, out);
}

// round 12
// speedup vs baseline: 6.3266x; 1.1019x over previous
#include <cuda_runtime.h>
#include <cuda_fp16.h>
#include <cstdint>
#include <cstddef>

// ---------------- static scratch (no cudaMalloc allowed) -------------------
__device__ __half g_x16[(size_t)16384*512];          // x fp16 single
__device__ __half g_wc16[(size_t)1536*512];          // 16*[Wq;Wk;Wv] fp16 single
__device__ __half g_wo16[(size_t)512*4096];          // 16*Wo fp16 single
__device__ float  g_q[(size_t)16384*512];            // q * cv * 2  (= 16 * cv/8)
__device__ float  g_k[(size_t)16384*512];            // TRANSPOSED: [b][r][j]
__device__ __half g_v16[(size_t)16384*512];          // v fp16 single
__device__ __half g_F16[(size_t)16384*4096];         // 16*F fp16 single

// ---------------- helpers ----------------------------------------------------
__device__ __forceinline__ uint32_t smem_u32(const void* p) {
    uint32_t a;
    asm("{ .reg .u64 t; cvta.to.shared.u64 t, %1; cvt.u32.u64 %0, t; }"
        : "=r"(a) : "l"(p));
    return a;
}
__device__ __forceinline__ void cp16(uint32_t dst, const void* src) {
    asm volatile("cp.async.cg.shared.global [%0], [%1], 16;"
                 :: "r"(dst), "l"(src) : "memory");
}
#define CP_COMMIT() asm volatile("cp.async.commit_group;" ::: "memory")
#define CP_WAIT(n)  asm volatile("cp.async.wait_group %0;" :: "n"(n) : "memory")

#define LDM_X4(r, a) \
    asm volatile("ldmatrix.sync.aligned.m8n8.x4.shared.b16 {%0,%1,%2,%3}, [%4];" \
        : "=r"((r)[0]), "=r"((r)[1]), "=r"((r)[2]), "=r"((r)[3]) : "r"(a))
#define LDM_X2(r, a) \
    asm volatile("ldmatrix.sync.aligned.m8n8.x2.shared.b16 {%0,%1}, [%2];" \
        : "=r"((r)[0]), "=r"((r)[1]) : "r"(a))

__device__ __forceinline__ void mma_f16(float* c, const uint32_t* a, const uint32_t* b) {
    asm volatile(
        "mma.sync.aligned.m16n8k16.row.col.f32.f16.f16.f32 "
        "{%0,%1,%2,%3}, {%4,%5,%6,%7}, {%8,%9}, {%0,%1,%2,%3};"
        : "+f"(c[0]), "+f"(c[1]), "+f"(c[2]), "+f"(c[3])
        : "r"(a[0]), "r"(a[1]), "r"(a[2]), "r"(a[3]), "r"(b[0]), "r"(b[1]));
}
__device__ __forceinline__ uint32_t pack_f16x2(float p0, float p1) {
    uint32_t r;
    asm("cvt.rn.f16x2.f32 %0, %1, %2;" : "=r"(r) : "f"(p1), "f"(p0));
    return r;
}

// ---------------------------------------------------------------------------
// cvt_kernel: fp32 -> fp16 single with scale, 4 per thread
// ---------------------------------------------------------------------------
__global__ void cvt_kernel(const float4* __restrict__ in, uint2* __restrict__ out,
                           float s) {
    int i = blockIdx.x * blockDim.x + threadIdx.x;
    float4 v = in[i];
    uint2 o;
    o.x = pack_f16x2(s * v.x, s * v.y);
    o.y = pack_f16x2(s * v.z, s * v.w);
    out[i] = o;
}

// ---------------------------------------------------------------------------
// mm_kernel (projections, fp16 single-single): 16*C = x16 @ (16*W)^T
//   CTA 128x128, 8 warps (2Mx4N), K-chunk 64, 2-stage cp.async.
//   proj = n0>>9: 0=q (fp32 scramble, *cv*2), 1=k (fp32 transposed),
//                 2=v (fp16 single scramble)
// Stage (36864B): X16 128x72f16 | W16 128x72f16
// ---------------------------------------------------------------------------
#define MM_STAGE 36864
#define MM_SMEM  (2 * MM_STAGE)

__global__ __launch_bounds__(256, 2) void mm_kernel(
    const float* __restrict__ bq, const float* __restrict__ bk,
    const float* __restrict__ bv, const float* __restrict__ cv,
    float* __restrict__ outQ, float* __restrict__ outK,
    __half* __restrict__ outV)
{
    extern __shared__ char sm[];
    const int tid = threadIdx.x, ln = tid & 31, wid = tid >> 5;
    const int g = ln >> 2, t = ln & 3;
    const int mw = wid >> 2, nw = wid & 3;
    const int m0 = blockIdx.y * 128, n0 = blockIdx.x * 128;
    const uint32_t sb = smem_u32(sm);

    float c[4][4][4];
#pragma unroll
    for (int a = 0; a < 4; a++)
#pragma unroll
        for (int b = 0; b < 4; b++)
#pragma unroll
            for (int d = 0; d < 4; d++) c[a][b][d] = 0.f;

#define LOAD_CHUNK(kc, s) do {                                                 \
    int _k0 = (kc) << 6;                                                       \
    uint32_t _b = sb + (s) * MM_STAGE;                                         \
    _Pragma("unroll")                                                          \
    for (int _it = 0; _it < 4; _it++) {                                        \
        int _idx = _it * 256 + tid, _r = _idx >> 3, _sg = _idx & 7;            \
        size_t _sa = (size_t)(m0 + _r) * 512 + _k0 + _sg * 8;                  \
        size_t _sbo = (size_t)(n0 + _r) * 512 + _k0 + _sg * 8;                 \
        uint32_t _d = _r * 144 + _sg * 16;                                     \
        cp16(_b + _d,         g_x16 + _sa);                                    \
        cp16(_b + 18432 + _d, g_wc16 + _sbo);                                  \
    }                                                                          \
    CP_COMMIT();                                                               \
} while (0)

    LOAD_CHUNK(0, 0);

    const uint32_t a_lane = (uint32_t)((mw * 64 + (ln & 15)) * 144 + ((ln & 16) ? 16 : 0));
    const uint32_t b_lane = (uint32_t)((nw * 32 + (ln & 7)) * 144 + ((ln & 8) ? 16 : 0));

    for (int kc = 0; kc < 8; kc++) {
        if (kc + 1 < 8) { LOAD_CHUNK(kc + 1, (kc + 1) & 1); CP_WAIT(1); }
        else            { CP_WAIT(0); }
        __syncthreads();

        const uint32_t stage = sb + (kc & 1) * MM_STAGE;
#pragma unroll
        for (int ks = 0; ks < 4; ks++) {
            const uint32_t kb = ks * 32;
            uint32_t ah[4][4];
#pragma unroll
            for (int mt = 0; mt < 4; mt++) {
                uint32_t ad = stage + a_lane + mt * (16 * 144) + kb;
                LDM_X4(ah[mt], ad);
            }
#pragma unroll
            for (int nt = 0; nt < 4; nt++) {
                uint32_t bd = stage + 18432 + b_lane + nt * (8 * 144) + kb;
                uint32_t bh[2];
                LDM_X2(bh, bd);
#pragma unroll
                for (int mt = 0; mt < 4; mt++)
                    mma_f16(c[mt][nt], ah[mt], bh);
            }
        }
        __syncthreads();
    }

    // epilogue: C_true = accum/16 + bias, scramble-write per reference reshape
    const int proj = n0 >> 9;
    const float* bias = (proj == 0 ? bq : proj == 1 ? bk : bv);
#pragma unroll
    for (int mt = 0; mt < 4; mt++)
#pragma unroll
        for (int nt = 0; nt < 4; nt++) {
            int col = (n0 + nw * 32 + nt * 8 + t * 2) & 511;
            float b0 = bias[col], b1 = bias[col + 1];
#pragma unroll
            for (int hseg = 0; hseg < 2; hseg++) {
                int row = m0 + mw * 64 + mt * 16 + g + hseg * 8;
                float v0 = c[mt][nt][hseg * 2 + 0] * 0.0625f + b0;
                float v1 = c[mt][nt][hseg * 2 + 1] * 0.0625f + b1;
                int core = row >> 11, bb = (row >> 3) & 255;
                int ii = (row & 7) * 8 + (col >> 6), hh = col & 63;
                if (proj == 1) {
                    size_t rb = (size_t)bb * 512 + core * 64 + hh;
                    outK[rb * 64 + ii]       = v0;
                    outK[(rb + 1) * 64 + ii] = v1;
                } else {
                    size_t dst = (size_t)(bb * 64 + ii) * 512 + core * 64 + hh;
                    if (proj == 0) {
                        v0 *= cv[core * 64 + hh]     * 2.0f;   // 16 * cv/8
                        v1 *= cv[core * 64 + hh + 1] * 2.0f;
                        *(float2*)&outQ[dst] = make_float2(v0, v1);
                    } else {
                        *(uint32_t*)&outV[dst] = pack_f16x2(v0, v1);
                    }
                }
            }
        }
#undef LOAD_CHUNK
}

// ---------------------------------------------------------------------------
// gemm1_kernel (fp16 single-single): F16[m,n] = sum_r fp16(16 q k) * fp16(v)
//   per (b, i0=4 i's); M=256, N=64, K=512 in 8 chunks; 3-stage pipeline.
//   16 warps x (16M x 64N); A fragments built with one cvt per pair.
// Stage (27648B): K[r][j] 64x68 f32 | V16 64x72 f16 | Q 4x64 f32
// ---------------------------------------------------------------------------
#define G1_K   0
#define G1_V   17408
#define G1_Q   26624
#define G1_STAGE 27648
#define G1_SMEM  (3 * G1_STAGE)

__global__ __launch_bounds__(512, 1) void gemm1_kernel()
{
    extern __shared__ char sm[];
    const uint32_t sb = smem_u32(sm);
    const int tid = threadIdx.x, ln = tid & 31, wid = tid >> 5;
    const int g = ln >> 2, t = ln & 3;
    const int b = blockIdx.y, i0 = blockIdx.x * 4;
    const int il = wid >> 2;
    const int jb = (wid & 3) * 16;

    float c[8][4];
#pragma unroll
    for (int a = 0; a < 8; a++)
#pragma unroll
        for (int d = 0; d < 4; d++) c[a][d] = 0.f;

#define G1_PREFETCH(kc_, s_) do {                                              \
    int _r0 = (kc_) << 6;                                                      \
    uint32_t _st = sb + (s_) * G1_STAGE;                                       \
    _Pragma("unroll")                                                          \
    for (int _it = 0; _it < 2; _it++) {                                        \
        int _i = _it * 512 + tid, _r = _i >> 4, _sg = _i & 15;                 \
        cp16(_st + G1_K + _r * 272 + _sg * 16,                                 \
             g_k + ((size_t)b * 512 + _r0 + _r) * 64 + _sg * 4);               \
    }                                                                          \
    {                                                                          \
        int _r = tid >> 3, _sg = tid & 7;                                      \
        size_t _src = (size_t)(b * 64 + _r) * 512 + _r0 + _sg * 8;             \
        cp16(_st + G1_V + _r * 144 + _sg * 16, g_v16 + _src);                  \
    }                                                                          \
    if (tid < 64)                                                              \
        cp16(_st + G1_Q + (tid >> 4) * 256 + (tid & 15) * 16,                  \
             g_q + ((size_t)(b * 64 + i0 + (tid >> 4))) * 512 + _r0 + (tid & 15) * 4); \
    CP_COMMIT();                                                               \
} while (0)

    G1_PREFETCH(0, 0);
    G1_PREFETCH(1, 1);

    const uint32_t b_lane4 = (uint32_t)(((ln & 7) + ((ln & 16) ? 8 : 0)) * 144
                                        + ((ln & 8) ? 16 : 0));

    for (int kc = 0; kc < 8; kc++) {
        if (kc == 7) CP_WAIT(0); else CP_WAIT(1);
        __syncthreads();
        if (kc < 6) G1_PREFETCH(kc + 2, (kc + 2) % 3);

        const int s = kc % 3;
        const float* Ks = (const float*)(sm + s * G1_STAGE + G1_K);
        const float* Qs = (const float*)(sm + s * G1_STAGE + G1_Q);
        const uint32_t vbase = sb + s * G1_STAGE + G1_V;

#pragma unroll
        for (int ks = 0; ks < 4; ks++) {
            const int c0e = ks * 16 + t * 2;
            float2 qa = *(const float2*)&Qs[il * 64 + c0e];
            float2 qb = *(const float2*)&Qs[il * 64 + c0e + 8];
            const int j1 = jb + g, j2 = j1 + 8;
            const float* K0 = Ks + (size_t)c0e * 68;
            uint32_t ah[4];
            ah[0] = pack_f16x2(qa.x * K0[j1],          qa.y * K0[68 + j1]);
            ah[1] = pack_f16x2(qa.x * K0[j2],          qa.y * K0[68 + j2]);
            ah[2] = pack_f16x2(qb.x * K0[8 * 68 + j1], qb.y * K0[9 * 68 + j1]);
            ah[3] = pack_f16x2(qb.x * K0[8 * 68 + j2], qb.y * K0[9 * 68 + j2]);
#pragma unroll
            for (int ntp = 0; ntp < 4; ntp++) {
                uint32_t bd = vbase + b_lane4 + ntp * (16 * 144) + ks * 32;
                uint32_t bh4[4];
                LDM_X4(bh4, bd);
                mma_f16(c[2 * ntp],     ah, bh4);
                mma_f16(c[2 * ntp + 1], ah, bh4 + 2);
            }
        }
    }

    // epilogue: write 16F as fp16 single
#pragma unroll
    for (int nt = 0; nt < 8; nt++) {
        int n = nt * 8 + t * 2;
#pragma unroll
        for (int hseg = 0; hseg < 2; hseg++) {
            int m = wid * 16 + g + hseg * 8;
            size_t rowF = (size_t)(b * 64 + i0 + (m >> 6));
            size_t dst = rowF * 4096 + (size_t)(m & 63) * 64 + n;
            *(uint32_t*)&g_F16[dst] =
                pack_f16x2(c[nt][hseg * 2 + 0], c[nt][hseg * 2 + 1]);
        }
    }
#undef G1_PREFETCH
}

// ---------------------------------------------------------------------------
// gemm2_kernel (fp16 single-single): out = (F16 @ Wo16^T)/256 + bo
//   CTA 128x128, 8 warps (2Mx4N), K-chunk 64, 2-stage cp.async.
// Stage (36864B): F16 128x72f16 | Wo16 128x72f16
// ---------------------------------------------------------------------------
#define G2_STAGE 36864
#define G2_SMEM  (2 * G2_STAGE)

__global__ __launch_bounds__(256, 2) void gemm2_kernel(
    const float* __restrict__ bo, float* __restrict__ out0)
{
    extern __shared__ char sm[];
    const int tid = threadIdx.x, ln = tid & 31, wid = tid >> 5;
    const int g = ln >> 2, t = ln & 3;
    const int mw = wid >> 2, nw = wid & 3;
    const int m0 = blockIdx.y * 128, n0 = blockIdx.x * 128;
    const uint32_t sb = smem_u32(sm);

    float c[4][4][4];
#pragma unroll
    for (int a = 0; a < 4; a++)
#pragma unroll
        for (int b = 0; b < 4; b++)
#pragma unroll
            for (int d = 0; d < 4; d++) c[a][b][d] = 0.f;

#define G2_LOAD(kc, s) do {                                                    \
    int _k0 = (kc) << 6;                                                       \
    uint32_t _b = sb + (s) * G2_STAGE;                                         \
    _Pragma("unroll")                                                          \
    for (int _it = 0; _it < 4; _it++) {                                        \
        int _idx = _it * 256 + tid, _r = _idx >> 3, _sg = _idx & 7;            \
        size_t _sa = (size_t)(m0 + _r) * 4096 + _k0 + _sg * 8;                 \
        size_t _sb2 = (size_t)(n0 + _r) * 4096 + _k0 + _sg * 8;                \
        uint32_t _d = _r * 144 + _sg * 16;                                     \
        cp16(_b + _d,         g_F16 + _sa);                                    \
        cp16(_b + 18432 + _d, g_wo16 + _sb2);                                  \
    }                                                                          \
    CP_COMMIT();                                                               \
} while (0)

    G2_LOAD(0, 0);

    const uint32_t a_lane = (uint32_t)((mw * 64 + (ln & 15)) * 144 + ((ln & 16) ? 16 : 0));
    const uint32_t b_lane = (uint32_t)((nw * 32 + (ln & 7)) * 144 + ((ln & 8) ? 16 : 0));

    for (int kc = 0; kc < 64; kc++) {
        if (kc + 1 < 64) { G2_LOAD(kc + 1, (kc + 1) & 1); CP_WAIT(1); }
        else             { CP_WAIT(0); }
        __syncthreads();

        const uint32_t stage = sb + (kc & 1) * G2_STAGE;
#pragma unroll
        for (int ks = 0; ks < 4; ks++) {
            const uint32_t kb = ks * 32;
            uint32_t ah[4][4];
#pragma unroll
            for (int mt = 0; mt < 4; mt++) {
                uint32_t ad = stage + a_lane + mt * (16 * 144) + kb;
                LDM_X4(ah[mt], ad);
            }
#pragma unroll
            for (int nt = 0; nt < 4; nt++) {
                uint32_t bd = stage + 18432 + b_lane + nt * (8 * 144) + kb;
                uint32_t bh[2];
                LDM_X2(bh, bd);
#pragma unroll
                for (int mt = 0; mt < 4; mt++)
                    mma_f16(c[mt][nt], ah[mt], bh);
            }
        }
        __syncthreads();
    }

    // epilogue: /256 + bias
#pragma unroll
    for (int mt = 0; mt < 4; mt++)
#pragma unroll
        for (int nt = 0; nt < 4; nt++) {
            int col = n0 + nw * 32 + nt * 8 + t * 2;
            float b0 = bo[col], b1 = bo[col + 1];
#pragma unroll
            for (int hseg = 0; hseg < 2; hseg++) {
                int row = m0 + mw * 64 + mt * 16 + g + hseg * 8;
                float v0 = c[mt][nt][hseg * 2 + 0] * 0.00390625f + b0;
                float v1 = c[mt][nt][hseg * 2 + 1] * 0.00390625f + b1;
                *(float2*)&out0[(size_t)row * 512 + col] = make_float2(v0, v1);
            }
        }
#undef G2_LOAD
}

// ---------------------------------------------------------------------------
extern "C" void kernel_launch(void* const* d_in, const int* in_sizes, int n_in,
                              void* d_out, int out_size)
{
    const float* x  = (const float*)d_in[0];
    const float* Wq = (const float*)d_in[1];
    const float* bq = (const float*)d_in[2];
    const float* Wk = (const float*)d_in[3];
    const float* bk = (const float*)d_in[4];
    const float* Wv = (const float*)d_in[5];
    const float* bv = (const float*)d_in[6];
    const float* cv = (const float*)d_in[7];
    const float* Wo = (const float*)d_in[8];
    const float* bo = (const float*)d_in[9];
    float* out = (float*)d_out;

    cudaFuncSetAttribute(mm_kernel, cudaFuncAttributeMaxDynamicSharedMemorySize, MM_SMEM);
    cudaFuncSetAttribute(gemm1_kernel, cudaFuncAttributeMaxDynamicSharedMemorySize, G1_SMEM);
    cudaFuncSetAttribute(gemm2_kernel, cudaFuncAttributeMaxDynamicSharedMemorySize, G2_SMEM);

    __half *x16, *wc16, *wo16, *v16;
    float *q, *k;
    cudaGetSymbolAddress((void**)&x16, g_x16);
    cudaGetSymbolAddress((void**)&wc16, g_wc16);
    cudaGetSymbolAddress((void**)&wo16, g_wo16);
    cudaGetSymbolAddress((void**)&q, g_q);     cudaGetSymbolAddress((void**)&k, g_k);
    cudaGetSymbolAddress((void**)&v16, g_v16);

    cvt_kernel<<<8192, 256>>>((const float4*)x, (uint2*)x16, 1.0f);
    cvt_kernel<<<256, 256>>>((const float4*)Wq, (uint2*)wc16, 16.0f);
    cvt_kernel<<<256, 256>>>((const float4*)Wk, (uint2*)(wc16 + 512*512), 16.0f);
    cvt_kernel<<<256, 256>>>((const float4*)Wv, (uint2*)(wc16 + 2*512*512), 16.0f);
    cvt_kernel<<<2048, 256>>>((const float4*)Wo, (uint2*)wo16, 16.0f);

    mm_kernel<<<dim3(12, 128), 256, MM_SMEM>>>(bq, bk, bv, cv, q, k, v16);

    gemm1_kernel<<<dim3(16, 256), 512, G1_SMEM>>>();

    gemm2_kernel<<<dim3(4, 128), 256, G2_SMEM>>>(bo, out);
}

// round 13
// speedup vs baseline: 7.4881x; 1.1836x over previous
#include <cuda_runtime.h>
#include <cuda_fp16.h>
#include <cstdint>
#include <cstddef>

// ---------------- static scratch (no cudaMalloc allowed) -------------------
__device__ __half g_x16[(size_t)16384*512];          // x fp16 single
__device__ __half g_wc16[(size_t)1536*512];          // 16*[Wq;Wk;Wv] fp16 single
__device__ __half g_wo16[(size_t)512*4096];          // 16*Wo fp16 single
__device__ float  g_q[(size_t)16384*512];            // q * cv * 2  (= 16 * cv/8)
__device__ float  g_k[(size_t)16384*512];            // TRANSPOSED: [b][r][j]
__device__ __half g_v16[(size_t)16384*512];          // v fp16 single
__device__ __half g_F16[(size_t)16384*4096];         // 16*F fp16 single

// ---------------- helpers ----------------------------------------------------
__device__ __forceinline__ uint32_t smem_u32(const void* p) {
    uint32_t a;
    asm("{ .reg .u64 t; cvta.to.shared.u64 t, %1; cvt.u32.u64 %0, t; }"
        : "=r"(a) : "l"(p));
    return a;
}
__device__ __forceinline__ void cp16(uint32_t dst, const void* src) {
    asm volatile("cp.async.cg.shared.global [%0], [%1], 16;"
                 :: "r"(dst), "l"(src) : "memory");
}
#define CP_COMMIT() asm volatile("cp.async.commit_group;" ::: "memory")
#define CP_WAIT(n)  asm volatile("cp.async.wait_group %0;" :: "n"(n) : "memory")

#define LDM_X4(r, a) \
    asm volatile("ldmatrix.sync.aligned.m8n8.x4.shared.b16 {%0,%1,%2,%3}, [%4];" \
        : "=r"((r)[0]), "=r"((r)[1]), "=r"((r)[2]), "=r"((r)[3]) : "r"(a))
#define LDM_X2(r, a) \
    asm volatile("ldmatrix.sync.aligned.m8n8.x2.shared.b16 {%0,%1}, [%2];" \
        : "=r"((r)[0]), "=r"((r)[1]) : "r"(a))

__device__ __forceinline__ void mma_f16(float* c, const uint32_t* a, const uint32_t* b) {
    asm volatile(
        "mma.sync.aligned.m16n8k16.row.col.f32.f16.f16.f32 "
        "{%0,%1,%2,%3}, {%4,%5,%6,%7}, {%8,%9}, {%0,%1,%2,%3};"
        : "+f"(c[0]), "+f"(c[1]), "+f"(c[2]), "+f"(c[3])
        : "r"(a[0]), "r"(a[1]), "r"(a[2]), "r"(a[3]), "r"(b[0]), "r"(b[1]));
}
__device__ __forceinline__ uint32_t pack_f16x2(float p0, float p1) {
    uint32_t r;
    asm("cvt.rn.f16x2.f32 %0, %1, %2;" : "=r"(r) : "f"(p1), "f"(p0));
    return r;
}

// ---------------------------------------------------------------------------
// cvt_kernel: fp32 -> fp16 single with scale, 4 per thread
// ---------------------------------------------------------------------------
__global__ void cvt_kernel(const float4* __restrict__ in, uint2* __restrict__ out,
                           float s) {
    int i = blockIdx.x * blockDim.x + threadIdx.x;
    float4 v = in[i];
    uint2 o;
    o.x = pack_f16x2(s * v.x, s * v.y);
    o.y = pack_f16x2(s * v.z, s * v.w);
    out[i] = o;
}

// ---------------------------------------------------------------------------
// mm_kernel (projections, fp16 single-single): 16*C = x16 @ (16*W)^T
//   CTA 128x128, 8 warps (2Mx4N), K-chunk 64, 2-stage cp.async.
//   proj = n0>>9: 0=q (fp32 scramble, *cv*2), 1=k (fp32 transposed),
//                 2=v (fp16 single scramble)
// Stage (36864B): X16 128x72f16 | W16 128x72f16
// ---------------------------------------------------------------------------
#define MM_STAGE 36864
#define MM_SMEM  (2 * MM_STAGE)

__global__ __launch_bounds__(256, 2) void mm_kernel(
    const float* __restrict__ bq, const float* __restrict__ bk,
    const float* __restrict__ bv, const float* __restrict__ cv,
    float* __restrict__ outQ, float* __restrict__ outK,
    __half* __restrict__ outV)
{
    extern __shared__ char sm[];
    const int tid = threadIdx.x, ln = tid & 31, wid = tid >> 5;
    const int g = ln >> 2, t = ln & 3;
    const int mw = wid >> 2, nw = wid & 3;
    const int m0 = blockIdx.y * 128, n0 = blockIdx.x * 128;
    const uint32_t sb = smem_u32(sm);

    float c[4][4][4];
#pragma unroll
    for (int a = 0; a < 4; a++)
#pragma unroll
        for (int b = 0; b < 4; b++)
#pragma unroll
            for (int d = 0; d < 4; d++) c[a][b][d] = 0.f;

#define LOAD_CHUNK(kc, s) do {                                                 \
    int _k0 = (kc) << 6;                                                       \
    uint32_t _b = sb + (s) * MM_STAGE;                                         \
    _Pragma("unroll")                                                          \
    for (int _it = 0; _it < 4; _it++) {                                        \
        int _idx = _it * 256 + tid, _r = _idx >> 3, _sg = _idx & 7;            \
        size_t _sa = (size_t)(m0 + _r) * 512 + _k0 + _sg * 8;                  \
        size_t _sbo = (size_t)(n0 + _r) * 512 + _k0 + _sg * 8;                 \
        uint32_t _d = _r * 144 + _sg * 16;                                     \
        cp16(_b + _d,         g_x16 + _sa);                                    \
        cp16(_b + 18432 + _d, g_wc16 + _sbo);                                  \
    }                                                                          \
    CP_COMMIT();                                                               \
} while (0)

    LOAD_CHUNK(0, 0);

    const uint32_t a_lane = (uint32_t)((mw * 64 + (ln & 15)) * 144 + ((ln & 16) ? 16 : 0));
    const uint32_t b_lane = (uint32_t)((nw * 32 + (ln & 7)) * 144 + ((ln & 8) ? 16 : 0));

    for (int kc = 0; kc < 8; kc++) {
        if (kc + 1 < 8) { LOAD_CHUNK(kc + 1, (kc + 1) & 1); CP_WAIT(1); }
        else            { CP_WAIT(0); }
        __syncthreads();

        const uint32_t stage = sb + (kc & 1) * MM_STAGE;
#pragma unroll
        for (int ks = 0; ks < 4; ks++) {
            const uint32_t kb = ks * 32;
            uint32_t ah[4][4];
#pragma unroll
            for (int mt = 0; mt < 4; mt++) {
                uint32_t ad = stage + a_lane + mt * (16 * 144) + kb;
                LDM_X4(ah[mt], ad);
            }
#pragma unroll
            for (int nt = 0; nt < 4; nt++) {
                uint32_t bd = stage + 18432 + b_lane + nt * (8 * 144) + kb;
                uint32_t bh[2];
                LDM_X2(bh, bd);
#pragma unroll
                for (int mt = 0; mt < 4; mt++)
                    mma_f16(c[mt][nt], ah[mt], bh);
            }
        }
        __syncthreads();
    }

    // epilogue: C_true = accum/16 + bias, scramble-write per reference reshape
    const int proj = n0 >> 9;
    const float* bias = (proj == 0 ? bq : proj == 1 ? bk : bv);
#pragma unroll
    for (int mt = 0; mt < 4; mt++)
#pragma unroll
        for (int nt = 0; nt < 4; nt++) {
            int col = (n0 + nw * 32 + nt * 8 + t * 2) & 511;
            float b0 = bias[col], b1 = bias[col + 1];
#pragma unroll
            for (int hseg = 0; hseg < 2; hseg++) {
                int row = m0 + mw * 64 + mt * 16 + g + hseg * 8;
                float v0 = c[mt][nt][hseg * 2 + 0] * 0.0625f + b0;
                float v1 = c[mt][nt][hseg * 2 + 1] * 0.0625f + b1;
                int core = row >> 11, bb = (row >> 3) & 255;
                int ii = (row & 7) * 8 + (col >> 6), hh = col & 63;
                if (proj == 1) {
                    size_t rb = (size_t)bb * 512 + core * 64 + hh;
                    outK[rb * 64 + ii]       = v0;
                    outK[(rb + 1) * 64 + ii] = v1;
                } else {
                    size_t dst = (size_t)(bb * 64 + ii) * 512 + core * 64 + hh;
                    if (proj == 0) {
                        v0 *= cv[core * 64 + hh]     * 2.0f;   // 16 * cv/8
                        v1 *= cv[core * 64 + hh + 1] * 2.0f;
                        *(float2*)&outQ[dst] = make_float2(v0, v1);
                    } else {
                        *(uint32_t*)&outV[dst] = pack_f16x2(v0, v1);
                    }
                }
            }
        }
#undef LOAD_CHUNK
}

// ---------------------------------------------------------------------------
// gemm1_kernel (fp16 single-single): F16[m,n] = sum_r fp16(16 q k) * fp16(v)
//   per (b, i0=8 i's): M=512, N=64, K=512 in 8 chunks; 3-stage pipeline.
//   16 warps, warp = (1 i) x (32 j) = 32M x 64N, 2 m-tiles; V fragments
//   loaded once per ks and reused across both m-tiles. K/V traffic halved
//   vs i0=4 (16 -> 8 CTAs per b).
// Stage (28672B): K[r][j] 64x68 f32 | V16 64x72 f16 | Q 8x64 f32
// ---------------------------------------------------------------------------
#define G1_K   0
#define G1_V   17408
#define G1_Q   26624
#define G1_STAGE 28672
#define G1_SMEM  (3 * G1_STAGE)

__global__ __launch_bounds__(512, 1) void gemm1_kernel()
{
    extern __shared__ char sm[];
    const uint32_t sb = smem_u32(sm);
    const int tid = threadIdx.x, ln = tid & 31, wid = tid >> 5;
    const int g = ln >> 2, t = ln & 3;
    const int b = blockIdx.y, i0 = blockIdx.x * 8;
    const int il  = wid >> 1;            // i within group of 8
    const int jb0 = (wid & 1) * 32;      // j base within 64

    float c[2][8][4];                    // [mt][nt][frag]
#pragma unroll
    for (int a = 0; a < 2; a++)
#pragma unroll
        for (int bb = 0; bb < 8; bb++)
#pragma unroll
            for (int d = 0; d < 4; d++) c[a][bb][d] = 0.f;

#define G1_PREFETCH(kc_, s_) do {                                              \
    int _r0 = (kc_) << 6;                                                      \
    uint32_t _st = sb + (s_) * G1_STAGE;                                       \
    _Pragma("unroll")                                                          \
    for (int _it = 0; _it < 2; _it++) {                                        \
        int _i = _it * 512 + tid, _r = _i >> 4, _sg = _i & 15;                 \
        cp16(_st + G1_K + _r * 272 + _sg * 16,                                 \
             g_k + ((size_t)b * 512 + _r0 + _r) * 64 + _sg * 4);               \
    }                                                                          \
    {                                                                          \
        int _r = tid >> 3, _sg = tid & 7;                                      \
        size_t _src = (size_t)(b * 64 + _r) * 512 + _r0 + _sg * 8;             \
        cp16(_st + G1_V + _r * 144 + _sg * 16, g_v16 + _src);                  \
    }                                                                          \
    if (tid < 128)                                                             \
        cp16(_st + G1_Q + (tid >> 4) * 256 + (tid & 15) * 16,                  \
             g_q + ((size_t)(b * 64 + i0 + (tid >> 4))) * 512 + _r0 + (tid & 15) * 4); \
    CP_COMMIT();                                                               \
} while (0)

    G1_PREFETCH(0, 0);
    G1_PREFETCH(1, 1);

    const uint32_t b_lane4 = (uint32_t)(((ln & 7) + ((ln & 16) ? 8 : 0)) * 144
                                        + ((ln & 8) ? 16 : 0));

    for (int kc = 0; kc < 8; kc++) {
        if (kc == 7) CP_WAIT(0); else CP_WAIT(1);
        __syncthreads();
        if (kc < 6) G1_PREFETCH(kc + 2, (kc + 2) % 3);

        const int s = kc % 3;
        const float* Ks = (const float*)(sm + s * G1_STAGE + G1_K);
        const float* Qs = (const float*)(sm + s * G1_STAGE + G1_Q);
        const uint32_t vbase = sb + s * G1_STAGE + G1_V;

#pragma unroll
        for (int ks = 0; ks < 4; ks++) {
            const int c0e = ks * 16 + t * 2;
            float2 qa = *(const float2*)&Qs[il * 64 + c0e];
            float2 qb = *(const float2*)&Qs[il * 64 + c0e + 8];
            const float* K0 = Ks + (size_t)c0e * 68;

            // V fragments once per ks, shared across both m-tiles
            uint32_t bh4[4][4];
#pragma unroll
            for (int ntp = 0; ntp < 4; ntp++)
                LDM_X4(bh4[ntp], vbase + b_lane4 + ntp * (16 * 144) + ks * 32);

#pragma unroll
            for (int mt = 0; mt < 2; mt++) {
                const int j1 = jb0 + mt * 16 + g, j2 = j1 + 8;
                uint32_t ah[4];
                ah[0] = pack_f16x2(qa.x * K0[j1],          qa.y * K0[68 + j1]);
                ah[1] = pack_f16x2(qa.x * K0[j2],          qa.y * K0[68 + j2]);
                ah[2] = pack_f16x2(qb.x * K0[8 * 68 + j1], qb.y * K0[9 * 68 + j1]);
                ah[3] = pack_f16x2(qb.x * K0[8 * 68 + j2], qb.y * K0[9 * 68 + j2]);
#pragma unroll
                for (int ntp = 0; ntp < 4; ntp++) {
                    mma_f16(c[mt][2 * ntp],     ah, bh4[ntp]);
                    mma_f16(c[mt][2 * ntp + 1], ah, bh4[ntp] + 2);
                }
            }
        }
    }

    // epilogue: write 16F as fp16 single
    const size_t rowF = (size_t)(b * 64 + i0 + il);
#pragma unroll
    for (int mt = 0; mt < 2; mt++)
#pragma unroll
        for (int nt = 0; nt < 8; nt++) {
            int n = nt * 8 + t * 2;
#pragma unroll
            for (int hseg = 0; hseg < 2; hseg++) {
                int j = jb0 + mt * 16 + g + hseg * 8;
                size_t dst = rowF * 4096 + (size_t)j * 64 + n;
                *(uint32_t*)&g_F16[dst] =
                    pack_f16x2(c[mt][nt][hseg * 2 + 0], c[mt][nt][hseg * 2 + 1]);
            }
        }
#undef G1_PREFETCH
}

// ---------------------------------------------------------------------------
// gemm2_kernel (fp16 single-single): out = (F16 @ Wo16^T)/256 + bo
//   CTA 128x128, 8 warps (2Mx4N), K-chunk 64, 2-stage cp.async.
// Stage (36864B): F16 128x72f16 | Wo16 128x72f16
// ---------------------------------------------------------------------------
#define G2_STAGE 36864
#define G2_SMEM  (2 * G2_STAGE)

__global__ __launch_bounds__(256, 2) void gemm2_kernel(
    const float* __restrict__ bo, float* __restrict__ out0)
{
    extern __shared__ char sm[];
    const int tid = threadIdx.x, ln = tid & 31, wid = tid >> 5;
    const int g = ln >> 2, t = ln & 3;
    const int mw = wid >> 2, nw = wid & 3;
    const int m0 = blockIdx.y * 128, n0 = blockIdx.x * 128;
    const uint32_t sb = smem_u32(sm);

    float c[4][4][4];
#pragma unroll
    for (int a = 0; a < 4; a++)
#pragma unroll
        for (int b = 0; b < 4; b++)
#pragma unroll
            for (int d = 0; d < 4; d++) c[a][b][d] = 0.f;

#define G2_LOAD(kc, s) do {                                                    \
    int _k0 = (kc) << 6;                                                       \
    uint32_t _b = sb + (s) * G2_STAGE;                                         \
    _Pragma("unroll")                                                          \
    for (int _it = 0; _it < 4; _it++) {                                        \
        int _idx = _it * 256 + tid, _r = _idx >> 3, _sg = _idx & 7;            \
        size_t _sa = (size_t)(m0 + _r) * 4096 + _k0 + _sg * 8;                 \
        size_t _sb2 = (size_t)(n0 + _r) * 4096 + _k0 + _sg * 8;                \
        uint32_t _d = _r * 144 + _sg * 16;                                     \
        cp16(_b + _d,         g_F16 + _sa);                                    \
        cp16(_b + 18432 + _d, g_wo16 + _sb2);                                  \
    }                                                                          \
    CP_COMMIT();                                                               \
} while (0)

    G2_LOAD(0, 0);

    const uint32_t a_lane = (uint32_t)((mw * 64 + (ln & 15)) * 144 + ((ln & 16) ? 16 : 0));
    const uint32_t b_lane = (uint32_t)((nw * 32 + (ln & 7)) * 144 + ((ln & 8) ? 16 : 0));

    for (int kc = 0; kc < 64; kc++) {
        if (kc + 1 < 64) { G2_LOAD(kc + 1, (kc + 1) & 1); CP_WAIT(1); }
        else             { CP_WAIT(0); }
        __syncthreads();

        const uint32_t stage = sb + (kc & 1) * G2_STAGE;
#pragma unroll
        for (int ks = 0; ks < 4; ks++) {
            const uint32_t kb = ks * 32;
            uint32_t ah[4][4];
#pragma unroll
            for (int mt = 0; mt < 4; mt++) {
                uint32_t ad = stage + a_lane + mt * (16 * 144) + kb;
                LDM_X4(ah[mt], ad);
            }
#pragma unroll
            for (int nt = 0; nt < 4; nt++) {
                uint32_t bd = stage + 18432 + b_lane + nt * (8 * 144) + kb;
                uint32_t bh[2];
                LDM_X2(bh, bd);
#pragma unroll
                for (int mt = 0; mt < 4; mt++)
                    mma_f16(c[mt][nt], ah[mt], bh);
            }
        }
        __syncthreads();
    }

    // epilogue: /256 + bias
#pragma unroll
    for (int mt = 0; mt < 4; mt++)
#pragma unroll
        for (int nt = 0; nt < 4; nt++) {
            int col = n0 + nw * 32 + nt * 8 + t * 2;
            float b0 = bo[col], b1 = bo[col + 1];
#pragma unroll
            for (int hseg = 0; hseg < 2; hseg++) {
                int row = m0 + mw * 64 + mt * 16 + g + hseg * 8;
                float v0 = c[mt][nt][hseg * 2 + 0] * 0.00390625f + b0;
                float v1 = c[mt][nt][hseg * 2 + 1] * 0.00390625f + b1;
                *(float2*)&out0[(size_t)row * 512 + col] = make_float2(v0, v1);
            }
        }
#undef G2_LOAD
}

// ---------------------------------------------------------------------------
extern "C" void kernel_launch(void* const* d_in, const int* in_sizes, int n_in,
                              void* d_out, int out_size)
{
    const float* x  = (const float*)d_in[0];
    const float* Wq = (const float*)d_in[1];
    const float* bq = (const float*)d_in[2];
    const float* Wk = (const float*)d_in[3];
    const float* bk = (const float*)d_in[4];
    const float* Wv = (const float*)d_in[5];
    const float* bv = (const float*)d_in[6];
    const float* cv = (const float*)d_in[7];
    const float* Wo = (const float*)d_in[8];
    const float* bo = (const float*)d_in[9];
    float* out = (float*)d_out;

    cudaFuncSetAttribute(mm_kernel, cudaFuncAttributeMaxDynamicSharedMemorySize, MM_SMEM);
    cudaFuncSetAttribute(gemm1_kernel, cudaFuncAttributeMaxDynamicSharedMemorySize, G1_SMEM);
    cudaFuncSetAttribute(gemm2_kernel, cudaFuncAttributeMaxDynamicSharedMemorySize, G2_SMEM);

    __half *x16, *wc16, *wo16, *v16;
    float *q, *k;
    cudaGetSymbolAddress((void**)&x16, g_x16);
    cudaGetSymbolAddress((void**)&wc16, g_wc16);
    cudaGetSymbolAddress((void**)&wo16, g_wo16);
    cudaGetSymbolAddress((void**)&q, g_q);     cudaGetSymbolAddress((void**)&k, g_k);
    cudaGetSymbolAddress((void**)&v16, g_v16);

    cvt_kernel<<<8192, 256>>>((const float4*)x, (uint2*)x16, 1.0f);
    cvt_kernel<<<256, 256>>>((const float4*)Wq, (uint2*)wc16, 16.0f);
    cvt_kernel<<<256, 256>>>((const float4*)Wk, (uint2*)(wc16 + 512*512), 16.0f);
    cvt_kernel<<<256, 256>>>((const float4*)Wv, (uint2*)(wc16 + 2*512*512), 16.0f);
    cvt_kernel<<<2048, 256>>>((const float4*)Wo, (uint2*)wo16, 16.0f);

    mm_kernel<<<dim3(12, 128), 256, MM_SMEM>>>(bq, bk, bv, cv, q, k, v16);

    gemm1_kernel<<<dim3(8, 256), 512, G1_SMEM>>>();

    gemm2_kernel<<<dim3(4, 128), 256, G2_SMEM>>>(bo, out);
}

// round 14
// speedup vs baseline: 8.5146x; 1.1371x over previous
#include <cuda_runtime.h>
#include <cuda_fp16.h>
#include <cstdint>
#include <cstddef>

// ---------------- static scratch (no cudaMalloc allowed) -------------------
__device__ __half g_x16[(size_t)16384*512];          // x fp16 single
__device__ __half g_wc16[(size_t)1536*512];          // 16*[Wq;Wk;Wv] fp16 single
__device__ __half g_wo16[(size_t)512*4096];          // 16*Wo fp16 single
__device__ __half g_q16[(size_t)16384*512];          // fp16(q*cv*2), scrambled
__device__ __half g_k16[(size_t)16384*512];          // fp16(k), scrambled
__device__ __half g_v16[(size_t)16384*512];          // fp16(v), scrambled
__device__ __half g_F16[(size_t)16384*4096];         // 16*F fp16 single

// ---------------- helpers ----------------------------------------------------
__device__ __forceinline__ uint32_t smem_u32(const void* p) {
    uint32_t a;
    asm("{ .reg .u64 t; cvta.to.shared.u64 t, %1; cvt.u32.u64 %0, t; }"
        : "=r"(a) : "l"(p));
    return a;
}
__device__ __forceinline__ void cp16(uint32_t dst, const void* src) {
    asm volatile("cp.async.cg.shared.global [%0], [%1], 16;"
                 :: "r"(dst), "l"(src) : "memory");
}
#define CP_COMMIT() asm volatile("cp.async.commit_group;" ::: "memory")
#define CP_WAIT(n)  asm volatile("cp.async.wait_group %0;" :: "n"(n) : "memory")

#define LDM_X4(r, a) \
    asm volatile("ldmatrix.sync.aligned.m8n8.x4.shared.b16 {%0,%1,%2,%3}, [%4];" \
        : "=r"((r)[0]), "=r"((r)[1]), "=r"((r)[2]), "=r"((r)[3]) : "r"(a))
#define LDM_X2(r, a) \
    asm volatile("ldmatrix.sync.aligned.m8n8.x2.shared.b16 {%0,%1}, [%2];" \
        : "=r"((r)[0]), "=r"((r)[1]) : "r"(a))

__device__ __forceinline__ void mma_f16(float* c, const uint32_t* a, const uint32_t* b) {
    asm volatile(
        "mma.sync.aligned.m16n8k16.row.col.f32.f16.f16.f32 "
        "{%0,%1,%2,%3}, {%4,%5,%6,%7}, {%8,%9}, {%0,%1,%2,%3};"
        : "+f"(c[0]), "+f"(c[1]), "+f"(c[2]), "+f"(c[3])
        : "r"(a[0]), "r"(a[1]), "r"(a[2]), "r"(a[3]), "r"(b[0]), "r"(b[1]));
}
__device__ __forceinline__ uint32_t pack_f16x2(float p0, float p1) {
    uint32_t r;
    asm("cvt.rn.f16x2.f32 %0, %1, %2;" : "=r"(r) : "f"(p1), "f"(p0));
    return r;
}
__device__ __forceinline__ uint32_t hmul2(uint32_t a, uint32_t b) {
    uint32_t r;
    asm("mul.rn.f16x2 %0, %1, %2;" : "=r"(r) : "r"(a), "r"(b));
    return r;
}

// ---------------------------------------------------------------------------
// cvt_all: single launch converting x, Wq, Wk, Wv, Wo to fp16 (W's scaled 16x)
//   block ranges: [0,8192) x | [8192,8448) Wq | [8448,8704) Wk
//                 [8704,8960) Wv | [8960,11008) Wo
// ---------------------------------------------------------------------------
__global__ void cvt_all_kernel(const float4* __restrict__ x,
                               const float4* __restrict__ Wq,
                               const float4* __restrict__ Wk,
                               const float4* __restrict__ Wv,
                               const float4* __restrict__ Wo) {
    int bid = blockIdx.x;
    const float4* in;
    uint2* out;
    float s;
    int base;
    if (bid < 8192)      { in = x;  out = (uint2*)g_x16;  s = 1.f;  base = bid; }
    else if (bid < 8448) { in = Wq; out = (uint2*)g_wc16; s = 16.f; base = bid - 8192; }
    else if (bid < 8704) { in = Wk; out = (uint2*)(g_wc16 + 512*512); s = 16.f; base = bid - 8448; }
    else if (bid < 8960) { in = Wv; out = (uint2*)(g_wc16 + 2*512*512); s = 16.f; base = bid - 8704; }
    else                 { in = Wo; out = (uint2*)g_wo16; s = 16.f; base = bid - 8960; }
    int i = base * 256 + threadIdx.x;
    float4 v = in[i];
    uint2 o;
    o.x = pack_f16x2(s * v.x, s * v.y);
    o.y = pack_f16x2(s * v.z, s * v.w);
    out[i] = o;
}

// ---------------------------------------------------------------------------
// mm_kernel (projections, fp16 single-single): 16*C = x16 @ (16*W)^T
//   CTA 128x128, 8 warps (2Mx4N), K-chunk 64, 2-stage cp.async.
//   proj = n0>>9: 0=q (fp16 scramble, *cv*2), 1=k (fp16 scramble),
//                 2=v (fp16 scramble). All outputs fp16 scrambled now.
// Stage (36864B): X16 128x72f16 | W16 128x72f16
// ---------------------------------------------------------------------------
#define MM_STAGE 36864
#define MM_SMEM  (2 * MM_STAGE)

__global__ __launch_bounds__(256, 2) void mm_kernel(
    const float* __restrict__ bq, const float* __restrict__ bk,
    const float* __restrict__ bv, const float* __restrict__ cv)
{
    extern __shared__ char sm[];
    const int tid = threadIdx.x, ln = tid & 31, wid = tid >> 5;
    const int g = ln >> 2, t = ln & 3;
    const int mw = wid >> 2, nw = wid & 3;
    const int m0 = blockIdx.y * 128, n0 = blockIdx.x * 128;
    const uint32_t sb = smem_u32(sm);

    float c[4][4][4];
#pragma unroll
    for (int a = 0; a < 4; a++)
#pragma unroll
        for (int b = 0; b < 4; b++)
#pragma unroll
            for (int d = 0; d < 4; d++) c[a][b][d] = 0.f;

#define LOAD_CHUNK(kc, s) do {                                                 \
    int _k0 = (kc) << 6;                                                       \
    uint32_t _b = sb + (s) * MM_STAGE;                                         \
    _Pragma("unroll")                                                          \
    for (int _it = 0; _it < 4; _it++) {                                        \
        int _idx = _it * 256 + tid, _r = _idx >> 3, _sg = _idx & 7;            \
        size_t _sa = (size_t)(m0 + _r) * 512 + _k0 + _sg * 8;                  \
        size_t _sbo = (size_t)(n0 + _r) * 512 + _k0 + _sg * 8;                 \
        uint32_t _d = _r * 144 + _sg * 16;                                     \
        cp16(_b + _d,         g_x16 + _sa);                                    \
        cp16(_b + 18432 + _d, g_wc16 + _sbo);                                  \
    }                                                                          \
    CP_COMMIT();                                                               \
} while (0)

    LOAD_CHUNK(0, 0);

    const uint32_t a_lane = (uint32_t)((mw * 64 + (ln & 15)) * 144 + ((ln & 16) ? 16 : 0));
    const uint32_t b_lane = (uint32_t)((nw * 32 + (ln & 7)) * 144 + ((ln & 8) ? 16 : 0));

    for (int kc = 0; kc < 8; kc++) {
        if (kc + 1 < 8) { LOAD_CHUNK(kc + 1, (kc + 1) & 1); CP_WAIT(1); }
        else            { CP_WAIT(0); }
        __syncthreads();

        const uint32_t stage = sb + (kc & 1) * MM_STAGE;
#pragma unroll
        for (int ks = 0; ks < 4; ks++) {
            const uint32_t kb = ks * 32;
            uint32_t ah[4][4];
#pragma unroll
            for (int mt = 0; mt < 4; mt++) {
                uint32_t ad = stage + a_lane + mt * (16 * 144) + kb;
                LDM_X4(ah[mt], ad);
            }
#pragma unroll
            for (int nt = 0; nt < 4; nt++) {
                uint32_t bd = stage + 18432 + b_lane + nt * (8 * 144) + kb;
                uint32_t bh[2];
                LDM_X2(bh, bd);
#pragma unroll
                for (int mt = 0; mt < 4; mt++)
                    mma_f16(c[mt][nt], ah[mt], bh);
            }
        }
        __syncthreads();
    }

    // epilogue: C_true = accum/16 + bias, fp16 scramble-write (all projections)
    const int proj = n0 >> 9;
    const float* bias = (proj == 0 ? bq : proj == 1 ? bk : bv);
    __half* outp = (proj == 0 ? g_q16 : proj == 1 ? g_k16 : g_v16);
#pragma unroll
    for (int mt = 0; mt < 4; mt++)
#pragma unroll
        for (int nt = 0; nt < 4; nt++) {
            int col = (n0 + nw * 32 + nt * 8 + t * 2) & 511;
            float b0 = bias[col], b1 = bias[col + 1];
#pragma unroll
            for (int hseg = 0; hseg < 2; hseg++) {
                int row = m0 + mw * 64 + mt * 16 + g + hseg * 8;
                float v0 = c[mt][nt][hseg * 2 + 0] * 0.0625f + b0;
                float v1 = c[mt][nt][hseg * 2 + 1] * 0.0625f + b1;
                int core = row >> 11, bb = (row >> 3) & 255;
                int ii = (row & 7) * 8 + (col >> 6), hh = col & 63;
                size_t dst = (size_t)(bb * 64 + ii) * 512 + core * 64 + hh;
                if (proj == 0) {
                    v0 *= cv[core * 64 + hh]     * 2.0f;   // 16 * cv/8
                    v1 *= cv[core * 64 + hh + 1] * 2.0f;
                }
                *(uint32_t*)&outp[dst] = pack_f16x2(v0, v1);
            }
        }
#undef LOAD_CHUNK
}

// ---------------------------------------------------------------------------
// gemm1_kernel (fp16): F16[m,n] = sum_r (q16 .* k16)[m,r] * v16[n,r]
//   per (b, i0=8 i's): M=512, N=64, K=512 in 8 chunks; 3-stage pipeline.
//   A fragments: LDM_X4 on K tile (rows j) then HMUL2 with broadcast q pairs.
//   16 warps, warp = (1 i) x (32 j), 2 m-tiles; V frags shared across m-tiles.
// Stage (19456B): K16 64x72f16 | V16 64x72f16 | Q16 8x64f16 (pitch 128B)
// ---------------------------------------------------------------------------
#define G1_K   0
#define G1_V   9216
#define G1_Q   18432
#define G1_STAGE 19456
#define G1_SMEM  (3 * G1_STAGE)

__global__ __launch_bounds__(512, 1) void gemm1_kernel()
{
    extern __shared__ char sm[];
    const uint32_t sb = smem_u32(sm);
    const int tid = threadIdx.x, ln = tid & 31, wid = tid >> 5;
    const int g = ln >> 2, t = ln & 3;
    const int b = blockIdx.y, i0 = blockIdx.x * 8;
    const int il  = wid >> 1;            // i within group of 8
    const int jb0 = (wid & 1) * 32;      // j base within 64

    float c[2][8][4];                    // [mt][nt][frag]
#pragma unroll
    for (int a = 0; a < 2; a++)
#pragma unroll
        for (int bb = 0; bb < 8; bb++)
#pragma unroll
            for (int d = 0; d < 4; d++) c[a][bb][d] = 0.f;

#define G1_PREFETCH(kc_, s_) do {                                              \
    int _r0 = (kc_) << 6;                                                      \
    uint32_t _st = sb + (s_) * G1_STAGE;                                       \
    {                                                                          \
        int _r = tid >> 3, _sg = tid & 7;                                      \
        size_t _src = (size_t)(b * 64 + _r) * 512 + _r0 + _sg * 8;             \
        cp16(_st + G1_K + _r * 144 + _sg * 16, g_k16 + _src);                  \
        cp16(_st + G1_V + _r * 144 + _sg * 16, g_v16 + _src);                  \
    }                                                                          \
    if (tid < 64)                                                              \
        cp16(_st + G1_Q + (tid >> 3) * 128 + (tid & 7) * 16,                   \
             g_q16 + ((size_t)(b * 64 + i0 + (tid >> 3))) * 512 + _r0 + (tid & 7) * 8); \
    CP_COMMIT();                                                               \
} while (0)

    G1_PREFETCH(0, 0);
    G1_PREFETCH(1, 1);

    const uint32_t a_lane = (uint32_t)((jb0 + (ln & 15)) * 144 + ((ln & 16) ? 16 : 0));
    const uint32_t b_lane4 = (uint32_t)(((ln & 7) + ((ln & 16) ? 8 : 0)) * 144
                                        + ((ln & 8) ? 16 : 0));

    for (int kc = 0; kc < 8; kc++) {
        if (kc == 7) CP_WAIT(0); else CP_WAIT(1);
        __syncthreads();
        if (kc < 6) G1_PREFETCH(kc + 2, (kc + 2) % 3);

        const int s = kc % 3;
        const uint32_t kbase = sb + s * G1_STAGE + G1_K;
        const uint32_t vbase = sb + s * G1_STAGE + G1_V;
        const char*    qbase = sm + s * G1_STAGE + G1_Q;

#pragma unroll
        for (int ks = 0; ks < 4; ks++) {
            // q pairs broadcast: cols (ks*16 + t*2, +1) and (+8, +9)
            uint32_t q2a = *(const uint32_t*)(qbase + il * 128 + ks * 32 + t * 4);
            uint32_t q2b = *(const uint32_t*)(qbase + il * 128 + ks * 32 + t * 4 + 16);

            // V fragments once per ks, shared across both m-tiles
            uint32_t bh4[4][4];
#pragma unroll
            for (int ntp = 0; ntp < 4; ntp++)
                LDM_X4(bh4[ntp], vbase + b_lane4 + ntp * (16 * 144) + ks * 32);

#pragma unroll
            for (int mt = 0; mt < 2; mt++) {
                uint32_t kf[4];
                LDM_X4(kf, kbase + a_lane + mt * (16 * 144) + ks * 32);
                uint32_t ah[4];
                ah[0] = hmul2(kf[0], q2a);
                ah[1] = hmul2(kf[1], q2a);
                ah[2] = hmul2(kf[2], q2b);
                ah[3] = hmul2(kf[3], q2b);
#pragma unroll
                for (int ntp = 0; ntp < 4; ntp++) {
                    mma_f16(c[mt][2 * ntp],     ah, bh4[ntp]);
                    mma_f16(c[mt][2 * ntp + 1], ah, bh4[ntp] + 2);
                }
            }
        }
    }

    // epilogue: write 16F as fp16 single
    const size_t rowF = (size_t)(b * 64 + i0 + il);
#pragma unroll
    for (int mt = 0; mt < 2; mt++)
#pragma unroll
        for (int nt = 0; nt < 8; nt++) {
            int n = nt * 8 + t * 2;
#pragma unroll
            for (int hseg = 0; hseg < 2; hseg++) {
                int j = jb0 + mt * 16 + g + hseg * 8;
                size_t dst = rowF * 4096 + (size_t)j * 64 + n;
                *(uint32_t*)&g_F16[dst] =
                    pack_f16x2(c[mt][nt][hseg * 2 + 0], c[mt][nt][hseg * 2 + 1]);
            }
        }
#undef G1_PREFETCH
}

// ---------------------------------------------------------------------------
// gemm2_kernel (fp16 single-single): out = (F16 @ Wo16^T)/256 + bo
//   CTA 128x128, 8 warps (2Mx4N), K-chunk 64, 2-stage cp.async.
// Stage (36864B): F16 128x72f16 | Wo16 128x72f16
// ---------------------------------------------------------------------------
#define G2_STAGE 36864
#define G2_SMEM  (2 * G2_STAGE)

__global__ __launch_bounds__(256, 2) void gemm2_kernel(
    const float* __restrict__ bo, float* __restrict__ out0)
{
    extern __shared__ char sm[];
    const int tid = threadIdx.x, ln = tid & 31, wid = tid >> 5;
    const int g = ln >> 2, t = ln & 3;
    const int mw = wid >> 2, nw = wid & 3;
    const int m0 = blockIdx.y * 128, n0 = blockIdx.x * 128;
    const uint32_t sb = smem_u32(sm);

    float c[4][4][4];
#pragma unroll
    for (int a = 0; a < 4; a++)
#pragma unroll
        for (int b = 0; b < 4; b++)
#pragma unroll
            for (int d = 0; d < 4; d++) c[a][b][d] = 0.f;

#define G2_LOAD(kc, s) do {                                                    \
    int _k0 = (kc) << 6;                                                       \
    uint32_t _b = sb + (s) * G2_STAGE;                                         \
    _Pragma("unroll")                                                          \
    for (int _it = 0; _it < 4; _it++) {                                        \
        int _idx = _it * 256 + tid, _r = _idx >> 3, _sg = _idx & 7;            \
        size_t _sa = (size_t)(m0 + _r) * 4096 + _k0 + _sg * 8;                 \
        size_t _sb2 = (size_t)(n0 + _r) * 4096 + _k0 + _sg * 8;                \
        uint32_t _d = _r * 144 + _sg * 16;                                     \
        cp16(_b + _d,         g_F16 + _sa);                                    \
        cp16(_b + 18432 + _d, g_wo16 + _sb2);                                  \
    }                                                                          \
    CP_COMMIT();                                                               \
} while (0)

    G2_LOAD(0, 0);

    const uint32_t a_lane = (uint32_t)((mw * 64 + (ln & 15)) * 144 + ((ln & 16) ? 16 : 0));
    const uint32_t b_lane = (uint32_t)((nw * 32 + (ln & 7)) * 144 + ((ln & 8) ? 16 : 0));

    for (int kc = 0; kc < 64; kc++) {
        if (kc + 1 < 64) { G2_LOAD(kc + 1, (kc + 1) & 1); CP_WAIT(1); }
        else             { CP_WAIT(0); }
        __syncthreads();

        const uint32_t stage = sb + (kc & 1) * G2_STAGE;
#pragma unroll
        for (int ks = 0; ks < 4; ks++) {
            const uint32_t kb = ks * 32;
            uint32_t ah[4][4];
#pragma unroll
            for (int mt = 0; mt < 4; mt++) {
                uint32_t ad = stage + a_lane + mt * (16 * 144) + kb;
                LDM_X4(ah[mt], ad);
            }
#pragma unroll
            for (int nt = 0; nt < 4; nt++) {
                uint32_t bd = stage + 18432 + b_lane + nt * (8 * 144) + kb;
                uint32_t bh[2];
                LDM_X2(bh, bd);
#pragma unroll
                for (int mt = 0; mt < 4; mt++)
                    mma_f16(c[mt][nt], ah[mt], bh);
            }
        }
        __syncthreads();
    }

    // epilogue: /256 + bias
#pragma unroll
    for (int mt = 0; mt < 4; mt++)
#pragma unroll
        for (int nt = 0; nt < 4; nt++) {
            int col = n0 + nw * 32 + nt * 8 + t * 2;
            float b0 = bo[col], b1 = bo[col + 1];
#pragma unroll
            for (int hseg = 0; hseg < 2; hseg++) {
                int row = m0 + mw * 64 + mt * 16 + g + hseg * 8;
                float v0 = c[mt][nt][hseg * 2 + 0] * 0.00390625f + b0;
                float v1 = c[mt][nt][hseg * 2 + 1] * 0.00390625f + b1;
                *(float2*)&out0[(size_t)row * 512 + col] = make_float2(v0, v1);
            }
        }
#undef G2_LOAD
}

// ---------------------------------------------------------------------------
extern "C" void kernel_launch(void* const* d_in, const int* in_sizes, int n_in,
                              void* d_out, int out_size)
{
    const float* x  = (const float*)d_in[0];
    const float* Wq = (const float*)d_in[1];
    const float* bq = (const float*)d_in[2];
    const float* Wk = (const float*)d_in[3];
    const float* bk = (const float*)d_in[4];
    const float* Wv = (const float*)d_in[5];
    const float* bv = (const float*)d_in[6];
    const float* cv = (const float*)d_in[7];
    const float* Wo = (const float*)d_in[8];
    const float* bo = (const float*)d_in[9];
    float* out = (float*)d_out;

    cudaFuncSetAttribute(mm_kernel, cudaFuncAttributeMaxDynamicSharedMemorySize, MM_SMEM);
    cudaFuncSetAttribute(gemm1_kernel, cudaFuncAttributeMaxDynamicSharedMemorySize, G1_SMEM);
    cudaFuncSetAttribute(gemm2_kernel, cudaFuncAttributeMaxDynamicSharedMemorySize, G2_SMEM);

    cvt_all_kernel<<<11008, 256>>>((const float4*)x, (const float4*)Wq,
                                   (const float4*)Wk, (const float4*)Wv,
                                   (const float4*)Wo);

    mm_kernel<<<dim3(12, 128), 256, MM_SMEM>>>(bq, bk, bv, cv);

    gemm1_kernel<<<dim3(8, 256), 512, G1_SMEM>>>();

    gemm2_kernel<<<dim3(4, 128), 256, G2_SMEM>>>(bo, out);
}

// round 15
// speedup vs baseline: 8.6345x; 1.0141x over previous
#include <cuda_runtime.h>
#include <cuda_fp16.h>
#include <cstdint>
#include <cstddef>

// ---------------- static scratch (no cudaMalloc allowed) -------------------
__device__ __half g_x16[(size_t)16384*512];          // x fp16 single
__device__ __half g_wc16[(size_t)1536*512];          // 16*[Wq;Wk;Wv] fp16 single
__device__ __half g_wo16[(size_t)512*4096];          // 16*Wo fp16 single
__device__ __half g_q16[(size_t)16384*512];          // fp16(q*cv*2), scrambled
__device__ __half g_k16[(size_t)16384*512];          // fp16(k), scrambled
__device__ __half g_v16[(size_t)16384*512];          // fp16(v), scrambled
__device__ __half g_F16[(size_t)16384*4096];         // 16*F fp16 single

// ---------------- helpers ----------------------------------------------------
__device__ __forceinline__ uint32_t smem_u32(const void* p) {
    uint32_t a;
    asm("{ .reg .u64 t; cvta.to.shared.u64 t, %1; cvt.u32.u64 %0, t; }"
        : "=r"(a) : "l"(p));
    return a;
}
__device__ __forceinline__ void cp16(uint32_t dst, const void* src) {
    asm volatile("cp.async.cg.shared.global [%0], [%1], 16;"
                 :: "r"(dst), "l"(src) : "memory");
}
#define CP_COMMIT() asm volatile("cp.async.commit_group;" ::: "memory")
#define CP_WAIT(n)  asm volatile("cp.async.wait_group %0;" :: "n"(n) : "memory")

#define LDM_X4(r, a) \
    asm volatile("ldmatrix.sync.aligned.m8n8.x4.shared.b16 {%0,%1,%2,%3}, [%4];" \
        : "=r"((r)[0]), "=r"((r)[1]), "=r"((r)[2]), "=r"((r)[3]) : "r"(a))

__device__ __forceinline__ void mma_f16(float* c, const uint32_t* a, const uint32_t* b) {
    asm volatile(
        "mma.sync.aligned.m16n8k16.row.col.f32.f16.f16.f32 "
        "{%0,%1,%2,%3}, {%4,%5,%6,%7}, {%8,%9}, {%0,%1,%2,%3};"
        : "+f"(c[0]), "+f"(c[1]), "+f"(c[2]), "+f"(c[3])
        : "r"(a[0]), "r"(a[1]), "r"(a[2]), "r"(a[3]), "r"(b[0]), "r"(b[1]));
}
__device__ __forceinline__ uint32_t pack_f16x2(float p0, float p1) {
    uint32_t r;
    asm("cvt.rn.f16x2.f32 %0, %1, %2;" : "=r"(r) : "f"(p1), "f"(p0));
    return r;
}
__device__ __forceinline__ uint32_t hmul2(uint32_t a, uint32_t b) {
    uint32_t r;
    asm("mul.rn.f16x2 %0, %1, %2;" : "=r"(r) : "r"(a), "r"(b));
    return r;
}

// ---------------------------------------------------------------------------
// cvt_all: single launch converting x, Wq, Wk, Wv, Wo to fp16 (W's scaled 16x)
// ---------------------------------------------------------------------------
__global__ void cvt_all_kernel(const float4* __restrict__ x,
                               const float4* __restrict__ Wq,
                               const float4* __restrict__ Wk,
                               const float4* __restrict__ Wv,
                               const float4* __restrict__ Wo) {
    int bid = blockIdx.x;
    const float4* in;
    uint2* out;
    float s;
    int base;
    if (bid < 8192)      { in = x;  out = (uint2*)g_x16;  s = 1.f;  base = bid; }
    else if (bid < 8448) { in = Wq; out = (uint2*)g_wc16; s = 16.f; base = bid - 8192; }
    else if (bid < 8704) { in = Wk; out = (uint2*)(g_wc16 + 512*512); s = 16.f; base = bid - 8448; }
    else if (bid < 8960) { in = Wv; out = (uint2*)(g_wc16 + 2*512*512); s = 16.f; base = bid - 8704; }
    else                 { in = Wo; out = (uint2*)g_wo16; s = 16.f; base = bid - 8960; }
    int i = base * 256 + threadIdx.x;
    float4 v = in[i];
    uint2 o;
    o.x = pack_f16x2(s * v.x, s * v.y);
    o.y = pack_f16x2(s * v.z, s * v.w);
    out[i] = o;
}

// ---------------------------------------------------------------------------
// mm_kernel (projections): 16*C = x16 @ (16*W)^T
//   CTA 128x128, 8 warps (2Mx4N), K-chunk 64, 3-stage cp.async, LDM_X4 B.
//   proj = n0>>9: 0=q (*cv*2), 1=k, 2=v — all fp16 scramble-writes.
// Stage (36864B): X16 128x72f16 | W16 128x72f16
// ---------------------------------------------------------------------------
#define MM_STAGE 36864
#define MM_SMEM  (3 * MM_STAGE)

__global__ __launch_bounds__(256, 2) void mm_kernel(
    const float* __restrict__ bq, const float* __restrict__ bk,
    const float* __restrict__ bv, const float* __restrict__ cv)
{
    extern __shared__ char sm[];
    const int tid = threadIdx.x, ln = tid & 31, wid = tid >> 5;
    const int g = ln >> 2, t = ln & 3;
    const int mw = wid >> 2, nw = wid & 3;
    const int m0 = blockIdx.y * 128, n0 = blockIdx.x * 128;
    const uint32_t sb = smem_u32(sm);

    float c[4][4][4];
#pragma unroll
    for (int a = 0; a < 4; a++)
#pragma unroll
        for (int b = 0; b < 4; b++)
#pragma unroll
            for (int d = 0; d < 4; d++) c[a][b][d] = 0.f;

#define LOAD_CHUNK(kc, s) do {                                                 \
    int _k0 = (kc) << 6;                                                       \
    uint32_t _b = sb + (s) * MM_STAGE;                                         \
    _Pragma("unroll")                                                          \
    for (int _it = 0; _it < 4; _it++) {                                        \
        int _idx = _it * 256 + tid, _r = _idx >> 3, _sg = _idx & 7;            \
        size_t _sa = (size_t)(m0 + _r) * 512 + _k0 + _sg * 8;                  \
        size_t _sbo = (size_t)(n0 + _r) * 512 + _k0 + _sg * 8;                 \
        uint32_t _d = _r * 144 + _sg * 16;                                     \
        cp16(_b + _d,         g_x16 + _sa);                                    \
        cp16(_b + 18432 + _d, g_wc16 + _sbo);                                  \
    }                                                                          \
    CP_COMMIT();                                                               \
} while (0)

    LOAD_CHUNK(0, 0);
    LOAD_CHUNK(1, 1);

    const uint32_t a_lane = (uint32_t)((mw * 64 + (ln & 15)) * 144 + ((ln & 16) ? 16 : 0));
    const uint32_t b_lane4 = (uint32_t)(((ln & 7) + ((ln & 16) ? 8 : 0)) * 144
                                        + ((ln & 8) ? 16 : 0));

    for (int kc = 0; kc < 8; kc++) {
        if (kc == 7) CP_WAIT(0); else CP_WAIT(1);
        __syncthreads();
        if (kc < 6) LOAD_CHUNK(kc + 2, (kc + 2) % 3);

        const uint32_t stage = sb + (kc % 3) * MM_STAGE;
#pragma unroll
        for (int ks = 0; ks < 4; ks++) {
            const uint32_t kb = ks * 32;
            uint32_t ah[4][4];
#pragma unroll
            for (int mt = 0; mt < 4; mt++) {
                uint32_t ad = stage + a_lane + mt * (16 * 144) + kb;
                LDM_X4(ah[mt], ad);
            }
#pragma unroll
            for (int ntp = 0; ntp < 2; ntp++) {
                uint32_t bd = stage + 18432 + b_lane4 + (nw * 32 + ntp * 16) * 144 + kb;
                uint32_t bh4[4];
                LDM_X4(bh4, bd);
#pragma unroll
                for (int mt = 0; mt < 4; mt++) {
                    mma_f16(c[mt][2 * ntp],     ah[mt], bh4);
                    mma_f16(c[mt][2 * ntp + 1], ah[mt], bh4 + 2);
                }
            }
        }
        __syncthreads();
    }

    // epilogue: C_true = accum/16 + bias, fp16 scramble-write
    const int proj = n0 >> 9;
    const float* bias = (proj == 0 ? bq : proj == 1 ? bk : bv);
    __half* outp = (proj == 0 ? g_q16 : proj == 1 ? g_k16 : g_v16);
#pragma unroll
    for (int mt = 0; mt < 4; mt++)
#pragma unroll
        for (int nt = 0; nt < 4; nt++) {
            int col = (n0 + nw * 32 + nt * 8 + t * 2) & 511;
            float b0 = bias[col], b1 = bias[col + 1];
#pragma unroll
            for (int hseg = 0; hseg < 2; hseg++) {
                int row = m0 + mw * 64 + mt * 16 + g + hseg * 8;
                float v0 = c[mt][nt][hseg * 2 + 0] * 0.0625f + b0;
                float v1 = c[mt][nt][hseg * 2 + 1] * 0.0625f + b1;
                int core = row >> 11, bb = (row >> 3) & 255;
                int ii = (row & 7) * 8 + (col >> 6), hh = col & 63;
                size_t dst = (size_t)(bb * 64 + ii) * 512 + core * 64 + hh;
                if (proj == 0) {
                    v0 *= cv[core * 64 + hh]     * 2.0f;   // 16 * cv/8
                    v1 *= cv[core * 64 + hh + 1] * 2.0f;
                }
                *(uint32_t*)&outp[dst] = pack_f16x2(v0, v1);
            }
        }
#undef LOAD_CHUNK
}

// ---------------------------------------------------------------------------
// gemm1_kernel (fp16): F16[m,n] = sum_r (q16 .* k16)[m,r] * v16[n,r]
//   per (b, i0=8 i's): M=512, N=64, K=512 in 8 chunks; 3-stage pipeline.
//   A fragments: LDM_X4 on K tile then HMUL2 with broadcast q pairs.
// Stage (19456B): K16 64x72f16 | V16 64x72f16 | Q16 8x64f16
// ---------------------------------------------------------------------------
#define G1_K   0
#define G1_V   9216
#define G1_Q   18432
#define G1_STAGE 19456
#define G1_SMEM  (3 * G1_STAGE)

__global__ __launch_bounds__(512, 1) void gemm1_kernel()
{
    extern __shared__ char sm[];
    const uint32_t sb = smem_u32(sm);
    const int tid = threadIdx.x, ln = tid & 31, wid = tid >> 5;
    const int g = ln >> 2, t = ln & 3;
    const int b = blockIdx.y, i0 = blockIdx.x * 8;
    const int il  = wid >> 1;            // i within group of 8
    const int jb0 = (wid & 1) * 32;      // j base within 64

    float c[2][8][4];                    // [mt][nt][frag]
#pragma unroll
    for (int a = 0; a < 2; a++)
#pragma unroll
        for (int bb = 0; bb < 8; bb++)
#pragma unroll
            for (int d = 0; d < 4; d++) c[a][bb][d] = 0.f;

#define G1_PREFETCH(kc_, s_) do {                                              \
    int _r0 = (kc_) << 6;                                                      \
    uint32_t _st = sb + (s_) * G1_STAGE;                                       \
    {                                                                          \
        int _r = tid >> 3, _sg = tid & 7;                                      \
        size_t _src = (size_t)(b * 64 + _r) * 512 + _r0 + _sg * 8;             \
        cp16(_st + G1_K + _r * 144 + _sg * 16, g_k16 + _src);                  \
        cp16(_st + G1_V + _r * 144 + _sg * 16, g_v16 + _src);                  \
    }                                                                          \
    if (tid < 64)                                                              \
        cp16(_st + G1_Q + (tid >> 3) * 128 + (tid & 7) * 16,                   \
             g_q16 + ((size_t)(b * 64 + i0 + (tid >> 3))) * 512 + _r0 + (tid & 7) * 8); \
    CP_COMMIT();                                                               \
} while (0)

    G1_PREFETCH(0, 0);
    G1_PREFETCH(1, 1);

    const uint32_t a_lane = (uint32_t)((jb0 + (ln & 15)) * 144 + ((ln & 16) ? 16 : 0));
    const uint32_t b_lane4 = (uint32_t)(((ln & 7) + ((ln & 16) ? 8 : 0)) * 144
                                        + ((ln & 8) ? 16 : 0));

    for (int kc = 0; kc < 8; kc++) {
        if (kc == 7) CP_WAIT(0); else CP_WAIT(1);
        __syncthreads();
        if (kc < 6) G1_PREFETCH(kc + 2, (kc + 2) % 3);

        const int s = kc % 3;
        const uint32_t kbase = sb + s * G1_STAGE + G1_K;
        const uint32_t vbase = sb + s * G1_STAGE + G1_V;
        const char*    qbase = sm + s * G1_STAGE + G1_Q;

#pragma unroll
        for (int ks = 0; ks < 4; ks++) {
            uint32_t q2a = *(const uint32_t*)(qbase + il * 128 + ks * 32 + t * 4);
            uint32_t q2b = *(const uint32_t*)(qbase + il * 128 + ks * 32 + t * 4 + 16);

            uint32_t bh4[4][4];
#pragma unroll
            for (int ntp = 0; ntp < 4; ntp++)
                LDM_X4(bh4[ntp], vbase + b_lane4 + ntp * (16 * 144) + ks * 32);

#pragma unroll
            for (int mt = 0; mt < 2; mt++) {
                uint32_t kf[4];
                LDM_X4(kf, kbase + a_lane + mt * (16 * 144) + ks * 32);
                uint32_t ah[4];
                ah[0] = hmul2(kf[0], q2a);
                ah[1] = hmul2(kf[1], q2a);
                ah[2] = hmul2(kf[2], q2b);
                ah[3] = hmul2(kf[3], q2b);
#pragma unroll
                for (int ntp = 0; ntp < 4; ntp++) {
                    mma_f16(c[mt][2 * ntp],     ah, bh4[ntp]);
                    mma_f16(c[mt][2 * ntp + 1], ah, bh4[ntp] + 2);
                }
            }
        }
    }

    // epilogue: write 16F as fp16 single
    const size_t rowF = (size_t)(b * 64 + i0 + il);
#pragma unroll
    for (int mt = 0; mt < 2; mt++)
#pragma unroll
        for (int nt = 0; nt < 8; nt++) {
            int n = nt * 8 + t * 2;
#pragma unroll
            for (int hseg = 0; hseg < 2; hseg++) {
                int j = jb0 + mt * 16 + g + hseg * 8;
                size_t dst = rowF * 4096 + (size_t)j * 64 + n;
                *(uint32_t*)&g_F16[dst] =
                    pack_f16x2(c[mt][nt][hseg * 2 + 0], c[mt][nt][hseg * 2 + 1]);
            }
        }
#undef G1_PREFETCH
}

// ---------------------------------------------------------------------------
// gemm2_kernel (fp16): out = (F16 @ Wo16^T)/256 + bo
//   CTA 128x128, 8 warps (2Mx4N), K-chunk 64, 3-stage cp.async, LDM_X4 B.
// Stage (36864B): F16 128x72f16 | Wo16 128x72f16
// ---------------------------------------------------------------------------
#define G2_STAGE 36864
#define G2_SMEM  (3 * G2_STAGE)

__global__ __launch_bounds__(256, 2) void gemm2_kernel(
    const float* __restrict__ bo, float* __restrict__ out0)
{
    extern __shared__ char sm[];
    const int tid = threadIdx.x, ln = tid & 31, wid = tid >> 5;
    const int g = ln >> 2, t = ln & 3;
    const int mw = wid >> 2, nw = wid & 3;
    const int m0 = blockIdx.y * 128, n0 = blockIdx.x * 128;
    const uint32_t sb = smem_u32(sm);

    float c[4][4][4];
#pragma unroll
    for (int a = 0; a < 4; a++)
#pragma unroll
        for (int b = 0; b < 4; b++)
#pragma unroll
            for (int d = 0; d < 4; d++) c[a][b][d] = 0.f;

#define G2_LOAD(kc, s) do {                                                    \
    int _k0 = (kc) << 6;                                                       \
    uint32_t _b = sb + (s) * G2_STAGE;                                         \
    _Pragma("unroll")                                                          \
    for (int _it = 0; _it < 4; _it++) {                                        \
        int _idx = _it * 256 + tid, _r = _idx >> 3, _sg = _idx & 7;            \
        size_t _sa = (size_t)(m0 + _r) * 4096 + _k0 + _sg * 8;                 \
        size_t _sb2 = (size_t)(n0 + _r) * 4096 + _k0 + _sg * 8;                \
        uint32_t _d = _r * 144 + _sg * 16;                                     \
        cp16(_b + _d,         g_F16 + _sa);                                    \
        cp16(_b + 18432 + _d, g_wo16 + _sb2);                                  \
    }                                                                          \
    CP_COMMIT();                                                               \
} while (0)

    G2_LOAD(0, 0);
    G2_LOAD(1, 1);

    const uint32_t a_lane = (uint32_t)((mw * 64 + (ln & 15)) * 144 + ((ln & 16) ? 16 : 0));
    const uint32_t b_lane4 = (uint32_t)(((ln & 7) + ((ln & 16) ? 8 : 0)) * 144
                                        + ((ln & 8) ? 16 : 0));

    for (int kc = 0; kc < 64; kc++) {
        if (kc == 63) CP_WAIT(0); else CP_WAIT(1);
        __syncthreads();
        if (kc < 62) G2_LOAD(kc + 2, (kc + 2) % 3);

        const uint32_t stage = sb + (kc % 3) * G2_STAGE;
#pragma unroll
        for (int ks = 0; ks < 4; ks++) {
            const uint32_t kb = ks * 32;
            uint32_t ah[4][4];
#pragma unroll
            for (int mt = 0; mt < 4; mt++) {
                uint32_t ad = stage + a_lane + mt * (16 * 144) + kb;
                LDM_X4(ah[mt], ad);
            }
#pragma unroll
            for (int ntp = 0; ntp < 2; ntp++) {
                uint32_t bd = stage + 18432 + b_lane4 + (nw * 32 + ntp * 16) * 144 + kb;
                uint32_t bh4[4];
                LDM_X4(bh4, bd);
#pragma unroll
                for (int mt = 0; mt < 4; mt++) {
                    mma_f16(c[mt][2 * ntp],     ah[mt], bh4);
                    mma_f16(c[mt][2 * ntp + 1], ah[mt], bh4 + 2);
                }
            }
        }
        __syncthreads();
    }

    // epilogue: /256 + bias
#pragma unroll
    for (int mt = 0; mt < 4; mt++)
#pragma unroll
        for (int nt = 0; nt < 4; nt++) {
            int col = n0 + nw * 32 + nt * 8 + t * 2;
            float b0 = bo[col], b1 = bo[col + 1];
#pragma unroll
            for (int hseg = 0; hseg < 2; hseg++) {
                int row = m0 + mw * 64 + mt * 16 + g + hseg * 8;
                float v0 = c[mt][nt][hseg * 2 + 0] * 0.00390625f + b0;
                float v1 = c[mt][nt][hseg * 2 + 1] * 0.00390625f + b1;
                *(float2*)&out0[(size_t)row * 512 + col] = make_float2(v0, v1);
            }
        }
#undef G2_LOAD
}

// ---------------------------------------------------------------------------
extern "C" void kernel_launch(void* const* d_in, const int* in_sizes, int n_in,
                              void* d_out, int out_size)
{
    const float* x  = (const float*)d_in[0];
    const float* Wq = (const float*)d_in[1];
    const float* bq = (const float*)d_in[2];
    const float* Wk = (const float*)d_in[3];
    const float* bk = (const float*)d_in[4];
    const float* Wv = (const float*)d_in[5];
    const float* bv = (const float*)d_in[6];
    const float* cv = (const float*)d_in[7];
    const float* Wo = (const float*)d_in[8];
    const float* bo = (const float*)d_in[9];
    float* out = (float*)d_out;

    cudaFuncSetAttribute(mm_kernel, cudaFuncAttributeMaxDynamicSharedMemorySize, MM_SMEM);
    cudaFuncSetAttribute(gemm1_kernel, cudaFuncAttributeMaxDynamicSharedMemorySize, G1_SMEM);
    cudaFuncSetAttribute(gemm2_kernel, cudaFuncAttributeMaxDynamicSharedMemorySize, G2_SMEM);

    cvt_all_kernel<<<11008, 256>>>((const float4*)x, (const float4*)Wq,
                                   (const float4*)Wk, (const float4*)Wv,
                                   (const float4*)Wo);

    mm_kernel<<<dim3(12, 128), 256, MM_SMEM>>>(bq, bk, bv, cv);

    gemm1_kernel<<<dim3(8, 256), 512, G1_SMEM>>>();

    gemm2_kernel<<<dim3(4, 128), 256, G2_SMEM>>>(bo, out);
}

// round 16
// speedup vs baseline: 9.5630x; 1.1075x over previous
#include <cuda_runtime.h>
#include <cuda_fp16.h>
#include <cstdint>
#include <cstddef>

// ---------------- static scratch (no cudaMalloc allowed) -------------------
__device__ __half g_x16[(size_t)16384*512];          // x fp16 single
__device__ __half g_wc16[(size_t)1536*512];          // 16*[Wq;Wk;Wv] fp16 single
__device__ __half g_wo16[(size_t)512*4096];          // 16*Wo fp16 single
__device__ __half g_q16[(size_t)16384*512];          // fp16(q*cv*2), scrambled
__device__ __half g_k16[(size_t)16384*512];          // fp16(k), scrambled
__device__ __half g_v16[(size_t)16384*512];          // fp16(v), scrambled
__device__ __half g_F16[(size_t)16384*4096];         // 16*F fp16 single

// ---------------- helpers ----------------------------------------------------
__device__ __forceinline__ uint32_t smem_u32(const void* p) {
    uint32_t a;
    asm("{ .reg .u64 t; cvta.to.shared.u64 t, %1; cvt.u32.u64 %0, t; }"
        : "=r"(a) : "l"(p));
    return a;
}
__device__ __forceinline__ void cp16(uint32_t dst, const void* src) {
    asm volatile("cp.async.cg.shared.global [%0], [%1], 16;"
                 :: "r"(dst), "l"(src) : "memory");
}
#define CP_COMMIT() asm volatile("cp.async.commit_group;" ::: "memory")
#define CP_WAIT(n)  asm volatile("cp.async.wait_group %0;" :: "n"(n) : "memory")

#define LDM_X4(r, a) \
    asm volatile("ldmatrix.sync.aligned.m8n8.x4.shared.b16 {%0,%1,%2,%3}, [%4];" \
        : "=r"((r)[0]), "=r"((r)[1]), "=r"((r)[2]), "=r"((r)[3]) : "r"(a))

__device__ __forceinline__ void mma_f16(float* c, const uint32_t* a, const uint32_t* b) {
    asm volatile(
        "mma.sync.aligned.m16n8k16.row.col.f32.f16.f16.f32 "
        "{%0,%1,%2,%3}, {%4,%5,%6,%7}, {%8,%9}, {%0,%1,%2,%3};"
        : "+f"(c[0]), "+f"(c[1]), "+f"(c[2]), "+f"(c[3])
        : "r"(a[0]), "r"(a[1]), "r"(a[2]), "r"(a[3]), "r"(b[0]), "r"(b[1]));
}
__device__ __forceinline__ uint32_t pack_f16x2(float p0, float p1) {
    uint32_t r;
    asm("cvt.rn.f16x2.f32 %0, %1, %2;" : "=r"(r) : "f"(p1), "f"(p0));
    return r;
}
__device__ __forceinline__ uint32_t hmul2(uint32_t a, uint32_t b) {
    uint32_t r;
    asm("mul.rn.f16x2 %0, %1, %2;" : "=r"(r) : "r"(a), "r"(b));
    return r;
}

// ---------------------------------------------------------------------------
// cvt_all: single launch converting x, Wq, Wk, Wv, Wo to fp16 (W's scaled 16x)
// ---------------------------------------------------------------------------
__global__ void cvt_all_kernel(const float4* __restrict__ x,
                               const float4* __restrict__ Wq,
                               const float4* __restrict__ Wk,
                               const float4* __restrict__ Wv,
                               const float4* __restrict__ Wo) {
    int bid = blockIdx.x;
    const float4* in;
    uint2* out;
    float s;
    int base;
    if (bid < 8192)      { in = x;  out = (uint2*)g_x16;  s = 1.f;  base = bid; }
    else if (bid < 8448) { in = Wq; out = (uint2*)g_wc16; s = 16.f; base = bid - 8192; }
    else if (bid < 8704) { in = Wk; out = (uint2*)(g_wc16 + 512*512); s = 16.f; base = bid - 8448; }
    else if (bid < 8960) { in = Wv; out = (uint2*)(g_wc16 + 2*512*512); s = 16.f; base = bid - 8704; }
    else                 { in = Wo; out = (uint2*)g_wo16; s = 16.f; base = bid - 8960; }
    int i = base * 256 + threadIdx.x;
    float4 v = in[i];
    uint2 o;
    o.x = pack_f16x2(s * v.x, s * v.y);
    o.y = pack_f16x2(s * v.z, s * v.w);
    out[i] = o;
}

// ---------------------------------------------------------------------------
// mm_kernel (projections): 16*C = x16 @ (16*W)^T
//   CTA 128x128, 8 warps (2Mx4N), K-chunk 64, 3-stage cp.async, LDM_X4 B.
//   ONE barrier per chunk; loads issued after ks=0 to de-burst the smem port.
// Stage (36864B): X16 128x72f16 | W16 128x72f16
// ---------------------------------------------------------------------------
#define MM_STAGE 36864
#define MM_SMEM  (3 * MM_STAGE)

__global__ __launch_bounds__(256, 2) void mm_kernel(
    const float* __restrict__ bq, const float* __restrict__ bk,
    const float* __restrict__ bv, const float* __restrict__ cv)
{
    extern __shared__ char sm[];
    const int tid = threadIdx.x, ln = tid & 31, wid = tid >> 5;
    const int g = ln >> 2, t = ln & 3;
    const int mw = wid >> 2, nw = wid & 3;
    const int m0 = blockIdx.y * 128, n0 = blockIdx.x * 128;
    const uint32_t sb = smem_u32(sm);

    float c[4][4][4];
#pragma unroll
    for (int a = 0; a < 4; a++)
#pragma unroll
        for (int b = 0; b < 4; b++)
#pragma unroll
            for (int d = 0; d < 4; d++) c[a][b][d] = 0.f;

#define LOAD_CHUNK(kc, s) do {                                                 \
    int _k0 = (kc) << 6;                                                       \
    uint32_t _b = sb + (s) * MM_STAGE;                                         \
    _Pragma("unroll")                                                          \
    for (int _it = 0; _it < 4; _it++) {                                        \
        int _idx = _it * 256 + tid, _r = _idx >> 3, _sg = _idx & 7;            \
        size_t _sa = (size_t)(m0 + _r) * 512 + _k0 + _sg * 8;                  \
        size_t _sbo = (size_t)(n0 + _r) * 512 + _k0 + _sg * 8;                 \
        uint32_t _d = _r * 144 + _sg * 16;                                     \
        cp16(_b + _d,         g_x16 + _sa);                                    \
        cp16(_b + 18432 + _d, g_wc16 + _sbo);                                  \
    }                                                                          \
    CP_COMMIT();                                                               \
} while (0)

    LOAD_CHUNK(0, 0);
    LOAD_CHUNK(1, 1);

    const uint32_t a_lane = (uint32_t)((mw * 64 + (ln & 15)) * 144 + ((ln & 16) ? 16 : 0));
    const uint32_t b_lane4 = (uint32_t)(((ln & 7) + ((ln & 16) ? 8 : 0)) * 144
                                        + ((ln & 8) ? 16 : 0));

    for (int kc = 0; kc < 8; kc++) {
        if (kc == 7) CP_WAIT(0); else CP_WAIT(1);
        __syncthreads();

        const uint32_t stage = sb + (kc % 3) * MM_STAGE;
#pragma unroll
        for (int ks = 0; ks < 4; ks++) {
            const uint32_t kb = ks * 32;
            uint32_t ah[4][4];
#pragma unroll
            for (int mt = 0; mt < 4; mt++) {
                uint32_t ad = stage + a_lane + mt * (16 * 144) + kb;
                LDM_X4(ah[mt], ad);
            }
#pragma unroll
            for (int ntp = 0; ntp < 2; ntp++) {
                uint32_t bd = stage + 18432 + b_lane4 + (nw * 32 + ntp * 16) * 144 + kb;
                uint32_t bh4[4];
                LDM_X4(bh4, bd);
#pragma unroll
                for (int mt = 0; mt < 4; mt++) {
                    mma_f16(c[mt][2 * ntp],     ah[mt], bh4);
                    mma_f16(c[mt][2 * ntp + 1], ah[mt], bh4 + 2);
                }
            }
            if (ks == 0 && kc < 6) LOAD_CHUNK(kc + 2, (kc + 2) % 3);
        }
    }

    // epilogue: C_true = accum/16 + bias, fp16 scramble-write
    const int proj = n0 >> 9;
    const float* bias = (proj == 0 ? bq : proj == 1 ? bk : bv);
    __half* outp = (proj == 0 ? g_q16 : proj == 1 ? g_k16 : g_v16);
#pragma unroll
    for (int mt = 0; mt < 4; mt++)
#pragma unroll
        for (int nt = 0; nt < 4; nt++) {
            int col = (n0 + nw * 32 + nt * 8 + t * 2) & 511;
            float b0 = bias[col], b1 = bias[col + 1];
#pragma unroll
            for (int hseg = 0; hseg < 2; hseg++) {
                int row = m0 + mw * 64 + mt * 16 + g + hseg * 8;
                float v0 = c[mt][nt][hseg * 2 + 0] * 0.0625f + b0;
                float v1 = c[mt][nt][hseg * 2 + 1] * 0.0625f + b1;
                int core = row >> 11, bb = (row >> 3) & 255;
                int ii = (row & 7) * 8 + (col >> 6), hh = col & 63;
                size_t dst = (size_t)(bb * 64 + ii) * 512 + core * 64 + hh;
                if (proj == 0) {
                    v0 *= cv[core * 64 + hh]     * 2.0f;   // 16 * cv/8
                    v1 *= cv[core * 64 + hh + 1] * 2.0f;
                }
                *(uint32_t*)&outp[dst] = pack_f16x2(v0, v1);
            }
        }
#undef LOAD_CHUNK
}

// ---------------------------------------------------------------------------
// gemm1_kernel (fp16): F16[m,n] = sum_r (q16 .* k16)[m,r] * v16[n,r]
//   per (b, i0=8 i's): M=512, N=64, K=512 in 8 chunks; 3-stage pipeline.
//   A fragments: LDM_X4 on K tile then HMUL2 with broadcast q pairs.
//   Prefetch issued after ks=0 to de-burst the smem port.
// Stage (19456B): K16 64x72f16 | V16 64x72f16 | Q16 8x64f16
// ---------------------------------------------------------------------------
#define G1_K   0
#define G1_V   9216
#define G1_Q   18432
#define G1_STAGE 19456
#define G1_SMEM  (3 * G1_STAGE)

__global__ __launch_bounds__(512, 1) void gemm1_kernel()
{
    extern __shared__ char sm[];
    const uint32_t sb = smem_u32(sm);
    const int tid = threadIdx.x, ln = tid & 31, wid = tid >> 5;
    const int g = ln >> 2, t = ln & 3;
    const int b = blockIdx.y, i0 = blockIdx.x * 8;
    const int il  = wid >> 1;            // i within group of 8
    const int jb0 = (wid & 1) * 32;      // j base within 64

    float c[2][8][4];                    // [mt][nt][frag]
#pragma unroll
    for (int a = 0; a < 2; a++)
#pragma unroll
        for (int bb = 0; bb < 8; bb++)
#pragma unroll
            for (int d = 0; d < 4; d++) c[a][bb][d] = 0.f;

#define G1_PREFETCH(kc_, s_) do {                                              \
    int _r0 = (kc_) << 6;                                                      \
    uint32_t _st = sb + (s_) * G1_STAGE;                                       \
    {                                                                          \
        int _r = tid >> 3, _sg = tid & 7;                                      \
        size_t _src = (size_t)(b * 64 + _r) * 512 + _r0 + _sg * 8;             \
        cp16(_st + G1_K + _r * 144 + _sg * 16, g_k16 + _src);                  \
        cp16(_st + G1_V + _r * 144 + _sg * 16, g_v16 + _src);                  \
    }                                                                          \
    if (tid < 64)                                                              \
        cp16(_st + G1_Q + (tid >> 3) * 128 + (tid & 7) * 16,                   \
             g_q16 + ((size_t)(b * 64 + i0 + (tid >> 3))) * 512 + _r0 + (tid & 7) * 8); \
    CP_COMMIT();                                                               \
} while (0)

    G1_PREFETCH(0, 0);
    G1_PREFETCH(1, 1);

    const uint32_t a_lane = (uint32_t)((jb0 + (ln & 15)) * 144 + ((ln & 16) ? 16 : 0));
    const uint32_t b_lane4 = (uint32_t)(((ln & 7) + ((ln & 16) ? 8 : 0)) * 144
                                        + ((ln & 8) ? 16 : 0));

    for (int kc = 0; kc < 8; kc++) {
        if (kc == 7) CP_WAIT(0); else CP_WAIT(1);
        __syncthreads();

        const int s = kc % 3;
        const uint32_t kbase = sb + s * G1_STAGE + G1_K;
        const uint32_t vbase = sb + s * G1_STAGE + G1_V;
        const char*    qbase = sm + s * G1_STAGE + G1_Q;

#pragma unroll
        for (int ks = 0; ks < 4; ks++) {
            uint32_t q2a = *(const uint32_t*)(qbase + il * 128 + ks * 32 + t * 4);
            uint32_t q2b = *(const uint32_t*)(qbase + il * 128 + ks * 32 + t * 4 + 16);

            uint32_t bh4[4][4];
#pragma unroll
            for (int ntp = 0; ntp < 4; ntp++)
                LDM_X4(bh4[ntp], vbase + b_lane4 + ntp * (16 * 144) + ks * 32);

#pragma unroll
            for (int mt = 0; mt < 2; mt++) {
                uint32_t kf[4];
                LDM_X4(kf, kbase + a_lane + mt * (16 * 144) + ks * 32);
                uint32_t ah[4];
                ah[0] = hmul2(kf[0], q2a);
                ah[1] = hmul2(kf[1], q2a);
                ah[2] = hmul2(kf[2], q2b);
                ah[3] = hmul2(kf[3], q2b);
#pragma unroll
                for (int ntp = 0; ntp < 4; ntp++) {
                    mma_f16(c[mt][2 * ntp],     ah, bh4[ntp]);
                    mma_f16(c[mt][2 * ntp + 1], ah, bh4[ntp] + 2);
                }
            }
            if (ks == 0 && kc < 6) G1_PREFETCH(kc + 2, (kc + 2) % 3);
        }
    }

    // epilogue: write 16F as fp16 single
    const size_t rowF = (size_t)(b * 64 + i0 + il);
#pragma unroll
    for (int mt = 0; mt < 2; mt++)
#pragma unroll
        for (int nt = 0; nt < 8; nt++) {
            int n = nt * 8 + t * 2;
#pragma unroll
            for (int hseg = 0; hseg < 2; hseg++) {
                int j = jb0 + mt * 16 + g + hseg * 8;
                size_t dst = rowF * 4096 + (size_t)j * 64 + n;
                *(uint32_t*)&g_F16[dst] =
                    pack_f16x2(c[mt][nt][hseg * 2 + 0], c[mt][nt][hseg * 2 + 1]);
            }
        }
#undef G1_PREFETCH
}

// ---------------------------------------------------------------------------
// gemm2_kernel (fp16): out = (F16 @ Wo16^T)/256 + bo
//   CTA 128x128, 8 warps (2Mx4N), K-chunk 64, 3-stage cp.async, LDM_X4 B.
//   ONE barrier per chunk; loads issued after ks=0.
// Stage (36864B): F16 128x72f16 | Wo16 128x72f16
// ---------------------------------------------------------------------------
#define G2_STAGE 36864
#define G2_SMEM  (3 * G2_STAGE)

__global__ __launch_bounds__(256, 2) void gemm2_kernel(
    const float* __restrict__ bo, float* __restrict__ out0)
{
    extern __shared__ char sm[];
    const int tid = threadIdx.x, ln = tid & 31, wid = tid >> 5;
    const int g = ln >> 2, t = ln & 3;
    const int mw = wid >> 2, nw = wid & 3;
    const int m0 = blockIdx.y * 128, n0 = blockIdx.x * 128;
    const uint32_t sb = smem_u32(sm);

    float c[4][4][4];
#pragma unroll
    for (int a = 0; a < 4; a++)
#pragma unroll
        for (int b = 0; b < 4; b++)
#pragma unroll
            for (int d = 0; d < 4; d++) c[a][b][d] = 0.f;

#define G2_LOAD(kc, s) do {                                                    \
    int _k0 = (kc) << 6;                                                       \
    uint32_t _b = sb + (s) * G2_STAGE;                                         \
    _Pragma("unroll")                                                          \
    for (int _it = 0; _it < 4; _it++) {                                        \
        int _idx = _it * 256 + tid, _r = _idx >> 3, _sg = _idx & 7;            \
        size_t _sa = (size_t)(m0 + _r) * 4096 + _k0 + _sg * 8;                 \
        size_t _sb2 = (size_t)(n0 + _r) * 4096 + _k0 + _sg * 8;                \
        uint32_t _d = _r * 144 + _sg * 16;                                     \
        cp16(_b + _d,         g_F16 + _sa);                                    \
        cp16(_b + 18432 + _d, g_wo16 + _sb2);                                  \
    }                                                                          \
    CP_COMMIT();                                                               \
} while (0)

    G2_LOAD(0, 0);
    G2_LOAD(1, 1);

    const uint32_t a_lane = (uint32_t)((mw * 64 + (ln & 15)) * 144 + ((ln & 16) ? 16 : 0));
    const uint32_t b_lane4 = (uint32_t)(((ln & 7) + ((ln & 16) ? 8 : 0)) * 144
                                        + ((ln & 8) ? 16 : 0));

    for (int kc = 0; kc < 64; kc++) {
        if (kc == 63) CP_WAIT(0); else CP_WAIT(1);
        __syncthreads();

        const uint32_t stage = sb + (kc % 3) * G2_STAGE;
#pragma unroll
        for (int ks = 0; ks < 4; ks++) {
            const uint32_t kb = ks * 32;
            uint32_t ah[4][4];
#pragma unroll
            for (int mt = 0; mt < 4; mt++) {
                uint32_t ad = stage + a_lane + mt * (16 * 144) + kb;
                LDM_X4(ah[mt], ad);
            }
#pragma unroll
            for (int ntp = 0; ntp < 2; ntp++) {
                uint32_t bd = stage + 18432 + b_lane4 + (nw * 32 + ntp * 16) * 144 + kb;
                uint32_t bh4[4];
                LDM_X4(bh4, bd);
#pragma unroll
                for (int mt = 0; mt < 4; mt++) {
                    mma_f16(c[mt][2 * ntp],     ah[mt], bh4);
                    mma_f16(c[mt][2 * ntp + 1], ah[mt], bh4 + 2);
                }
            }
            if (ks == 0 && kc < 62) G2_LOAD(kc + 2, (kc + 2) % 3);
        }
    }

    // epilogue: /256 + bias
#pragma unroll
    for (int mt = 0; mt < 4; mt++)
#pragma unroll
        for (int nt = 0; nt < 4; nt++) {
            int col = n0 + nw * 32 + nt * 8 + t * 2;
            float b0 = bo[col], b1 = bo[col + 1];
#pragma unroll
            for (int hseg = 0; hseg < 2; hseg++) {
                int row = m0 + mw * 64 + mt * 16 + g + hseg * 8;
                float v0 = c[mt][nt][hseg * 2 + 0] * 0.00390625f + b0;
                float v1 = c[mt][nt][hseg * 2 + 1] * 0.00390625f + b1;
                *(float2*)&out0[(size_t)row * 512 + col] = make_float2(v0, v1);
            }
        }
#undef G2_LOAD
}

// ---------------------------------------------------------------------------
extern "C" void kernel_launch(void* const* d_in, const int* in_sizes, int n_in,
                              void* d_out, int out_size)
{
    const float* x  = (const float*)d_in[0];
    const float* Wq = (const float*)d_in[1];
    const float* bq = (const float*)d_in[2];
    const float* Wk = (const float*)d_in[3];
    const float* bk = (const float*)d_in[4];
    const float* Wv = (const float*)d_in[5];
    const float* bv = (const float*)d_in[6];
    const float* cv = (const float*)d_in[7];
    const float* Wo = (const float*)d_in[8];
    const float* bo = (const float*)d_in[9];
    float* out = (float*)d_out;

    cudaFuncSetAttribute(mm_kernel, cudaFuncAttributeMaxDynamicSharedMemorySize, MM_SMEM);
    cudaFuncSetAttribute(gemm1_kernel, cudaFuncAttributeMaxDynamicSharedMemorySize, G1_SMEM);
    cudaFuncSetAttribute(gemm2_kernel, cudaFuncAttributeMaxDynamicSharedMemorySize, G2_SMEM);

    cvt_all_kernel<<<11008, 256>>>((const float4*)x, (const float4*)Wq,
                                   (const float4*)Wk, (const float4*)Wv,
                                   (const float4*)Wo);

    mm_kernel<<<dim3(12, 128), 256, MM_SMEM>>>(bq, bk, bv, cv);

    gemm1_kernel<<<dim3(8, 256), 512, G1_SMEM>>>();

    gemm2_kernel<<<dim3(4, 128), 256, G2_SMEM>>>(bo, out);
}

// round 17
// speedup vs baseline: 9.7773x; 1.0224x over previous
#include <cuda_runtime.h>
#include <cuda_fp16.h>
#include <cstdint>
#include <cstddef>

// ---------------- static scratch (no cudaMalloc allowed) -------------------
__device__ __half g_x16[(size_t)16384*512];          // x fp16 single
__device__ __half g_wc16[(size_t)1536*512];          // 16*[Wq;Wk;Wv] fp16 single
__device__ __half g_wo16[(size_t)512*4096];          // 16*Wo fp16 single
__device__ __half g_q16[(size_t)16384*512];          // fp16(q*cv*2), scrambled
__device__ __half g_k16[(size_t)16384*512];          // fp16(k), scrambled
__device__ __half g_v16[(size_t)16384*512];          // fp16(v), scrambled
__device__ __half g_F16[(size_t)16384*4096];         // 16*F fp16 single

// ---------------- helpers ----------------------------------------------------
__device__ __forceinline__ uint32_t smem_u32(const void* p) {
    uint32_t a;
    asm("{ .reg .u64 t; cvta.to.shared.u64 t, %1; cvt.u32.u64 %0, t; }"
        : "=r"(a) : "l"(p));
    return a;
}
__device__ __forceinline__ void cp16(uint32_t dst, const void* src) {
    asm volatile("cp.async.cg.shared.global [%0], [%1], 16;"
                 :: "r"(dst), "l"(src) : "memory");
}
#define CP_COMMIT() asm volatile("cp.async.commit_group;" ::: "memory")
#define CP_WAIT(n)  asm volatile("cp.async.wait_group %0;" :: "n"(n) : "memory")

#define LDM_X4(r, a) \
    asm volatile("ldmatrix.sync.aligned.m8n8.x4.shared.b16 {%0,%1,%2,%3}, [%4];" \
        : "=r"((r)[0]), "=r"((r)[1]), "=r"((r)[2]), "=r"((r)[3]) : "r"(a))

__device__ __forceinline__ void mma_f16(float* c, const uint32_t* a, const uint32_t* b) {
    asm volatile(
        "mma.sync.aligned.m16n8k16.row.col.f32.f16.f16.f32 "
        "{%0,%1,%2,%3}, {%4,%5,%6,%7}, {%8,%9}, {%0,%1,%2,%3};"
        : "+f"(c[0]), "+f"(c[1]), "+f"(c[2]), "+f"(c[3])
        : "r"(a[0]), "r"(a[1]), "r"(a[2]), "r"(a[3]), "r"(b[0]), "r"(b[1]));
}
__device__ __forceinline__ uint32_t pack_f16x2(float p0, float p1) {
    uint32_t r;
    asm("cvt.rn.f16x2.f32 %0, %1, %2;" : "=r"(r) : "f"(p1), "f"(p0));
    return r;
}
__device__ __forceinline__ uint32_t hmul2(uint32_t a, uint32_t b) {
    uint32_t r;
    asm("mul.rn.f16x2 %0, %1, %2;" : "=r"(r) : "r"(a), "r"(b));
    return r;
}

// ---------------------------------------------------------------------------
// cvt_all: single launch converting x, Wq, Wk, Wv, Wo to fp16 (W's scaled 16x)
// ---------------------------------------------------------------------------
__global__ void cvt_all_kernel(const float4* __restrict__ x,
                               const float4* __restrict__ Wq,
                               const float4* __restrict__ Wk,
                               const float4* __restrict__ Wv,
                               const float4* __restrict__ Wo) {
    int bid = blockIdx.x;
    const float4* in;
    uint2* out;
    float s;
    int base;
    if (bid < 8192)      { in = x;  out = (uint2*)g_x16;  s = 1.f;  base = bid; }
    else if (bid < 8448) { in = Wq; out = (uint2*)g_wc16; s = 16.f; base = bid - 8192; }
    else if (bid < 8704) { in = Wk; out = (uint2*)(g_wc16 + 512*512); s = 16.f; base = bid - 8448; }
    else if (bid < 8960) { in = Wv; out = (uint2*)(g_wc16 + 2*512*512); s = 16.f; base = bid - 8704; }
    else                 { in = Wo; out = (uint2*)g_wo16; s = 16.f; base = bid - 8960; }
    int i = base * 256 + threadIdx.x;
    float4 v = in[i];
    uint2 o;
    o.x = pack_f16x2(s * v.x, s * v.y);
    o.y = pack_f16x2(s * v.z, s * v.w);
    out[i] = o;
}

// ---------------------------------------------------------------------------
// mm_kernel (projections): 16*C = x16 @ (16*W)^T
//   CTA 128x128, 8 warps (2Mx4N), K-chunk 64, 3-stage cp.async, LDM_X4 B.
//   ONE barrier/chunk; prefetch split across ks=0 / ks=1 (commit at ks=1).
// Stage (36864B): X16 128x72f16 | W16 128x72f16
// ---------------------------------------------------------------------------
#define MM_STAGE 36864
#define MM_SMEM  (3 * MM_STAGE)

__global__ __launch_bounds__(256, 2) void mm_kernel(
    const float* __restrict__ bq, const float* __restrict__ bk,
    const float* __restrict__ bv, const float* __restrict__ cv)
{
    extern __shared__ char sm[];
    const int tid = threadIdx.x, ln = tid & 31, wid = tid >> 5;
    const int g = ln >> 2, t = ln & 3;
    const int mw = wid >> 2, nw = wid & 3;
    const int m0 = blockIdx.y * 128, n0 = blockIdx.x * 128;
    const uint32_t sb = smem_u32(sm);

    float c[4][4][4];
#pragma unroll
    for (int a = 0; a < 4; a++)
#pragma unroll
        for (int b = 0; b < 4; b++)
#pragma unroll
            for (int d = 0; d < 4; d++) c[a][b][d] = 0.f;

#define MM_LOAD_HALF(kc, s, h) do {                                            \
    int _k0 = (kc) << 6;                                                       \
    uint32_t _b = sb + (s) * MM_STAGE;                                         \
    _Pragma("unroll")                                                          \
    for (int _it = (h) * 2; _it < (h) * 2 + 2; _it++) {                        \
        int _idx = _it * 256 + tid, _r = _idx >> 3, _sg = _idx & 7;            \
        size_t _sa = (size_t)(m0 + _r) * 512 + _k0 + _sg * 8;                  \
        size_t _sbo = (size_t)(n0 + _r) * 512 + _k0 + _sg * 8;                 \
        uint32_t _d = _r * 144 + _sg * 16;                                     \
        cp16(_b + _d,         g_x16 + _sa);                                    \
        cp16(_b + 18432 + _d, g_wc16 + _sbo);                                  \
    }                                                                          \
} while (0)

    MM_LOAD_HALF(0, 0, 0); MM_LOAD_HALF(0, 0, 1); CP_COMMIT();
    MM_LOAD_HALF(1, 1, 0); MM_LOAD_HALF(1, 1, 1); CP_COMMIT();

    const uint32_t a_lane = (uint32_t)((mw * 64 + (ln & 15)) * 144 + ((ln & 16) ? 16 : 0));
    const uint32_t b_lane4 = (uint32_t)(((ln & 7) + ((ln & 16) ? 8 : 0)) * 144
                                        + ((ln & 8) ? 16 : 0));

    for (int kc = 0; kc < 8; kc++) {
        if (kc == 7) CP_WAIT(0); else CP_WAIT(1);
        __syncthreads();

        const uint32_t stage = sb + (kc % 3) * MM_STAGE;
#pragma unroll
        for (int ks = 0; ks < 4; ks++) {
            const uint32_t kb = ks * 32;
            uint32_t ah[4][4];
#pragma unroll
            for (int mt = 0; mt < 4; mt++) {
                uint32_t ad = stage + a_lane + mt * (16 * 144) + kb;
                LDM_X4(ah[mt], ad);
            }
#pragma unroll
            for (int ntp = 0; ntp < 2; ntp++) {
                uint32_t bd = stage + 18432 + b_lane4 + (nw * 32 + ntp * 16) * 144 + kb;
                uint32_t bh4[4];
                LDM_X4(bh4, bd);
#pragma unroll
                for (int mt = 0; mt < 4; mt++) {
                    mma_f16(c[mt][2 * ntp],     ah[mt], bh4);
                    mma_f16(c[mt][2 * ntp + 1], ah[mt], bh4 + 2);
                }
            }
            if (ks == 0 && kc < 6) MM_LOAD_HALF(kc + 2, (kc + 2) % 3, 0);
            if (ks == 1 && kc < 6) { MM_LOAD_HALF(kc + 2, (kc + 2) % 3, 1); CP_COMMIT(); }
        }
    }

    // epilogue: C_true = accum/16 + bias, fp16 scramble-write
    const int proj = n0 >> 9;
    const float* bias = (proj == 0 ? bq : proj == 1 ? bk : bv);
    __half* outp = (proj == 0 ? g_q16 : proj == 1 ? g_k16 : g_v16);
#pragma unroll
    for (int mt = 0; mt < 4; mt++)
#pragma unroll
        for (int nt = 0; nt < 4; nt++) {
            int col = (n0 + nw * 32 + nt * 8 + t * 2) & 511;
            float b0 = bias[col], b1 = bias[col + 1];
#pragma unroll
            for (int hseg = 0; hseg < 2; hseg++) {
                int row = m0 + mw * 64 + mt * 16 + g + hseg * 8;
                float v0 = c[mt][nt][hseg * 2 + 0] * 0.0625f + b0;
                float v1 = c[mt][nt][hseg * 2 + 1] * 0.0625f + b1;
                int core = row >> 11, bb = (row >> 3) & 255;
                int ii = (row & 7) * 8 + (col >> 6), hh = col & 63;
                size_t dst = (size_t)(bb * 64 + ii) * 512 + core * 64 + hh;
                if (proj == 0) {
                    v0 *= cv[core * 64 + hh]     * 2.0f;   // 16 * cv/8
                    v1 *= cv[core * 64 + hh + 1] * 2.0f;
                }
                *(uint32_t*)&outp[dst] = pack_f16x2(v0, v1);
            }
        }
#undef MM_LOAD_HALF
}

// ---------------------------------------------------------------------------
// gemm1_kernel (fp16): F16[m,n] = sum_r (q16 .* k16)[m,r] * v16[n,r]
//   per (b, i0=8 i's): M=512, N=64, K=512 in 4 chunks of 128; 3-stage pipe.
//   A fragments: LDM_X4 on K tile then HMUL2 with broadcast q pairs.
//   Prefetch split across ks=0 (K/V half) / ks=1 (rest + Q, commit).
// Stage (36864B): K16 64x136f16 | V16 64x136f16 | Q16 8x128f16
// ---------------------------------------------------------------------------
#define G1_K   0
#define G1_V   17408
#define G1_Q   34816
#define G1_STAGE 36864
#define G1_SMEM  (3 * G1_STAGE)

__global__ __launch_bounds__(512, 1) void gemm1_kernel()
{
    extern __shared__ char sm[];
    const uint32_t sb = smem_u32(sm);
    const int tid = threadIdx.x, ln = tid & 31, wid = tid >> 5;
    const int g = ln >> 2, t = ln & 3;
    const int b = blockIdx.y, i0 = blockIdx.x * 8;
    const int il  = wid >> 1;            // i within group of 8
    const int jb0 = (wid & 1) * 32;      // j base within 64

    float c[2][8][4];                    // [mt][nt][frag]
#pragma unroll
    for (int a = 0; a < 2; a++)
#pragma unroll
        for (int bb = 0; bb < 8; bb++)
#pragma unroll
            for (int d = 0; d < 4; d++) c[a][bb][d] = 0.f;

    // chunk = 128 r-values. K/V: 64 rows x 256B (pitch 272B). Q: 8 rows x 256B.
#define G1_LOAD_HALF(kc_, s_, h_) do {                                         \
    int _r0 = (kc_) << 7;                                                      \
    uint32_t _st = sb + (s_) * G1_STAGE;                                       \
    {                                                                          \
        int _i = (h_) * 512 + tid, _r = _i >> 4, _sg = _i & 15;                \
        size_t _src = (size_t)(b * 64 + _r) * 512 + _r0 + _sg * 8;             \
        cp16(_st + G1_K + _r * 272 + _sg * 16, g_k16 + _src);                  \
        cp16(_st + G1_V + _r * 272 + _sg * 16, g_v16 + _src);                  \
    }                                                                          \
    if ((h_) == 1 && tid < 128)                                                \
        cp16(_st + G1_Q + (tid >> 4) * 256 + (tid & 15) * 16,                  \
             g_q16 + ((size_t)(b * 64 + i0 + (tid >> 4))) * 512 + _r0 + (tid & 15) * 8); \
} while (0)

    G1_LOAD_HALF(0, 0, 0); G1_LOAD_HALF(0, 0, 1); CP_COMMIT();
    G1_LOAD_HALF(1, 1, 0); G1_LOAD_HALF(1, 1, 1); CP_COMMIT();

    const uint32_t a_lane = (uint32_t)((jb0 + (ln & 15)) * 272 + ((ln & 16) ? 16 : 0));
    const uint32_t b_lane4 = (uint32_t)(((ln & 7) + ((ln & 16) ? 8 : 0)) * 272
                                        + ((ln & 8) ? 16 : 0));

    for (int kc = 0; kc < 4; kc++) {
        if (kc == 3) CP_WAIT(0); else CP_WAIT(1);
        __syncthreads();

        const int s = kc % 3;
        const uint32_t kbase = sb + s * G1_STAGE + G1_K;
        const uint32_t vbase = sb + s * G1_STAGE + G1_V;
        const char*    qbase = sm + s * G1_STAGE + G1_Q;

#pragma unroll
        for (int ks = 0; ks < 8; ks++) {
            uint32_t q2a = *(const uint32_t*)(qbase + il * 256 + ks * 32 + t * 4);
            uint32_t q2b = *(const uint32_t*)(qbase + il * 256 + ks * 32 + t * 4 + 16);

            uint32_t bh4[4][4];
#pragma unroll
            for (int ntp = 0; ntp < 4; ntp++)
                LDM_X4(bh4[ntp], vbase + b_lane4 + ntp * (16 * 272) + ks * 32);

#pragma unroll
            for (int mt = 0; mt < 2; mt++) {
                uint32_t kf[4];
                LDM_X4(kf, kbase + a_lane + mt * (16 * 272) + ks * 32);
                uint32_t ah[4];
                ah[0] = hmul2(kf[0], q2a);
                ah[1] = hmul2(kf[1], q2a);
                ah[2] = hmul2(kf[2], q2b);
                ah[3] = hmul2(kf[3], q2b);
#pragma unroll
                for (int ntp = 0; ntp < 4; ntp++) {
                    mma_f16(c[mt][2 * ntp],     ah, bh4[ntp]);
                    mma_f16(c[mt][2 * ntp + 1], ah, bh4[ntp] + 2);
                }
            }
            if (ks == 0 && kc < 2) G1_LOAD_HALF(kc + 2, (kc + 2) % 3, 0);
            if (ks == 1 && kc < 2) { G1_LOAD_HALF(kc + 2, (kc + 2) % 3, 1); CP_COMMIT(); }
        }
    }

    // epilogue: write 16F as fp16 single
    const size_t rowF = (size_t)(b * 64 + i0 + il);
#pragma unroll
    for (int mt = 0; mt < 2; mt++)
#pragma unroll
        for (int nt = 0; nt < 8; nt++) {
            int n = nt * 8 + t * 2;
#pragma unroll
            for (int hseg = 0; hseg < 2; hseg++) {
                int j = jb0 + mt * 16 + g + hseg * 8;
                size_t dst = rowF * 4096 + (size_t)j * 64 + n;
                *(uint32_t*)&g_F16[dst] =
                    pack_f16x2(c[mt][nt][hseg * 2 + 0], c[mt][nt][hseg * 2 + 1]);
            }
        }
#undef G1_LOAD_HALF
}

// ---------------------------------------------------------------------------
// gemm2_kernel (fp16): out = (F16 @ Wo16^T)/256 + bo
//   CTA 128x128, 8 warps (2Mx4N), K-chunk 64, 3-stage cp.async, LDM_X4 B.
//   ONE barrier/chunk; prefetch split across ks=0 / ks=1 (commit at ks=1).
// Stage (36864B): F16 128x72f16 | Wo16 128x72f16
// ---------------------------------------------------------------------------
#define G2_STAGE 36864
#define G2_SMEM  (3 * G2_STAGE)

__global__ __launch_bounds__(256, 2) void gemm2_kernel(
    const float* __restrict__ bo, float* __restrict__ out0)
{
    extern __shared__ char sm[];
    const int tid = threadIdx.x, ln = tid & 31, wid = tid >> 5;
    const int g = ln >> 2, t = ln & 3;
    const int mw = wid >> 2, nw = wid & 3;
    const int m0 = blockIdx.y * 128, n0 = blockIdx.x * 128;
    const uint32_t sb = smem_u32(sm);

    float c[4][4][4];
#pragma unroll
    for (int a = 0; a < 4; a++)
#pragma unroll
        for (int b = 0; b < 4; b++)
#pragma unroll
            for (int d = 0; d < 4; d++) c[a][b][d] = 0.f;

#define G2_LOAD_HALF(kc, s, h) do {                                            \
    int _k0 = (kc) << 6;                                                       \
    uint32_t _b = sb + (s) * G2_STAGE;                                         \
    _Pragma("unroll")                                                          \
    for (int _it = (h) * 2; _it < (h) * 2 + 2; _it++) {                        \
        int _idx = _it * 256 + tid, _r = _idx >> 3, _sg = _idx & 7;            \
        size_t _sa = (size_t)(m0 + _r) * 4096 + _k0 + _sg * 8;                 \
        size_t _sb2 = (size_t)(n0 + _r) * 4096 + _k0 + _sg * 8;                \
        uint32_t _d = _r * 144 + _sg * 16;                                     \
        cp16(_b + _d,         g_F16 + _sa);                                    \
        cp16(_b + 18432 + _d, g_wo16 + _sb2);                                  \
    }                                                                          \
} while (0)

    G2_LOAD_HALF(0, 0, 0); G2_LOAD_HALF(0, 0, 1); CP_COMMIT();
    G2_LOAD_HALF(1, 1, 0); G2_LOAD_HALF(1, 1, 1); CP_COMMIT();

    const uint32_t a_lane = (uint32_t)((mw * 64 + (ln & 15)) * 144 + ((ln & 16) ? 16 : 0));
    const uint32_t b_lane4 = (uint32_t)(((ln & 7) + ((ln & 16) ? 8 : 0)) * 144
                                        + ((ln & 8) ? 16 : 0));

    for (int kc = 0; kc < 64; kc++) {
        if (kc == 63) CP_WAIT(0); else CP_WAIT(1);
        __syncthreads();

        const uint32_t stage = sb + (kc % 3) * G2_STAGE;
#pragma unroll
        for (int ks = 0; ks < 4; ks++) {
            const uint32_t kb = ks * 32;
            uint32_t ah[4][4];
#pragma unroll
            for (int mt = 0; mt < 4; mt++) {
                uint32_t ad = stage + a_lane + mt * (16 * 144) + kb;
                LDM_X4(ah[mt], ad);
            }
#pragma unroll
            for (int ntp = 0; ntp < 2; ntp++) {
                uint32_t bd = stage + 18432 + b_lane4 + (nw * 32 + ntp * 16) * 144 + kb;
                uint32_t bh4[4];
                LDM_X4(bh4, bd);
#pragma unroll
                for (int mt = 0; mt < 4; mt++) {
                    mma_f16(c[mt][2 * ntp],     ah[mt], bh4);
                    mma_f16(c[mt][2 * ntp + 1], ah[mt], bh4 + 2);
                }
            }
            if (ks == 0 && kc < 62) G2_LOAD_HALF(kc + 2, (kc + 2) % 3, 0);
            if (ks == 1 && kc < 62) { G2_LOAD_HALF(kc + 2, (kc + 2) % 3, 1); CP_COMMIT(); }
        }
    }

    // epilogue: /256 + bias
#pragma unroll
    for (int mt = 0; mt < 4; mt++)
#pragma unroll
        for (int nt = 0; nt < 4; nt++) {
            int col = n0 + nw * 32 + nt * 8 + t * 2;
            float b0 = bo[col], b1 = bo[col + 1];
#pragma unroll
            for (int hseg = 0; hseg < 2; hseg++) {
                int row = m0 + mw * 64 + mt * 16 + g + hseg * 8;
                float v0 = c[mt][nt][hseg * 2 + 0] * 0.00390625f + b0;
                float v1 = c[mt][nt][hseg * 2 + 1] * 0.00390625f + b1;
                *(float2*)&out0[(size_t)row * 512 + col] = make_float2(v0, v1);
            }
        }
#undef G2_LOAD_HALF
}

// ---------------------------------------------------------------------------
extern "C" void kernel_launch(void* const* d_in, const int* in_sizes, int n_in,
                              void* d_out, int out_size)
{
    const float* x  = (const float*)d_in[0];
    const float* Wq = (const float*)d_in[1];
    const float* bq = (const float*)d_in[2];
    const float* Wk = (const float*)d_in[3];
    const float* bk = (const float*)d_in[4];
    const float* Wv = (const float*)d_in[5];
    const float* bv = (const float*)d_in[6];
    const float* cv = (const float*)d_in[7];
    const float* Wo = (const float*)d_in[8];
    const float* bo = (const float*)d_in[9];
    float* out = (float*)d_out;

    cudaFuncSetAttribute(mm_kernel, cudaFuncAttributeMaxDynamicSharedMemorySize, MM_SMEM);
    cudaFuncSetAttribute(gemm1_kernel, cudaFuncAttributeMaxDynamicSharedMemorySize, G1_SMEM);
    cudaFuncSetAttribute(gemm2_kernel, cudaFuncAttributeMaxDynamicSharedMemorySize, G2_SMEM);

    cvt_all_kernel<<<11008, 256>>>((const float4*)x, (const float4*)Wq,
                                   (const float4*)Wk, (const float4*)Wv,
                                   (const float4*)Wo);

    mm_kernel<<<dim3(12, 128), 256, MM_SMEM>>>(bq, bk, bv, cv);

    gemm1_kernel<<<dim3(8, 256), 512, G1_SMEM>>>();

    gemm2_kernel<<<dim3(4, 128), 256, G2_SMEM>>>(bo, out);
}